// round 1
// baseline (speedup 1.0000x reference)
#include <cuda_runtime.h>
#include <math.h>

// Problem constants
#define BB   8
#define SS   1024
#define DD   768
#define HH   12
#define DK   64
#define MM   (BB*SS)        // 8192 rows
#define BHN  (BB*HH)        // 96 (b,h) pairs

// ---------------- scratch (device globals; no allocations allowed) ----------
__device__ float g_q[(size_t)BHN*SS*DK];      // [B,H,S,DK]  25 MB
__device__ float g_k[(size_t)BHN*SS*DK];
__device__ float g_v[(size_t)BHN*SS*DK];
__device__ float g_ctx[(size_t)MM*DD];        // [B,S,H*DK]  25 MB
__device__ float g_scores[(size_t)BHN*SS*SS]; // [B,H,S,S]  403 MB (used only if attn not in d_out)

// ============================================================================
// Generic 64x64-tile SGEMM: C[M,N] = A[M,K] @ W[K,N] + bias[N]
// mode 0: row-major write C[m*N+n]
// mode 1: head-split write  C[((b*H+h)*S+s)*DK+d]   (for Q/K/V projections)
// 256 threads, 4x4 per-thread tile, BK=16.
// ============================================================================
__global__ __launch_bounds__(256) void sgemm64(
    const float* __restrict__ A, const float* __restrict__ W,
    const float* __restrict__ bias, float* __restrict__ C,
    int M, int N, int K, int mode)
{
    __shared__ float As[16][65];   // As[k][m], pad -> conflict-free
    __shared__ float Ws[16][64];   // Ws[k][n], row-contiguous

    const int row0 = blockIdx.y * 64;
    const int col0 = blockIdx.x * 64;
    const int tid  = threadIdx.x;
    const int tx   = tid & 15;     // 16 col-groups
    const int ty   = tid >> 4;     // 16 row-groups

    float acc[4][4] = {};

    for (int k0 = 0; k0 < K; k0 += 16) {
        #pragma unroll
        for (int i = tid; i < 64*16; i += 256) {
            int r = i >> 4, c = i & 15;                 // coalesced 16-float rows
            As[c][r] = A[(size_t)(row0 + r) * K + k0 + c];
        }
        #pragma unroll
        for (int i = tid; i < 16*64; i += 256) {
            int r = i >> 6, c = i & 63;                 // fully coalesced
            Ws[r][c] = W[(size_t)(k0 + r) * N + col0 + c];
        }
        __syncthreads();
        #pragma unroll
        for (int kk = 0; kk < 16; kk++) {
            float a[4], b[4];
            #pragma unroll
            for (int t = 0; t < 4; t++) a[t] = As[kk][ty*4 + t];
            #pragma unroll
            for (int t = 0; t < 4; t++) b[t] = Ws[kk][tx*4 + t];
            #pragma unroll
            for (int i = 0; i < 4; i++)
                #pragma unroll
                for (int j = 0; j < 4; j++)
                    acc[i][j] += a[i] * b[j];
        }
        __syncthreads();
    }

    #pragma unroll
    for (int i = 0; i < 4; i++) {
        #pragma unroll
        for (int j = 0; j < 4; j++) {
            int m = row0 + ty*4 + i;
            int n = col0 + tx*4 + j;
            float v = acc[i][j] + bias[n];
            if (mode == 0) {
                C[(size_t)m * N + n] = v;
            } else {
                int b = m >> 10, s = m & 1023;   // S = 1024
                int h = n >> 6,  d = n & 63;     // DK = 64
                C[(((size_t)(b*HH + h)) * SS + s) * DK + d] = v;
            }
        }
    }
}

// ============================================================================
// Scores: per (b,h): S_out = (Q @ K^T) * 0.125   -> [B,H,S,S]
// Block: 64x64 output tile; K-dim (=DK=64) resident in smem in one shot.
// ============================================================================
__global__ __launch_bounds__(256) void scores_kernel(
    const float* __restrict__ Q, const float* __restrict__ Kv,
    float* __restrict__ out)
{
    const int bh   = blockIdx.z;
    const float* Qb = Q  + (size_t)bh * SS * DK;
    const float* Kb = Kv + (size_t)bh * SS * DK;

    __shared__ float Qs[64][65];   // Qs[d][qrow]  (transposed, padded)
    __shared__ float Ks[64][65];   // Ks[d][krow]

    const int row0 = blockIdx.y * 64;
    const int col0 = blockIdx.x * 64;
    const int tid  = threadIdx.x;
    const int tx   = tid & 15;
    const int ty   = tid >> 4;

    #pragma unroll
    for (int i = tid; i < 64*64; i += 256) {
        int r = i >> 6, c = i & 63;                    // coalesced, conflict-free store
        Qs[c][r] = Qb[(size_t)(row0 + r) * DK + c];
        Ks[c][r] = Kb[(size_t)(col0 + r) * DK + c];
    }
    __syncthreads();

    float acc[4][4] = {};
    #pragma unroll
    for (int kk = 0; kk < 64; kk++) {
        float a[4], b[4];
        #pragma unroll
        for (int t = 0; t < 4; t++) a[t] = Qs[kk][ty*4 + t];
        #pragma unroll
        for (int t = 0; t < 4; t++) b[t] = Ks[kk][tx*4 + t];
        #pragma unroll
        for (int i = 0; i < 4; i++)
            #pragma unroll
            for (int j = 0; j < 4; j++)
                acc[i][j] += a[i] * b[j];
    }

    float* ob = out + (size_t)bh * SS * SS;
    #pragma unroll
    for (int i = 0; i < 4; i++)
        #pragma unroll
        for (int j = 0; j < 4; j++)
            ob[(size_t)(row0 + ty*4 + i) * SS + col0 + tx*4 + j] = acc[i][j] * 0.125f;
}

// ============================================================================
// In-place row softmax over rows of length 1024. One block per row.
// ============================================================================
__global__ __launch_bounds__(256) void softmax_kernel(float* __restrict__ P)
{
    const size_t row = blockIdx.x;
    float4* p = reinterpret_cast<float4*>(P + row * SS);
    const int tid  = threadIdx.x;
    const int lane = tid & 31;
    const int warp = tid >> 5;

    __shared__ float smax[8];
    __shared__ float ssum[8];

    float4 v = p[tid];
    float mx = fmaxf(fmaxf(v.x, v.y), fmaxf(v.z, v.w));
    #pragma unroll
    for (int o = 16; o > 0; o >>= 1) mx = fmaxf(mx, __shfl_xor_sync(0xffffffffu, mx, o));
    if (lane == 0) smax[warp] = mx;
    __syncthreads();
    float m = smax[0];
    #pragma unroll
    for (int w = 1; w < 8; w++) m = fmaxf(m, smax[w]);

    float4 e;
    e.x = __expf(v.x - m);
    e.y = __expf(v.y - m);
    e.z = __expf(v.z - m);
    e.w = __expf(v.w - m);
    float s = e.x + e.y + e.z + e.w;
    #pragma unroll
    for (int o = 16; o > 0; o >>= 1) s += __shfl_xor_sync(0xffffffffu, s, o);
    if (lane == 0) ssum[warp] = s;
    __syncthreads();
    float tot = 0.f;
    #pragma unroll
    for (int w = 0; w < 8; w++) tot += ssum[w];
    float inv = 1.0f / tot;

    e.x *= inv; e.y *= inv; e.z *= inv; e.w *= inv;
    p[tid] = e;
}

// ============================================================================
// AV: per (b,h): ctx_tile = P[S,S] @ V[S,DK]  written as [B,S,H*DK]
// Block: 64 rows x 64 cols (full DK), K-loop step 32.
// ============================================================================
__global__ __launch_bounds__(256) void av_kernel(
    const float* __restrict__ P, const float* __restrict__ V,
    float* __restrict__ ctx)
{
    const int bh  = blockIdx.y;
    const int b   = bh / HH;
    const int h   = bh % HH;
    const float* Pb = P + (size_t)bh * SS * SS;
    const float* Vb = V + (size_t)bh * SS * DK;

    __shared__ float Ps[32][65];   // Ps[k][row]  transposed, padded
    __shared__ float Vs[32][64];   // Vs[k][col]

    const int row0 = blockIdx.x * 64;
    const int tid  = threadIdx.x;
    const int tx   = tid & 15;
    const int ty   = tid >> 4;

    float acc[4][4] = {};

    for (int k0 = 0; k0 < SS; k0 += 32) {
        #pragma unroll
        for (int i = tid; i < 64*32; i += 256) {
            int r = i >> 5, c = i & 31;
            Ps[c][r] = Pb[(size_t)(row0 + r) * SS + k0 + c];
        }
        #pragma unroll
        for (int i = tid; i < 32*64; i += 256) {
            int r = i >> 6, c = i & 63;
            Vs[r][c] = Vb[(size_t)(k0 + r) * DK + c];
        }
        __syncthreads();
        #pragma unroll
        for (int kk = 0; kk < 32; kk++) {
            float a[4], bv[4];
            #pragma unroll
            for (int t = 0; t < 4; t++) a[t]  = Ps[kk][ty*4 + t];
            #pragma unroll
            for (int t = 0; t < 4; t++) bv[t] = Vs[kk][tx*4 + t];
            #pragma unroll
            for (int i = 0; i < 4; i++)
                #pragma unroll
                for (int j = 0; j < 4; j++)
                    acc[i][j] += a[i] * bv[j];
        }
        __syncthreads();
    }

    #pragma unroll
    for (int i = 0; i < 4; i++) {
        #pragma unroll
        for (int j = 0; j < 4; j++) {
            int s = row0 + ty*4 + i;
            int d = tx*4 + j;
            ctx[((size_t)(b*SS + s)) * DD + h*DK + d] = acc[i][j];
        }
    }
}

// ============================================================================
// Host launcher
// ============================================================================
extern "C" void kernel_launch(void* const* d_in, const int* in_sizes, int n_in,
                              void* d_out, int out_size)
{
    (void)in_sizes; (void)n_in;
    const float* x  = (const float*)d_in[0];
    const float* Wq = (const float*)d_in[1];
    const float* bq = (const float*)d_in[2];
    const float* Wk = (const float*)d_in[3];
    const float* bk = (const float*)d_in[4];
    const float* Wv = (const float*)d_in[5];
    const float* bv = (const float*)d_in[6];
    const float* Wo = (const float*)d_in[7];
    const float* bo = (const float*)d_in[8];
    float* out = (float*)d_out;

    float *gq, *gk, *gv, *gctx, *gsc;
    cudaGetSymbolAddress((void**)&gq,   g_q);
    cudaGetSymbolAddress((void**)&gk,   g_k);
    cudaGetSymbolAddress((void**)&gv,   g_v);
    cudaGetSymbolAddress((void**)&gctx, g_ctx);
    cudaGetSymbolAddress((void**)&gsc,  g_scores);

    // If the harness expects (out, attn) concatenated, write attn directly
    // into its slot of d_out; otherwise keep it in scratch.
    const size_t final_elems = (size_t)MM * DD;   // 6,291,456
    float* attn = ((size_t)out_size > final_elems) ? (out + final_elems) : gsc;

    dim3 blk(256);

    // QKV projections (head-split epilogue)
    dim3 g1(DD / 64, MM / 64);            // (12, 128)
    sgemm64<<<g1, blk>>>(x, Wq, bq, gq, MM, DD, DD, 1);
    sgemm64<<<g1, blk>>>(x, Wk, bk, gk, MM, DD, DD, 1);
    sgemm64<<<g1, blk>>>(x, Wv, bv, gv, MM, DD, DD, 1);

    // Scores = Q K^T / 8, written straight to the attn destination
    dim3 g2(SS / 64, SS / 64, BHN);       // (16, 16, 96)
    scores_kernel<<<g2, blk>>>(gq, gk, attn);

    // In-place softmax (one block per row)
    softmax_kernel<<<BHN * SS, blk>>>(attn);

    // ctx = attn @ V  -> [B,S,H*DK]
    dim3 g3(SS / 64, BHN);                // (16, 96)
    av_kernel<<<g3, blk>>>(attn, gv, gctx);

    // final = ctx @ Wo + bo -> d_out[0 : M*D]
    sgemm64<<<g1, blk>>>(gctx, Wo, bo, out, MM, DD, DD, 0);
}

// round 3
// speedup vs baseline: 2.2593x; 2.2593x over previous
#include <cuda_runtime.h>
#include <cuda_bf16.h>
#include <cstdint>

#define BBATCH 8
#define SSEQ   1024
#define DMODEL 768
#define NHEAD  12
#define DHEAD  64
#define MROWS  (BBATCH*SSEQ)     // 8192
#define NBH    (BBATCH*NHEAD)    // 96
#define KP     (3*DMODEL)        // 2304  packed K for proj/final
#define KSC    (3*DHEAD)         // 192   packed K for scores
#define KAV    (3*SSEQ)          // 3072  packed K for AV

// ---------------- scratch (device globals; no allocations allowed) ----------
__device__ float g_attn[(size_t)NBH*SSEQ*SSEQ];                 // fallback attn (403MB)
__device__ __nv_bfloat16 g_xP [(size_t)MROWS*KP];               // x packed A-type
__device__ __nv_bfloat16 g_wqP[(size_t)DMODEL*KP];              // W^T packed B-type
__device__ __nv_bfloat16 g_wkP[(size_t)DMODEL*KP];
__device__ __nv_bfloat16 g_wvP[(size_t)DMODEL*KP];
__device__ __nv_bfloat16 g_woP[(size_t)DMODEL*KP];
__device__ __nv_bfloat16 g_qP [(size_t)NBH*SSEQ*KSC];           // Q packed A-type
__device__ __nv_bfloat16 g_kP [(size_t)NBH*SSEQ*KSC];           // K packed B-type
__device__ __nv_bfloat16 g_vP [(size_t)NBH*KAV*DHEAD];          // V packed [bh][3S][dk] (B, n-contig)
__device__ __nv_bfloat16 g_pP [(size_t)NBH*SSEQ*KAV];           // P packed A-type (603MB)
__device__ __nv_bfloat16 g_cP [(size_t)MROWS*KP];               // ctx packed A-type

// ============================ PTX helpers ===================================
__device__ __forceinline__ uint32_t smem_u32(const void* p) {
    uint32_t a;
    asm("{ .reg .u64 t; cvta.to.shared.u64 t, %1; cvt.u32.u64 %0, t; }" : "=r"(a) : "l"(p));
    return a;
}
#define SWZ(o) ((uint32_t)(o) ^ ((((uint32_t)(o)) >> 3) & 0x70))

__device__ __forceinline__ void cp16(uint32_t s, const void* g) {
    asm volatile("cp.async.cg.shared.global [%0], [%1], 16;" :: "r"(s), "l"(g));
}
#define CP_COMMIT() asm volatile("cp.async.commit_group;")
#define CP_WAIT(n)  asm volatile("cp.async.wait_group %0;" :: "n"(n))

__device__ __forceinline__ void ldsm4(uint32_t& r0, uint32_t& r1, uint32_t& r2, uint32_t& r3, uint32_t a) {
    asm volatile("ldmatrix.sync.aligned.m8n8.x4.shared.b16 {%0,%1,%2,%3}, [%4];"
                 : "=r"(r0), "=r"(r1), "=r"(r2), "=r"(r3) : "r"(a));
}
__device__ __forceinline__ void ldsm4t(uint32_t& r0, uint32_t& r1, uint32_t& r2, uint32_t& r3, uint32_t a) {
    asm volatile("ldmatrix.sync.aligned.m8n8.x4.trans.shared.b16 {%0,%1,%2,%3}, [%4];"
                 : "=r"(r0), "=r"(r1), "=r"(r2), "=r"(r3) : "r"(a));
}
__device__ __forceinline__ void mma16816(float* c, const uint32_t* a, const uint32_t* b) {
    asm volatile("mma.sync.aligned.m16n8k16.row.col.f32.bf16.bf16.f32 "
                 "{%0,%1,%2,%3}, {%4,%5,%6,%7}, {%8,%9}, {%0,%1,%2,%3};"
                 : "+f"(c[0]), "+f"(c[1]), "+f"(c[2]), "+f"(c[3])
                 : "r"(a[0]), "r"(a[1]), "r"(a[2]), "r"(a[3]), "r"(b[0]), "r"(b[1]));
}

// epilogue modes
enum { M_QA = 0, M_KB = 1, M_VP = 2, M_SC = 3, M_CTX = 4, M_FIN = 5 };

__device__ __forceinline__ void hilo2(float v0, float v1, __nv_bfloat162& hp, __nv_bfloat162& lp) {
    __nv_bfloat16 h0 = __float2bfloat16(v0), h1 = __float2bfloat16(v1);
    hp.x = h0; hp.y = h1;
    lp.x = __float2bfloat16(v0 - __bfloat162float(h0));
    lp.y = __float2bfloat16(v1 - __bfloat162float(h1));
}

__device__ __forceinline__ void emit_pair(int mode, int m, int n, float v0, float v1,
                                          void* out0, const float* bias, int bz)
{
    if (mode == M_SC) {
        float* o = (float*)out0 + (size_t)bz * SSEQ * SSEQ + (size_t)m * SSEQ + n;
        float2 w; w.x = v0 * 0.125f; w.y = v1 * 0.125f;
        *(float2*)o = w;
        return;
    }
    if (mode == M_FIN) {
        float* o = (float*)out0 + (size_t)m * DMODEL + n;
        float2 w; w.x = v0 + bias[n]; w.y = v1 + bias[n + 1];
        *(float2*)o = w;
        return;
    }
    if (mode != M_CTX) { v0 += bias[n]; v1 += bias[n + 1]; }
    __nv_bfloat162 hp, lp;
    hilo2(v0, v1, hp, lp);
    __nv_bfloat16* ob = (__nv_bfloat16*)out0;
    if (mode == M_QA || mode == M_KB) {
        int b = m >> 10, s = m & 1023, h = n >> 6, d = n & 63;
        size_t base = ((size_t)(b * NHEAD + h) * SSEQ + s) * KSC + d;
        *(__nv_bfloat162*)(ob + base) = hp;
        if (mode == M_QA) {
            *(__nv_bfloat162*)(ob + base + DHEAD)     = lp;
            *(__nv_bfloat162*)(ob + base + 2 * DHEAD) = hp;
        } else {
            *(__nv_bfloat162*)(ob + base + DHEAD)     = hp;
            *(__nv_bfloat162*)(ob + base + 2 * DHEAD) = lp;
        }
    } else if (mode == M_VP) {
        int b = m >> 10, s = m & 1023, h = n >> 6, d = n & 63;
        size_t base = (size_t)(b * NHEAD + h) * KAV * DHEAD + (size_t)s * DHEAD + d;
        *(__nv_bfloat162*)(ob + base)                        = hp;
        *(__nv_bfloat162*)(ob + base + (size_t)SSEQ * DHEAD)     = hp;
        *(__nv_bfloat162*)(ob + base + (size_t)2 * SSEQ * DHEAD) = lp;
    } else { // M_CTX
        int h = bz % NHEAD, b = bz / NHEAD;
        int gm = b * SSEQ + m;
        int ck = h * DHEAD + n;
        size_t base = (size_t)gm * KP + ck;
        *(__nv_bfloat162*)(ob + base)              = hp;
        *(__nv_bfloat162*)(ob + base + DMODEL)     = lp;
        *(__nv_bfloat162*)(ob + base + 2 * DMODEL) = hp;
    }
}

// ============================ generic bf16 HMMA GEMM ========================
// C[M, N-tile] = A[M, K'] (k-contig) @ B^T.  BTRANS=0: B[N][K'] k-contig;
// BTRANS=1: B[K'][ldB] n-contig (ldmatrix .trans path).
template<int BN, int WPM, int WPN, int BTRANS>
__global__ __launch_bounds__(256) void hgemm(
    const __nv_bfloat16* __restrict__ Ag, const __nv_bfloat16* __restrict__ Bg,
    const float* __restrict__ bias, void* __restrict__ out0,
    size_t aZ, size_t bZ, int K, int ldB, int mode)
{
    constexpr int BM = 128, BK = 64;
    constexpr int WM = BM / WPM, WN = BN / WPN;
    constexpr int MI = WM / 16, NI = WN / 8;
    constexpr int SA = BM * BK * 2;
    constexpr int SB = BN * BK * 2;
    constexpr int STG = SA + SB;

    extern __shared__ char smem[];
    const uint32_t sbase = smem_u32(smem);
    const int tid = threadIdx.x, l = tid & 31, wid = tid >> 5;
    const int bz = blockIdx.z;
    const int row0 = blockIdx.y * BM, col0 = blockIdx.x * BN;
    const int wm0 = (wid / WPN) * WM, wn0 = (wid % WPN) * WN;

    const __nv_bfloat16* A = Ag + (size_t)bz * aZ;
    const __nv_bfloat16* B = Bg + (size_t)bz * bZ;

    auto issue = [&](int ch, int st) {
        const int k0 = ch * BK;
        const uint32_t sA = sbase + st * STG;
        const uint32_t sB = sA + SA;
        for (int i = tid; i < BM * 8; i += 256) {
            int r = i >> 3, v = i & 7;
            cp16(sA + SWZ(r * 128 + v * 16), A + (size_t)(row0 + r) * K + k0 + v * 8);
        }
        if constexpr (BTRANS) {
            constexpr int VPR = BN / 8;           // 16B vecs per k-row
            for (int i = tid; i < BK * VPR; i += 256) {
                int r = i / VPR, v = i % VPR;
                cp16(sB + SWZ(r * (BN * 2) + v * 16),
                     B + (size_t)(k0 + r) * ldB + col0 + v * 8);
            }
        } else {
            for (int i = tid; i < BN * 8; i += 256) {
                int r = i >> 3, v = i & 7;
                cp16(sB + SWZ(r * 128 + v * 16), B + (size_t)(col0 + r) * K + k0 + v * 8);
            }
        }
    };

    float c[MI][NI][4];
    #pragma unroll
    for (int i = 0; i < MI; i++)
        #pragma unroll
        for (int j = 0; j < NI; j++)
            #pragma unroll
            for (int q = 0; q < 4; q++) c[i][j][q] = 0.f;

    const int nch = K / BK;
    issue(0, 0); CP_COMMIT();

    for (int ch = 0; ch < nch; ch++) {
        if (ch + 1 < nch) { issue(ch + 1, (ch + 1) & 1); CP_COMMIT(); CP_WAIT(1); }
        else              { CP_WAIT(0); }
        __syncthreads();

        const uint32_t sA = sbase + (ch & 1) * STG;
        const uint32_t sB = sA + SA;

        if constexpr (!BTRANS) {
            #pragma unroll
            for (int ks = 0; ks < 4; ks++) {
                uint32_t af[MI][4];
                #pragma unroll
                for (int im = 0; im < MI; im++)
                    ldsm4(af[im][0], af[im][1], af[im][2], af[im][3],
                          sA + SWZ((wm0 + im * 16 + (l & 15)) * 128 + ks * 32 + ((l >> 4) & 1) * 16));
                uint32_t bf[NI][2];
                #pragma unroll
                for (int i2 = 0; i2 < NI / 2; i2++) {
                    int g = l >> 3;
                    uint32_t r0, r1, r2, r3;
                    ldsm4(r0, r1, r2, r3,
                          sB + SWZ((wn0 + i2 * 16 + ((g >> 1) & 1) * 8 + (l & 7)) * 128 + ks * 32 + (g & 1) * 16));
                    bf[2 * i2][0] = r0; bf[2 * i2][1] = r1;
                    bf[2 * i2 + 1][0] = r2; bf[2 * i2 + 1][1] = r3;
                }
                #pragma unroll
                for (int im = 0; im < MI; im++)
                    #pragma unroll
                    for (int in = 0; in < NI; in++)
                        mma16816(c[im][in], af[im], bf[in]);
            }
        } else {
            #pragma unroll
            for (int p = 0; p < 2; p++) {
                uint32_t bf[2][NI][2];
                #pragma unroll
                for (int in = 0; in < NI; in++) {
                    int g = l >> 3;
                    uint32_t r0, r1, r2, r3;
                    ldsm4t(r0, r1, r2, r3,
                           sB + SWZ((p * 32 + g * 8 + (l & 7)) * (BN * 2) + (wn0 + in * 8) * 2));
                    bf[0][in][0] = r0; bf[0][in][1] = r1;
                    bf[1][in][0] = r2; bf[1][in][1] = r3;
                }
                #pragma unroll
                for (int q = 0; q < 2; q++) {
                    const int ks = 2 * p + q;
                    uint32_t af[MI][4];
                    #pragma unroll
                    for (int im = 0; im < MI; im++)
                        ldsm4(af[im][0], af[im][1], af[im][2], af[im][3],
                              sA + SWZ((wm0 + im * 16 + (l & 15)) * 128 + ks * 32 + ((l >> 4) & 1) * 16));
                    #pragma unroll
                    for (int im = 0; im < MI; im++)
                        #pragma unroll
                        for (int in = 0; in < NI; in++)
                            mma16816(c[im][in], af[im], bf[q][in]);
                }
            }
        }
        __syncthreads();
    }

    // epilogue: direct register writes (8B fp32 pairs / 4B bf16x2)
    #pragma unroll
    for (int im = 0; im < MI; im++) {
        #pragma unroll
        for (int in = 0; in < NI; in++) {
            int r = row0 + wm0 + im * 16 + (l >> 2);
            int n = col0 + wn0 + in * 8 + (l & 3) * 2;
            emit_pair(mode, r,     n, c[im][in][0], c[im][in][1], out0, bias, bz);
            emit_pair(mode, r + 8, n, c[im][in][2], c[im][in][3], out0, bias, bz);
        }
    }
}

// ============================ prep kernels ==================================
// x [M,768] fp32 -> xP [M,2304] A-type ([hi|lo|hi])
__global__ __launch_bounds__(256) void pack_a(const float* __restrict__ in, __nv_bfloat16* __restrict__ o)
{
    size_t i = (size_t)blockIdx.x * 256 + threadIdx.x;   // pair index
    size_t m = i / (DMODEL / 2);
    int kk = (int)(i % (DMODEL / 2)) * 2;
    if (m >= MROWS) return;
    float2 v = *(const float2*)(in + m * DMODEL + kk);
    __nv_bfloat162 hp, lp;
    hilo2(v.x, v.y, hp, lp);
    size_t base = m * KP + kk;
    *(__nv_bfloat162*)(o + base)              = hp;
    *(__nv_bfloat162*)(o + base + DMODEL)     = lp;
    *(__nv_bfloat162*)(o + base + 2 * DMODEL) = hp;
}

// W [K,N] fp32 -> W^T packed B-type [n][2304] ([hi|hi|lo])
__global__ void pack_w(const float* __restrict__ W, __nv_bfloat16* __restrict__ o)
{
    __shared__ float t[32][33];
    int n0 = blockIdx.x * 32, k0 = blockIdx.y * 32;
    int x = threadIdx.x, y = threadIdx.y;     // (32,8)
    #pragma unroll
    for (int j = 0; j < 32; j += 8)
        t[y + j][x] = W[(size_t)(k0 + y + j) * DMODEL + n0 + x];
    __syncthreads();
    #pragma unroll
    for (int j = 0; j < 32; j += 8) {
        float v = t[x][y + j];
        size_t base = (size_t)(n0 + y + j) * KP + k0 + x;
        __nv_bfloat16 h = __float2bfloat16(v);
        __nv_bfloat16 lo = __float2bfloat16(v - __bfloat162float(h));
        o[base] = h;
        o[base + DMODEL] = h;
        o[base + 2 * DMODEL] = lo;
    }
}

// softmax over 1024-length rows; writes fp32 attn in-place + P packed A-type
__global__ __launch_bounds__(256) void softmax_kernel(
    float* __restrict__ P, __nv_bfloat16* __restrict__ pP)
{
    const size_t row = blockIdx.x;
    float4* p = reinterpret_cast<float4*>(P + row * SSEQ);
    const int tid = threadIdx.x;
    const int lane = tid & 31, warp = tid >> 5;

    __shared__ float smax[8];
    __shared__ float ssum[8];

    float4 v = p[tid];
    float mx = fmaxf(fmaxf(v.x, v.y), fmaxf(v.z, v.w));
    #pragma unroll
    for (int o = 16; o > 0; o >>= 1) mx = fmaxf(mx, __shfl_xor_sync(0xffffffffu, mx, o));
    if (lane == 0) smax[warp] = mx;
    __syncthreads();
    float m = smax[0];
    #pragma unroll
    for (int w = 1; w < 8; w++) m = fmaxf(m, smax[w]);

    float4 e;
    e.x = __expf(v.x - m); e.y = __expf(v.y - m);
    e.z = __expf(v.z - m); e.w = __expf(v.w - m);
    float s = e.x + e.y + e.z + e.w;
    #pragma unroll
    for (int o = 16; o > 0; o >>= 1) s += __shfl_xor_sync(0xffffffffu, s, o);
    if (lane == 0) ssum[warp] = s;
    __syncthreads();
    float tot = 0.f;
    #pragma unroll
    for (int w = 0; w < 8; w++) tot += ssum[w];
    float inv = 1.0f / tot;

    e.x *= inv; e.y *= inv; e.z *= inv; e.w *= inv;
    p[tid] = e;

    __nv_bfloat162 hp0, lp0, hp1, lp1;
    hilo2(e.x, e.y, hp0, lp0);
    hilo2(e.z, e.w, hp1, lp1);
    size_t base = row * KAV + (size_t)tid * 4;
    *(__nv_bfloat162*)(pP + base)                = hp0;
    *(__nv_bfloat162*)(pP + base + 2)            = hp1;
    *(__nv_bfloat162*)(pP + base + SSEQ)         = lp0;
    *(__nv_bfloat162*)(pP + base + SSEQ + 2)     = lp1;
    *(__nv_bfloat162*)(pP + base + 2 * SSEQ)     = hp0;
    *(__nv_bfloat162*)(pP + base + 2 * SSEQ + 2) = hp1;
}

// ============================ host launcher =================================
extern "C" void kernel_launch(void* const* d_in, const int* in_sizes, int n_in,
                              void* d_out, int out_size)
{
    (void)in_sizes; (void)n_in;
    const float* x  = (const float*)d_in[0];
    const float* Wq = (const float*)d_in[1];
    const float* bq = (const float*)d_in[2];
    const float* Wk = (const float*)d_in[3];
    const float* bk = (const float*)d_in[4];
    const float* Wv = (const float*)d_in[5];
    const float* bv = (const float*)d_in[6];
    const float* Wo = (const float*)d_in[7];
    const float* bo = (const float*)d_in[8];
    float* out = (float*)d_out;

    float* gattn;
    __nv_bfloat16 *xP, *wqP, *wkP, *wvP, *woP, *qP, *kP, *vP, *pP, *cP;
    cudaGetSymbolAddress((void**)&gattn, g_attn);
    cudaGetSymbolAddress((void**)&xP,  g_xP);
    cudaGetSymbolAddress((void**)&wqP, g_wqP);
    cudaGetSymbolAddress((void**)&wkP, g_wkP);
    cudaGetSymbolAddress((void**)&wvP, g_wvP);
    cudaGetSymbolAddress((void**)&woP, g_woP);
    cudaGetSymbolAddress((void**)&qP,  g_qP);
    cudaGetSymbolAddress((void**)&kP,  g_kP);
    cudaGetSymbolAddress((void**)&vP,  g_vP);
    cudaGetSymbolAddress((void**)&pP,  g_pP);
    cudaGetSymbolAddress((void**)&cP,  g_cP);

    const size_t final_elems = (size_t)MROWS * DMODEL;
    float* attn = ((size_t)out_size > final_elems) ? (out + final_elems) : gattn;

    constexpr int SM_BIG   = 2 * (128 * 64 * 2 + 128 * 64 * 2);   // 64 KB
    constexpr int SM_SMALL = 2 * (128 * 64 * 2 + 64 * 64 * 2);    // 48 KB
    cudaFuncSetAttribute((const void*)hgemm<128, 2, 4, 0>,
                         cudaFuncAttributeMaxDynamicSharedMemorySize, SM_BIG);
    cudaFuncSetAttribute((const void*)hgemm<64, 4, 2, 1>,
                         cudaFuncAttributeMaxDynamicSharedMemorySize, SM_SMALL);

    // pack inputs
    {
        size_t pairs = (size_t)MROWS * (DMODEL / 2);
        pack_a<<<(unsigned)((pairs + 255) / 256), 256>>>(x, xP);
        dim3 tb(32, 8), tg(DMODEL / 32, DMODEL / 32);
        pack_w<<<tg, tb>>>(Wq, wqP);
        pack_w<<<tg, tb>>>(Wk, wkP);
        pack_w<<<tg, tb>>>(Wv, wvP);
        pack_w<<<tg, tb>>>(Wo, woP);
    }

    // QKV projections: [8192,768] = xP @ W^T
    dim3 gproj(DMODEL / 128, MROWS / 128, 1);     // (6, 64)
    hgemm<128, 2, 4, 0><<<gproj, 256, SM_BIG>>>(xP, wqP, bq, qP, 0, 0, KP, KP, M_QA);
    hgemm<128, 2, 4, 0><<<gproj, 256, SM_BIG>>>(xP, wkP, bk, kP, 0, 0, KP, KP, M_KB);
    hgemm<128, 2, 4, 0><<<gproj, 256, SM_BIG>>>(xP, wvP, bv, vP, 0, 0, KP, KP, M_VP);

    // scores = Q K^T / 8 -> attn fp32
    dim3 gsc(SSEQ / 128, SSEQ / 128, NBH);        // (8, 8, 96)
    hgemm<128, 2, 4, 0><<<gsc, 256, SM_BIG>>>(qP, kP, nullptr, attn,
                                              (size_t)SSEQ * KSC, (size_t)SSEQ * KSC, KSC, KSC, M_SC);

    // softmax in-place + emit packed P
    softmax_kernel<<<NBH * SSEQ, 256>>>(attn, pP);

    // ctx = P @ V -> cP packed
    dim3 gav(1, SSEQ / 128, NBH);                 // (1, 8, 96)
    hgemm<64, 4, 2, 1><<<gav, 256, SM_SMALL>>>(pP, vP, nullptr, cP,
                                               (size_t)SSEQ * KAV, (size_t)KAV * DHEAD, KAV, DHEAD, M_CTX);

    // out = ctx @ Wo + bo (fp32)
    hgemm<128, 2, 4, 0><<<gproj, 256, SM_BIG>>>(cP, woP, bo, out, 0, 0, KP, KP, M_FIN);
}

// round 4
// speedup vs baseline: 2.3955x; 1.0603x over previous
#include <cuda_runtime.h>
#include <cuda_bf16.h>
#include <cstdint>

#define BBATCH 8
#define SSEQ   1024
#define DMODEL 768
#define NHEAD  12
#define DHEAD  64
#define MROWS  (BBATCH*SSEQ)     // 8192
#define NBH    (BBATCH*NHEAD)    // 96
#define KP     (3*DMODEL)        // 2304  packed K for proj/final
#define KSC    (3*DHEAD)         // 192   packed K for Q/K
#define VOFFBH ((size_t)NBH*SSEQ*DHEAD)

// ---------------- scratch (device globals; no allocations allowed) ----------
__device__ float g_attn[(size_t)NBH*SSEQ*SSEQ];                 // fallback attn (403MB)
__device__ float g_l[(size_t)NBH*SSEQ];                         // softmax denominators
__device__ __nv_bfloat16 g_xP [(size_t)MROWS*KP];               // x packed A-type
__device__ __nv_bfloat16 g_wqP[(size_t)DMODEL*KP];
__device__ __nv_bfloat16 g_wkP[(size_t)DMODEL*KP];
__device__ __nv_bfloat16 g_wvP[(size_t)DMODEL*KP];
__device__ __nv_bfloat16 g_woP[(size_t)DMODEL*KP];
__device__ __nv_bfloat16 g_qP [(size_t)NBH*SSEQ*KSC];           // Q packed [hi|lo|hi]
__device__ __nv_bfloat16 g_kP [(size_t)NBH*SSEQ*KSC];           // K packed [hi|hi|lo]
__device__ __nv_bfloat16 g_vhl[2*VOFFBH];                       // V hi then lo, [bh][s][64]
__device__ __nv_bfloat16 g_cP [(size_t)MROWS*KP];               // ctx packed [hi|lo|hi]

// ============================ PTX helpers ===================================
__device__ __forceinline__ uint32_t smem_u32(const void* p) {
    uint32_t a;
    asm("{ .reg .u64 t; cvta.to.shared.u64 t, %1; cvt.u32.u64 %0, t; }" : "=r"(a) : "l"(p));
    return a;
}
#define SWZ(o) ((uint32_t)(o) ^ ((((uint32_t)(o)) >> 3) & 0x70))

__device__ __forceinline__ void cp16(uint32_t s, const void* g) {
    asm volatile("cp.async.cg.shared.global [%0], [%1], 16;" :: "r"(s), "l"(g));
}
#define CP_COMMIT() asm volatile("cp.async.commit_group;")
#define CP_WAIT(n)  asm volatile("cp.async.wait_group %0;" :: "n"(n))

__device__ __forceinline__ void ldsm4(uint32_t& r0, uint32_t& r1, uint32_t& r2, uint32_t& r3, uint32_t a) {
    asm volatile("ldmatrix.sync.aligned.m8n8.x4.shared.b16 {%0,%1,%2,%3}, [%4];"
                 : "=r"(r0), "=r"(r1), "=r"(r2), "=r"(r3) : "r"(a));
}
__device__ __forceinline__ void ldsm2t(uint32_t& r0, uint32_t& r1, uint32_t a) {
    asm volatile("ldmatrix.sync.aligned.m8n8.x2.trans.shared.b16 {%0,%1}, [%2];"
                 : "=r"(r0), "=r"(r1) : "r"(a));
}
__device__ __forceinline__ void mma16816(float* c, const uint32_t* a, const uint32_t* b) {
    asm volatile("mma.sync.aligned.m16n8k16.row.col.f32.bf16.bf16.f32 "
                 "{%0,%1,%2,%3}, {%4,%5,%6,%7}, {%8,%9}, {%0,%1,%2,%3};"
                 : "+f"(c[0]), "+f"(c[1]), "+f"(c[2]), "+f"(c[3])
                 : "r"(a[0]), "r"(a[1]), "r"(a[2]), "r"(a[3]), "r"(b[0]), "r"(b[1]));
}

__device__ __forceinline__ void hilo2(float v0, float v1, __nv_bfloat162& hp, __nv_bfloat162& lp) {
    __nv_bfloat16 h0 = __float2bfloat16(v0), h1 = __float2bfloat16(v1);
    hp.x = h0; hp.y = h1;
    lp.x = __float2bfloat16(v0 - __bfloat162float(h0));
    lp.y = __float2bfloat16(v1 - __bfloat162float(h1));
}
__device__ __forceinline__ uint32_t pk_hi(float x, float y) {
    __nv_bfloat162 t; t.x = __float2bfloat16(x); t.y = __float2bfloat16(y);
    return *(uint32_t*)&t;
}
__device__ __forceinline__ uint32_t pk_lo(float x, float y, uint32_t hi) {
    __nv_bfloat162 h = *(__nv_bfloat162*)&hi;
    __nv_bfloat162 t;
    t.x = __float2bfloat16(x - __bfloat162float(h.x));
    t.y = __float2bfloat16(y - __bfloat162float(h.y));
    return *(uint32_t*)&t;
}

// epilogue modes
enum { M_QA = 0, M_KB = 1, M_VHL = 2, M_FIN = 3 };

__device__ __forceinline__ void emit_pair(int mode, int m, int n, float v0, float v1,
                                          void* out0, const float* bias)
{
    v0 += bias[n]; v1 += bias[n + 1];
    if (mode == M_FIN) {
        float2 w; w.x = v0; w.y = v1;
        *(float2*)((float*)out0 + (size_t)m * DMODEL + n) = w;
        return;
    }
    __nv_bfloat162 hp, lp;
    hilo2(v0, v1, hp, lp);
    __nv_bfloat16* ob = (__nv_bfloat16*)out0;
    int b = m >> 10, s = m & 1023, h = n >> 6, d = n & 63;
    if (mode == M_VHL) {
        size_t base = ((size_t)(b * NHEAD + h) * SSEQ + s) * DHEAD + d;
        *(__nv_bfloat162*)(ob + base)          = hp;
        *(__nv_bfloat162*)(ob + base + VOFFBH) = lp;
    } else {
        size_t base = ((size_t)(b * NHEAD + h) * SSEQ + s) * KSC + d;
        *(__nv_bfloat162*)(ob + base) = hp;
        if (mode == M_QA) {
            *(__nv_bfloat162*)(ob + base + DHEAD)     = lp;
            *(__nv_bfloat162*)(ob + base + 2 * DHEAD) = hp;
        } else {
            *(__nv_bfloat162*)(ob + base + DHEAD)     = hp;
            *(__nv_bfloat162*)(ob + base + 2 * DHEAD) = lp;
        }
    }
}

// ============================ proj / final GEMM (HMMA) ======================
__global__ __launch_bounds__(256) void hgemm(
    const __nv_bfloat16* __restrict__ Ag, const __nv_bfloat16* __restrict__ Bg,
    const float* __restrict__ bias, void* __restrict__ out0, int mode)
{
    constexpr int BM = 128, BN = 128, BK = 64, K = KP;
    constexpr int WM = 64, WN = 32;                 // 2x4 warps
    constexpr int MI = WM / 16, NI = WN / 8;
    constexpr int SA = BM * BK * 2, SB = BN * BK * 2, STG = SA + SB;

    extern __shared__ char smem[];
    const uint32_t sbase = smem_u32(smem);
    const int tid = threadIdx.x, l = tid & 31, wid = tid >> 5;
    const int row0 = blockIdx.y * BM, col0 = blockIdx.x * BN;
    const int wm0 = (wid / 4) * WM, wn0 = (wid % 4) * WN;

    auto issue = [&](int ch, int st) {
        const int k0 = ch * BK;
        const uint32_t sA = sbase + st * STG;
        const uint32_t sB = sA + SA;
        for (int i = tid; i < BM * 8; i += 256) {
            int r = i >> 3, v = i & 7;
            cp16(sA + SWZ(r * 128 + v * 16), Ag + (size_t)(row0 + r) * K + k0 + v * 8);
        }
        for (int i = tid; i < BN * 8; i += 256) {
            int r = i >> 3, v = i & 7;
            cp16(sB + SWZ(r * 128 + v * 16), Bg + (size_t)(col0 + r) * K + k0 + v * 8);
        }
    };

    float c[MI][NI][4] = {};
    const int nch = K / BK;
    issue(0, 0); CP_COMMIT();

    for (int ch = 0; ch < nch; ch++) {
        if (ch + 1 < nch) { issue(ch + 1, (ch + 1) & 1); CP_COMMIT(); CP_WAIT(1); }
        else              { CP_WAIT(0); }
        __syncthreads();

        const uint32_t sA = sbase + (ch & 1) * STG;
        const uint32_t sB = sA + SA;

        #pragma unroll
        for (int ks = 0; ks < 4; ks++) {
            uint32_t af[MI][4];
            #pragma unroll
            for (int im = 0; im < MI; im++)
                ldsm4(af[im][0], af[im][1], af[im][2], af[im][3],
                      sA + SWZ((wm0 + im * 16 + (l & 15)) * 128 + ks * 32 + ((l >> 4) & 1) * 16));
            uint32_t bf[NI][2];
            #pragma unroll
            for (int i2 = 0; i2 < NI / 2; i2++) {
                int g = l >> 3;
                uint32_t r0, r1, r2, r3;
                ldsm4(r0, r1, r2, r3,
                      sB + SWZ((wn0 + i2 * 16 + ((g >> 1) & 1) * 8 + (l & 7)) * 128 + ks * 32 + (g & 1) * 16));
                bf[2 * i2][0] = r0; bf[2 * i2][1] = r1;
                bf[2 * i2 + 1][0] = r2; bf[2 * i2 + 1][1] = r3;
            }
            #pragma unroll
            for (int im = 0; im < MI; im++)
                #pragma unroll
                for (int in = 0; in < NI; in++)
                    mma16816(c[im][in], af[im], bf[in]);
        }
        __syncthreads();
    }

    #pragma unroll
    for (int im = 0; im < MI; im++)
        #pragma unroll
        for (int in = 0; in < NI; in++) {
            int r = row0 + wm0 + im * 16 + (l >> 2);
            int n = col0 + wn0 + in * 8 + (l & 3) * 2;
            emit_pair(mode, r,     n, c[im][in][0], c[im][in][1], out0, bias);
            emit_pair(mode, r + 8, n, c[im][in][2], c[im][in][3], out0, bias);
        }
}

// ============================ fused attention ===============================
// Per CTA: (bh, 128 q-rows). S = QK^T/8 packed 3-term; P~=exp(S) unnormalized;
// write P~ fp32 to attn; O += P~ @ V (3-term hi/lo in-register); l = row sums.
// Epilogue: ctx = O/l packed to cP; l to g_l. Rescale kernel fixes attn.
#define SQ_OFF  0                         // 3 x 16KB Q chunks
#define SK_OFF  49152                     // 2 x 48KB K buffers
#define SV_OFF  (49152 + 98304)           // Vh 16KB + Vl 16KB
#define FSM_BYTES (SV_OFF + 32768)        // 180224

__global__ __launch_bounds__(256, 1) void fused_attn(
    const __nv_bfloat16* __restrict__ Qp, const __nv_bfloat16* __restrict__ Kp,
    const __nv_bfloat16* __restrict__ Vhl,
    float* __restrict__ attn, float* __restrict__ lbuf,
    __nv_bfloat16* __restrict__ cP)
{
    extern __shared__ char smem[];
    const uint32_t sbase = smem_u32(smem);
    const int tid = threadIdx.x, l = tid & 31, wid = tid >> 5;
    const int bh = blockIdx.y, q0 = blockIdx.x * 128;
    const int wm0 = wid * 16;

    const __nv_bfloat16* Qb = Qp + (size_t)bh * SSEQ * KSC;
    const __nv_bfloat16* Kb = Kp + (size_t)bh * SSEQ * KSC;
    const __nv_bfloat16* Vh = Vhl + (size_t)bh * SSEQ * DHEAD;
    const __nv_bfloat16* Vl = Vh + VOFFBH;

    auto issueK = [&](int t, int st) {
        const uint32_t kb = sbase + SK_OFF + st * 49152;
        for (int i = tid; i < 3072; i += 256) {
            int c = i >> 10, r = (i >> 3) & 127, v = i & 7;
            cp16(kb + c * 16384 + SWZ(r * 128 + v * 16),
                 Kb + (size_t)(t * 128 + r) * KSC + c * 64 + v * 8);
        }
    };
    auto issueV = [&](int t) {
        for (int i = tid; i < 1024; i += 256) {
            int r = i >> 3, v = i & 7;
            size_t go = (size_t)(t * 128 + r) * DHEAD + v * 8;
            cp16(sbase + SV_OFF + SWZ(r * 128 + v * 16),         Vh + go);
            cp16(sbase + SV_OFF + 16384 + SWZ(r * 128 + v * 16), Vl + go);
        }
    };

    // preload Q (persistent) + K tile 0
    for (int i = tid; i < 3072; i += 256) {
        int c = i >> 10, r = (i >> 3) & 127, v = i & 7;
        cp16(sbase + SQ_OFF + c * 16384 + SWZ(r * 128 + v * 16),
             Qb + (size_t)(q0 + r) * KSC + c * 64 + v * 8);
    }
    issueK(0, 0);
    CP_COMMIT();

    float c_o[8][4] = {};
    float lsum0 = 0.f, lsum1 = 0.f;

    for (int t = 0; t < 8; t++) {
        CP_WAIT(0);
        __syncthreads();
        issueV(t); CP_COMMIT();
        if (t < 7) { issueK(t + 1, (t + 1) & 1); CP_COMMIT(); }

        // ---- S tile: 128x128, warp rows [wm0, wm0+16) ----
        float cs[16][4] = {};
        const uint32_t kb = sbase + SK_OFF + (t & 1) * 49152;
        #pragma unroll
        for (int cch = 0; cch < 3; cch++) {
            const uint32_t sQ = sbase + SQ_OFF + cch * 16384;
            const uint32_t sK = kb + cch * 16384;
            #pragma unroll
            for (int ks = 0; ks < 4; ks++) {
                uint32_t af[4];
                ldsm4(af[0], af[1], af[2], af[3],
                      sQ + SWZ((wm0 + (l & 15)) * 128 + ks * 32 + ((l >> 4) & 1) * 16));
                #pragma unroll
                for (int i2 = 0; i2 < 8; i2++) {
                    int g = l >> 3;
                    uint32_t r0, r1, r2, r3;
                    ldsm4(r0, r1, r2, r3,
                          sK + SWZ((i2 * 16 + ((g >> 1) & 1) * 8 + (l & 7)) * 128 + ks * 32 + (g & 1) * 16));
                    uint32_t b0[2] = {r0, r1}, b1[2] = {r2, r3};
                    mma16816(cs[2 * i2],     af, b0);
                    mma16816(cs[2 * i2 + 1], af, b1);
                }
            }
        }

        // ---- exp, row-sum, write unnormalized attn ----
        #pragma unroll
        for (int in = 0; in < 16; in++) {
            cs[in][0] = __expf(cs[in][0] * 0.125f);
            cs[in][1] = __expf(cs[in][1] * 0.125f);
            cs[in][2] = __expf(cs[in][2] * 0.125f);
            cs[in][3] = __expf(cs[in][3] * 0.125f);
            lsum0 += cs[in][0] + cs[in][1];
            lsum1 += cs[in][2] + cs[in][3];
        }
        {
            float* a0 = attn + ((size_t)bh << 20) + (size_t)(q0 + wm0 + (l >> 2)) * SSEQ
                        + t * 128 + 2 * (l & 3);
            float* a1 = a0 + 8 * SSEQ;
            #pragma unroll
            for (int in = 0; in < 16; in++) {
                float2 w0; w0.x = cs[in][0]; w0.y = cs[in][1];
                float2 w1; w1.x = cs[in][2]; w1.y = cs[in][3];
                *(float2*)(a0 + in * 8) = w0;
                *(float2*)(a1 + in * 8) = w1;
            }
        }

        if (t < 7) CP_WAIT(1); else CP_WAIT(0);
        __syncthreads();   // V tile visible to all warps

        // ---- O += P~ @ V (3-term), A-frags straight from S accumulators ----
        const uint32_t sVh = sbase + SV_OFF, sVl = sVh + 16384;
        #pragma unroll
        for (int j = 0; j < 8; j++) {
            uint32_t ah[4], al[4];
            ah[0] = pk_hi(cs[2*j][0],   cs[2*j][1]);   al[0] = pk_lo(cs[2*j][0],   cs[2*j][1],   ah[0]);
            ah[1] = pk_hi(cs[2*j][2],   cs[2*j][3]);   al[1] = pk_lo(cs[2*j][2],   cs[2*j][3],   ah[1]);
            ah[2] = pk_hi(cs[2*j+1][0], cs[2*j+1][1]); al[2] = pk_lo(cs[2*j+1][0], cs[2*j+1][1], ah[2]);
            ah[3] = pk_hi(cs[2*j+1][2], cs[2*j+1][3]); al[3] = pk_lo(cs[2*j+1][2], cs[2*j+1][3], ah[3]);
            uint32_t vrow = (uint32_t)(j * 16 + ((l >> 3) & 1) * 8 + (l & 7)) * 128;
            #pragma unroll
            for (int in = 0; in < 8; in++) {
                uint32_t bh2[2], bl2[2];
                ldsm2t(bh2[0], bh2[1], sVh + SWZ(vrow + in * 16));
                ldsm2t(bl2[0], bl2[1], sVl + SWZ(vrow + in * 16));
                mma16816(c_o[in], ah, bh2);
                mma16816(c_o[in], al, bh2);
                mma16816(c_o[in], ah, bl2);
            }
        }
        __syncthreads();   // V/K buffers consumed
    }

    // ---- finalize: reduce l across the quad, write l, write ctx = O/l ----
    lsum0 += __shfl_xor_sync(0xffffffffu, lsum0, 1);
    lsum0 += __shfl_xor_sync(0xffffffffu, lsum0, 2);
    lsum1 += __shfl_xor_sync(0xffffffffu, lsum1, 1);
    lsum1 += __shfl_xor_sync(0xffffffffu, lsum1, 2);

    const int r0g = q0 + wm0 + (l >> 2);
    if ((l & 3) == 0) {
        lbuf[(size_t)bh * SSEQ + r0g]     = lsum0;
        lbuf[(size_t)bh * SSEQ + r0g + 8] = lsum1;
    }
    const float inv0 = 1.0f / lsum0, inv1 = 1.0f / lsum1;

    const int b = bh / NHEAD, h = bh % NHEAD;
    const size_t gm0 = (size_t)(b * SSEQ + r0g) * KP;
    const size_t gm1 = gm0 + (size_t)8 * KP;
    #pragma unroll
    for (int in = 0; in < 8; in++) {
        int d = h * DHEAD + in * 8 + 2 * (l & 3);
        __nv_bfloat162 hp, lp;
        hilo2(c_o[in][0] * inv0, c_o[in][1] * inv0, hp, lp);
        *(__nv_bfloat162*)(cP + gm0 + d)              = hp;
        *(__nv_bfloat162*)(cP + gm0 + d + DMODEL)     = lp;
        *(__nv_bfloat162*)(cP + gm0 + d + 2 * DMODEL) = hp;
        hilo2(c_o[in][2] * inv1, c_o[in][3] * inv1, hp, lp);
        *(__nv_bfloat162*)(cP + gm1 + d)              = hp;
        *(__nv_bfloat162*)(cP + gm1 + d + DMODEL)     = lp;
        *(__nv_bfloat162*)(cP + gm1 + d + 2 * DMODEL) = hp;
    }
}

// attn rescale: each block normalizes one 1024-float row by 1/l
__global__ __launch_bounds__(256) void rescale_attn(float* __restrict__ attn,
                                                    const float* __restrict__ lbuf)
{
    const size_t row = blockIdx.x;
    const float inv = 1.0f / lbuf[row];
    float4* p = (float4*)(attn + row * SSEQ);
    float4 v = p[threadIdx.x];
    v.x *= inv; v.y *= inv; v.z *= inv; v.w *= inv;
    p[threadIdx.x] = v;
}

// ============================ prep kernels ==================================
__global__ __launch_bounds__(256) void pack_a(const float* __restrict__ in, __nv_bfloat16* __restrict__ o)
{
    size_t i = (size_t)blockIdx.x * 256 + threadIdx.x;
    size_t m = i / (DMODEL / 2);
    int kk = (int)(i % (DMODEL / 2)) * 2;
    if (m >= MROWS) return;
    float2 v = *(const float2*)(in + m * DMODEL + kk);
    __nv_bfloat162 hp, lp;
    hilo2(v.x, v.y, hp, lp);
    size_t base = m * KP + kk;
    *(__nv_bfloat162*)(o + base)              = hp;
    *(__nv_bfloat162*)(o + base + DMODEL)     = lp;
    *(__nv_bfloat162*)(o + base + 2 * DMODEL) = hp;
}

__global__ void pack_w(const float* __restrict__ W, __nv_bfloat16* __restrict__ o)
{
    __shared__ float t[32][33];
    int n0 = blockIdx.x * 32, k0 = blockIdx.y * 32;
    int x = threadIdx.x, y = threadIdx.y;
    #pragma unroll
    for (int j = 0; j < 32; j += 8)
        t[y + j][x] = W[(size_t)(k0 + y + j) * DMODEL + n0 + x];
    __syncthreads();
    #pragma unroll
    for (int j = 0; j < 32; j += 8) {
        float v = t[x][y + j];
        size_t base = (size_t)(n0 + y + j) * KP + k0 + x;
        __nv_bfloat16 h = __float2bfloat16(v);
        o[base] = h;
        o[base + DMODEL] = h;
        o[base + 2 * DMODEL] = __float2bfloat16(v - __bfloat162float(h));
    }
}

// ============================ host launcher =================================
extern "C" void kernel_launch(void* const* d_in, const int* in_sizes, int n_in,
                              void* d_out, int out_size)
{
    (void)in_sizes; (void)n_in;
    const float* x  = (const float*)d_in[0];
    const float* Wq = (const float*)d_in[1];
    const float* bq = (const float*)d_in[2];
    const float* Wk = (const float*)d_in[3];
    const float* bk = (const float*)d_in[4];
    const float* Wv = (const float*)d_in[5];
    const float* bv = (const float*)d_in[6];
    const float* Wo = (const float*)d_in[7];
    const float* bo = (const float*)d_in[8];
    float* out = (float*)d_out;

    float *gattn, *gl;
    __nv_bfloat16 *xP, *wqP, *wkP, *wvP, *woP, *qP, *kP, *vhl, *cP;
    cudaGetSymbolAddress((void**)&gattn, g_attn);
    cudaGetSymbolAddress((void**)&gl,  g_l);
    cudaGetSymbolAddress((void**)&xP,  g_xP);
    cudaGetSymbolAddress((void**)&wqP, g_wqP);
    cudaGetSymbolAddress((void**)&wkP, g_wkP);
    cudaGetSymbolAddress((void**)&wvP, g_wvP);
    cudaGetSymbolAddress((void**)&woP, g_woP);
    cudaGetSymbolAddress((void**)&qP,  g_qP);
    cudaGetSymbolAddress((void**)&kP,  g_kP);
    cudaGetSymbolAddress((void**)&vhl, g_vhl);
    cudaGetSymbolAddress((void**)&cP,  g_cP);

    const size_t final_elems = (size_t)MROWS * DMODEL;
    float* attn = ((size_t)out_size > final_elems) ? (out + final_elems) : gattn;

    constexpr int SM_GEMM = 2 * (128 * 64 * 2 + 128 * 64 * 2);   // 64 KB
    cudaFuncSetAttribute(hgemm,      cudaFuncAttributeMaxDynamicSharedMemorySize, SM_GEMM);
    cudaFuncSetAttribute(fused_attn, cudaFuncAttributeMaxDynamicSharedMemorySize, FSM_BYTES);

    // pack inputs
    {
        size_t pairs = (size_t)MROWS * (DMODEL / 2);
        pack_a<<<(unsigned)((pairs + 255) / 256), 256>>>(x, xP);
        dim3 tb(32, 8), tg(DMODEL / 32, DMODEL / 32);
        pack_w<<<tg, tb>>>(Wq, wqP);
        pack_w<<<tg, tb>>>(Wk, wkP);
        pack_w<<<tg, tb>>>(Wv, wvP);
        pack_w<<<tg, tb>>>(Wo, woP);
    }

    // QKV projections
    dim3 gproj(DMODEL / 128, MROWS / 128);        // (6, 64)
    hgemm<<<gproj, 256, SM_GEMM>>>(xP, wqP, bq, qP,  M_QA);
    hgemm<<<gproj, 256, SM_GEMM>>>(xP, wkP, bk, kP,  M_KB);
    hgemm<<<gproj, 256, SM_GEMM>>>(xP, wvP, bv, vhl, M_VHL);

    // fused scores + softmax + AV
    dim3 gf(SSEQ / 128, NBH);                     // (8, 96)
    fused_attn<<<gf, 256, FSM_BYTES>>>(qP, kP, vhl, attn, gl, cP);

    // normalize attn rows
    rescale_attn<<<NBH * SSEQ, 256>>>(attn, gl);

    // out = ctx @ Wo + bo
    hgemm<<<gproj, 256, SM_GEMM>>>(cP, woP, bo, out, M_FIN);
}

// round 5
// speedup vs baseline: 2.6107x; 1.0898x over previous
#include <cuda_runtime.h>
#include <cuda_bf16.h>
#include <cstdint>

#define BBATCH 8
#define SSEQ   1024
#define DMODEL 768
#define NHEAD  12
#define DHEAD  64
#define MROWS  (BBATCH*SSEQ)     // 8192
#define NBH    (BBATCH*NHEAD)    // 96
#define KP     (3*DMODEL)        // 2304
#define KSC    (3*DHEAD)         // 192
#define VOFFBH ((size_t)NBH*SSEQ*DHEAD)

// ---------------- scratch (device globals; no allocations allowed) ----------
__device__ float g_attn[(size_t)NBH*SSEQ*SSEQ];
__device__ float g_l[(size_t)NBH*SSEQ];
__device__ __nv_bfloat16 g_xP   [(size_t)MROWS*KP];
__device__ __nv_bfloat16 g_wqkvP[(size_t)3*DMODEL*KP];          // Wq|Wk|Wv rows
__device__ __nv_bfloat16 g_woP  [(size_t)DMODEL*KP];
__device__ __nv_bfloat16 g_qP [(size_t)NBH*SSEQ*KSC];           // [hi|lo|hi]
__device__ __nv_bfloat16 g_kP [(size_t)NBH*SSEQ*KSC];           // [hi|hi|lo]
__device__ __nv_bfloat16 g_vhl[2*VOFFBH];                       // V hi then lo
__device__ __nv_bfloat16 g_cP [(size_t)MROWS*KP];               // ctx [hi|lo|hi]

// ============================ PTX helpers ===================================
__device__ __forceinline__ uint32_t smem_u32(const void* p) {
    uint32_t a;
    asm("{ .reg .u64 t; cvta.to.shared.u64 t, %1; cvt.u32.u64 %0, t; }" : "=r"(a) : "l"(p));
    return a;
}
#define SWZ(o) ((uint32_t)(o) ^ ((((uint32_t)(o)) >> 3) & 0x70))

__device__ __forceinline__ void cp16(uint32_t s, const void* g) {
    asm volatile("cp.async.cg.shared.global [%0], [%1], 16;" :: "r"(s), "l"(g));
}
#define CP_COMMIT() asm volatile("cp.async.commit_group;")
#define CP_WAIT(n)  asm volatile("cp.async.wait_group %0;" :: "n"(n))

__device__ __forceinline__ void ldsm4(uint32_t& r0, uint32_t& r1, uint32_t& r2, uint32_t& r3, uint32_t a) {
    asm volatile("ldmatrix.sync.aligned.m8n8.x4.shared.b16 {%0,%1,%2,%3}, [%4];"
                 : "=r"(r0), "=r"(r1), "=r"(r2), "=r"(r3) : "r"(a));
}
__device__ __forceinline__ void ldsm4t(uint32_t& r0, uint32_t& r1, uint32_t& r2, uint32_t& r3, uint32_t a) {
    asm volatile("ldmatrix.sync.aligned.m8n8.x4.trans.shared.b16 {%0,%1,%2,%3}, [%4];"
                 : "=r"(r0), "=r"(r1), "=r"(r2), "=r"(r3) : "r"(a));
}
__device__ __forceinline__ void mma16816(float* c, const uint32_t* a, const uint32_t* b) {
    asm volatile("mma.sync.aligned.m16n8k16.row.col.f32.bf16.bf16.f32 "
                 "{%0,%1,%2,%3}, {%4,%5,%6,%7}, {%8,%9}, {%0,%1,%2,%3};"
                 : "+f"(c[0]), "+f"(c[1]), "+f"(c[2]), "+f"(c[3])
                 : "r"(a[0]), "r"(a[1]), "r"(a[2]), "r"(a[3]), "r"(b[0]), "r"(b[1]));
}

__device__ __forceinline__ void hilo2(float v0, float v1, __nv_bfloat162& hp, __nv_bfloat162& lp) {
    __nv_bfloat16 h0 = __float2bfloat16(v0), h1 = __float2bfloat16(v1);
    hp.x = h0; hp.y = h1;
    lp.x = __float2bfloat16(v0 - __bfloat162float(h0));
    lp.y = __float2bfloat16(v1 - __bfloat162float(h1));
}
__device__ __forceinline__ uint32_t pk_hi(float x, float y) {
    __nv_bfloat162 t; t.x = __float2bfloat16(x); t.y = __float2bfloat16(y);
    return *(uint32_t*)&t;
}
__device__ __forceinline__ uint32_t pk_lo(float x, float y, uint32_t hi) {
    __nv_bfloat162 h = *(__nv_bfloat162*)&hi;
    __nv_bfloat162 t;
    t.x = __float2bfloat16(x - __bfloat162float(h.x));
    t.y = __float2bfloat16(y - __bfloat162float(h.y));
    return *(uint32_t*)&t;
}

// ============================ unified GEMM (HMMA) ===========================
// mode 0: QKV merged (N=2304, col sel -> q/k/v epilogues)
// mode 1: final     (N=768, fp32 out + bias)
__global__ __launch_bounds__(256) void hgemm(
    const __nv_bfloat16* __restrict__ Ag, const __nv_bfloat16* __restrict__ Bg,
    const float* __restrict__ b0p, const float* __restrict__ b1p, const float* __restrict__ b2p,
    void* __restrict__ o0, void* __restrict__ o1, void* __restrict__ o2,
    int mode)
{
    constexpr int BM = 128, BN = 128, BK = 64, K = KP;
    constexpr int MI = 4, NI = 4;                   // 2x4 warps, 64x32 per warp
    constexpr int SA = BM * BK * 2, SB = BN * BK * 2, STG = SA + SB;

    extern __shared__ char smem[];
    const uint32_t sbase = smem_u32(smem);
    const int tid = threadIdx.x, l = tid & 31, wid = tid >> 5;
    const int row0 = blockIdx.y * BM, col0 = blockIdx.x * BN;
    const int wm0 = (wid / 4) * 64, wn0 = (wid % 4) * 32;

    auto issue = [&](int ch, int st) {
        const int k0 = ch * BK;
        const uint32_t sA = sbase + st * STG;
        const uint32_t sB = sA + SA;
        for (int i = tid; i < BM * 8; i += 256) {
            int r = i >> 3, v = i & 7;
            cp16(sA + SWZ(r * 128 + v * 16), Ag + (size_t)(row0 + r) * K + k0 + v * 8);
        }
        for (int i = tid; i < BN * 8; i += 256) {
            int r = i >> 3, v = i & 7;
            cp16(sB + SWZ(r * 128 + v * 16), Bg + (size_t)(col0 + r) * K + k0 + v * 8);
        }
    };

    float c[MI][NI][4] = {};
    const int nch = K / BK;
    issue(0, 0); CP_COMMIT();

    for (int ch = 0; ch < nch; ch++) {
        if (ch + 1 < nch) { issue(ch + 1, (ch + 1) & 1); CP_COMMIT(); CP_WAIT(1); }
        else              { CP_WAIT(0); }
        __syncthreads();

        const uint32_t sA = sbase + (ch & 1) * STG;
        const uint32_t sB = sA + SA;

        #pragma unroll
        for (int ks = 0; ks < 4; ks++) {
            uint32_t af[MI][4];
            #pragma unroll
            for (int im = 0; im < MI; im++)
                ldsm4(af[im][0], af[im][1], af[im][2], af[im][3],
                      sA + SWZ((wm0 + im * 16 + (l & 15)) * 128 + ks * 32 + ((l >> 4) & 1) * 16));
            uint32_t bf[NI][2];
            #pragma unroll
            for (int i2 = 0; i2 < NI / 2; i2++) {
                int g = l >> 3;
                uint32_t r0, r1, r2, r3;
                ldsm4(r0, r1, r2, r3,
                      sB + SWZ((wn0 + i2 * 16 + ((g >> 1) & 1) * 8 + (l & 7)) * 128 + ks * 32 + (g & 1) * 16));
                bf[2 * i2][0] = r0; bf[2 * i2][1] = r1;
                bf[2 * i2 + 1][0] = r2; bf[2 * i2 + 1][1] = r3;
            }
            #pragma unroll
            for (int im = 0; im < MI; im++)
                #pragma unroll
                for (int in = 0; in < NI; in++)
                    mma16816(c[im][in], af[im], bf[in]);
        }
        __syncthreads();
    }

    // epilogue
    #pragma unroll
    for (int im = 0; im < MI; im++)
        #pragma unroll
        for (int in = 0; in < NI; in++) {
            #pragma unroll
            for (int half = 0; half < 2; half++) {
                int m = row0 + wm0 + im * 16 + (l >> 2) + half * 8;
                int n = col0 + wn0 + in * 8 + (l & 3) * 2;
                float v0 = c[im][in][2 * half], v1 = c[im][in][2 * half + 1];
                if (mode == 1) {
                    v0 += b0p[n]; v1 += b0p[n + 1];
                    float2 w; w.x = v0; w.y = v1;
                    *(float2*)((float*)o0 + (size_t)m * DMODEL + n) = w;
                    continue;
                }
                int sel = n / DMODEL, d = n % DMODEL;
                const float* bs = (sel == 0) ? b0p : (sel == 1) ? b1p : b2p;
                v0 += bs[d]; v1 += bs[d + 1];
                __nv_bfloat162 hp, lp;
                hilo2(v0, v1, hp, lp);
                int b = m >> 10, s = m & 1023, h = d >> 6, dd = d & 63;
                __nv_bfloat16* ob = (sel == 0) ? (__nv_bfloat16*)o0
                                  : (sel == 1) ? (__nv_bfloat16*)o1 : (__nv_bfloat16*)o2;
                if (sel == 2) {
                    size_t base = ((size_t)(b * NHEAD + h) * SSEQ + s) * DHEAD + dd;
                    *(__nv_bfloat162*)(ob + base)          = hp;
                    *(__nv_bfloat162*)(ob + base + VOFFBH) = lp;
                } else {
                    size_t base = ((size_t)(b * NHEAD + h) * SSEQ + s) * KSC + dd;
                    *(__nv_bfloat162*)(ob + base) = hp;
                    if (sel == 0) {
                        *(__nv_bfloat162*)(ob + base + DHEAD)     = lp;
                        *(__nv_bfloat162*)(ob + base + 2 * DHEAD) = hp;
                    } else {
                        *(__nv_bfloat162*)(ob + base + DHEAD)     = hp;
                        *(__nv_bfloat162*)(ob + base + 2 * DHEAD) = lp;
                    }
                }
            }
        }
}

// ============================ fused attention ===============================
#define SQ_OFF  0
#define SK_OFF  49152
#define SV_OFF  (49152 + 98304)
#define FSM_BYTES (SV_OFF + 32768)

__global__ __launch_bounds__(256, 1) void fused_attn(
    const __nv_bfloat16* __restrict__ Qp, const __nv_bfloat16* __restrict__ Kp,
    const __nv_bfloat16* __restrict__ Vhl,
    float* __restrict__ attn, float* __restrict__ lbuf,
    __nv_bfloat16* __restrict__ cP)
{
    extern __shared__ char smem[];
    const uint32_t sbase = smem_u32(smem);
    const int tid = threadIdx.x, l = tid & 31, wid = tid >> 5;
    const int bh = blockIdx.y, q0 = blockIdx.x * 128;
    const int wm0 = wid * 16;

    const __nv_bfloat16* Qb = Qp + (size_t)bh * SSEQ * KSC;
    const __nv_bfloat16* Kb = Kp + (size_t)bh * SSEQ * KSC;
    const __nv_bfloat16* Vh = Vhl + (size_t)bh * SSEQ * DHEAD;
    const __nv_bfloat16* Vl = Vh + VOFFBH;

    auto issueK = [&](int t, int st) {
        const uint32_t kb = sbase + SK_OFF + st * 49152;
        for (int i = tid; i < 3072; i += 256) {
            int c = i >> 10, r = (i >> 3) & 127, v = i & 7;
            cp16(kb + c * 16384 + SWZ(r * 128 + v * 16),
                 Kb + (size_t)(t * 128 + r) * KSC + c * 64 + v * 8);
        }
    };
    auto issueV = [&](int t) {
        for (int i = tid; i < 1024; i += 256) {
            int r = i >> 3, v = i & 7;
            size_t go = (size_t)(t * 128 + r) * DHEAD + v * 8;
            cp16(sbase + SV_OFF + SWZ(r * 128 + v * 16),         Vh + go);
            cp16(sbase + SV_OFF + 16384 + SWZ(r * 128 + v * 16), Vl + go);
        }
    };

    for (int i = tid; i < 3072; i += 256) {
        int c = i >> 10, r = (i >> 3) & 127, v = i & 7;
        cp16(sbase + SQ_OFF + c * 16384 + SWZ(r * 128 + v * 16),
             Qb + (size_t)(q0 + r) * KSC + c * 64 + v * 8);
    }
    issueK(0, 0);
    CP_COMMIT();

    float c_o[8][4] = {};
    float lsum0 = 0.f, lsum1 = 0.f;

    for (int t = 0; t < 8; t++) {
        CP_WAIT(0);
        __syncthreads();
        issueV(t); CP_COMMIT();
        if (t < 7) { issueK(t + 1, (t + 1) & 1); CP_COMMIT(); }

        // ---- S tile ----
        float cs[16][4] = {};
        const uint32_t kb = sbase + SK_OFF + (t & 1) * 49152;
        #pragma unroll
        for (int cch = 0; cch < 3; cch++) {
            const uint32_t sQ = sbase + SQ_OFF + cch * 16384;
            const uint32_t sK = kb + cch * 16384;
            #pragma unroll
            for (int ks = 0; ks < 4; ks++) {
                uint32_t af[4];
                ldsm4(af[0], af[1], af[2], af[3],
                      sQ + SWZ((wm0 + (l & 15)) * 128 + ks * 32 + ((l >> 4) & 1) * 16));
                #pragma unroll
                for (int i2 = 0; i2 < 8; i2++) {
                    int g = l >> 3;
                    uint32_t r0, r1, r2, r3;
                    ldsm4(r0, r1, r2, r3,
                          sK + SWZ((i2 * 16 + ((g >> 1) & 1) * 8 + (l & 7)) * 128 + ks * 32 + (g & 1) * 16));
                    uint32_t b0[2] = {r0, r1}, b1[2] = {r2, r3};
                    mma16816(cs[2 * i2],     af, b0);
                    mma16816(cs[2 * i2 + 1], af, b1);
                }
            }
        }

        // ---- exp + row-sum + unnormalized attn write ----
        #pragma unroll
        for (int in = 0; in < 16; in++) {
            cs[in][0] = __expf(cs[in][0] * 0.125f);
            cs[in][1] = __expf(cs[in][1] * 0.125f);
            cs[in][2] = __expf(cs[in][2] * 0.125f);
            cs[in][3] = __expf(cs[in][3] * 0.125f);
            lsum0 += cs[in][0] + cs[in][1];
            lsum1 += cs[in][2] + cs[in][3];
        }
        {
            float* a0 = attn + ((size_t)bh << 20) + (size_t)(q0 + wm0 + (l >> 2)) * SSEQ
                        + t * 128 + 2 * (l & 3);
            float* a1 = a0 + 8 * SSEQ;
            #pragma unroll
            for (int in = 0; in < 16; in++) {
                float2 w0; w0.x = cs[in][0]; w0.y = cs[in][1];
                float2 w1; w1.x = cs[in][2]; w1.y = cs[in][3];
                *(float2*)(a0 + in * 8) = w0;
                *(float2*)(a1 + in * 8) = w1;
            }
        }

        if (t < 7) CP_WAIT(1); else CP_WAIT(0);
        __syncthreads();

        // ---- O += P~ @ V (3-term), V via ldmatrix.x4.trans ----
        const uint32_t sVh = sbase + SV_OFF, sVl = sVh + 16384;
        #pragma unroll
        for (int j = 0; j < 8; j++) {
            uint32_t ah[4], al[4];
            ah[0] = pk_hi(cs[2*j][0],   cs[2*j][1]);   al[0] = pk_lo(cs[2*j][0],   cs[2*j][1],   ah[0]);
            ah[1] = pk_hi(cs[2*j][2],   cs[2*j][3]);   al[1] = pk_lo(cs[2*j][2],   cs[2*j][3],   ah[1]);
            ah[2] = pk_hi(cs[2*j+1][0], cs[2*j+1][1]); al[2] = pk_lo(cs[2*j+1][0], cs[2*j+1][1], ah[2]);
            ah[3] = pk_hi(cs[2*j+1][2], cs[2*j+1][3]); al[3] = pk_lo(cs[2*j+1][2], cs[2*j+1][3], ah[3]);
            uint32_t vrow = (uint32_t)(j * 16 + ((l >> 3) & 1) * 8 + (l & 7)) * 128
                          + ((uint32_t)(l >> 4)) * 16;
            #pragma unroll
            for (int in = 0; in < 8; in += 2) {
                uint32_t h0, h1, h2, h3, q0r, q1r, q2r, q3r;
                ldsm4t(h0, h1, h2, h3,   sVh + SWZ(vrow + in * 16));
                ldsm4t(q0r, q1r, q2r, q3r, sVl + SWZ(vrow + in * 16));
                uint32_t bh2[2] = {h0, h1}, bh3[2] = {h2, h3};
                uint32_t bl2[2] = {q0r, q1r}, bl3[2] = {q2r, q3r};
                mma16816(c_o[in],     ah, bh2);
                mma16816(c_o[in],     al, bh2);
                mma16816(c_o[in],     ah, bl2);
                mma16816(c_o[in + 1], ah, bh3);
                mma16816(c_o[in + 1], al, bh3);
                mma16816(c_o[in + 1], ah, bl3);
            }
        }
        __syncthreads();
    }

    // ---- finalize ----
    lsum0 += __shfl_xor_sync(0xffffffffu, lsum0, 1);
    lsum0 += __shfl_xor_sync(0xffffffffu, lsum0, 2);
    lsum1 += __shfl_xor_sync(0xffffffffu, lsum1, 1);
    lsum1 += __shfl_xor_sync(0xffffffffu, lsum1, 2);

    const int r0g = q0 + wm0 + (l >> 2);
    if ((l & 3) == 0) {
        lbuf[(size_t)bh * SSEQ + r0g]     = lsum0;
        lbuf[(size_t)bh * SSEQ + r0g + 8] = lsum1;
    }
    const float inv0 = 1.0f / lsum0, inv1 = 1.0f / lsum1;

    const int b = bh / NHEAD, h = bh % NHEAD;
    const size_t gm0 = (size_t)(b * SSEQ + r0g) * KP;
    const size_t gm1 = gm0 + (size_t)8 * KP;
    #pragma unroll
    for (int in = 0; in < 8; in++) {
        int d = h * DHEAD + in * 8 + 2 * (l & 3);
        __nv_bfloat162 hp, lp;
        hilo2(c_o[in][0] * inv0, c_o[in][1] * inv0, hp, lp);
        *(__nv_bfloat162*)(cP + gm0 + d)              = hp;
        *(__nv_bfloat162*)(cP + gm0 + d + DMODEL)     = lp;
        *(__nv_bfloat162*)(cP + gm0 + d + 2 * DMODEL) = hp;
        hilo2(c_o[in][2] * inv1, c_o[in][3] * inv1, hp, lp);
        *(__nv_bfloat162*)(cP + gm1 + d)              = hp;
        *(__nv_bfloat162*)(cP + gm1 + d + DMODEL)     = lp;
        *(__nv_bfloat162*)(cP + gm1 + d + 2 * DMODEL) = hp;
    }
}

__global__ __launch_bounds__(256) void rescale_attn(float* __restrict__ attn,
                                                    const float* __restrict__ lbuf)
{
    const size_t row = blockIdx.x;
    const float inv = 1.0f / lbuf[row];
    float4* p = (float4*)(attn + row * SSEQ);
    float4 v = p[threadIdx.x];
    v.x *= inv; v.y *= inv; v.z *= inv; v.w *= inv;
    p[threadIdx.x] = v;
}

// ============================ prep kernels ==================================
__global__ __launch_bounds__(256) void pack_a(const float* __restrict__ in, __nv_bfloat16* __restrict__ o)
{
    size_t i = (size_t)blockIdx.x * 256 + threadIdx.x;
    size_t m = i / (DMODEL / 2);
    int kk = (int)(i % (DMODEL / 2)) * 2;
    if (m >= MROWS) return;
    float2 v = *(const float2*)(in + m * DMODEL + kk);
    __nv_bfloat162 hp, lp;
    hilo2(v.x, v.y, hp, lp);
    size_t base = m * KP + kk;
    *(__nv_bfloat162*)(o + base)              = hp;
    *(__nv_bfloat162*)(o + base + DMODEL)     = lp;
    *(__nv_bfloat162*)(o + base + 2 * DMODEL) = hp;
}

__global__ void pack_w(const float* __restrict__ W, __nv_bfloat16* __restrict__ o)
{
    __shared__ float t[32][33];
    int n0 = blockIdx.x * 32, k0 = blockIdx.y * 32;
    int x = threadIdx.x, y = threadIdx.y;
    #pragma unroll
    for (int j = 0; j < 32; j += 8)
        t[y + j][x] = W[(size_t)(k0 + y + j) * DMODEL + n0 + x];
    __syncthreads();
    #pragma unroll
    for (int j = 0; j < 32; j += 8) {
        float v = t[x][y + j];
        size_t base = (size_t)(n0 + y + j) * KP + k0 + x;
        __nv_bfloat16 h = __float2bfloat16(v);
        o[base] = h;
        o[base + DMODEL] = h;
        o[base + 2 * DMODEL] = __float2bfloat16(v - __bfloat162float(h));
    }
}

// ============================ host launcher =================================
extern "C" void kernel_launch(void* const* d_in, const int* in_sizes, int n_in,
                              void* d_out, int out_size)
{
    (void)in_sizes; (void)n_in;
    const float* x  = (const float*)d_in[0];
    const float* Wq = (const float*)d_in[1];
    const float* bq = (const float*)d_in[2];
    const float* Wk = (const float*)d_in[3];
    const float* bk = (const float*)d_in[4];
    const float* Wv = (const float*)d_in[5];
    const float* bv = (const float*)d_in[6];
    const float* Wo = (const float*)d_in[7];
    const float* bo = (const float*)d_in[8];
    float* out = (float*)d_out;

    float *gattn, *gl;
    __nv_bfloat16 *xP, *wP, *woP, *qP, *kP, *vhl, *cP;
    cudaGetSymbolAddress((void**)&gattn, g_attn);
    cudaGetSymbolAddress((void**)&gl,  g_l);
    cudaGetSymbolAddress((void**)&xP,  g_xP);
    cudaGetSymbolAddress((void**)&wP,  g_wqkvP);
    cudaGetSymbolAddress((void**)&woP, g_woP);
    cudaGetSymbolAddress((void**)&qP,  g_qP);
    cudaGetSymbolAddress((void**)&kP,  g_kP);
    cudaGetSymbolAddress((void**)&vhl, g_vhl);
    cudaGetSymbolAddress((void**)&cP,  g_cP);

    const size_t final_elems = (size_t)MROWS * DMODEL;
    float* attn = ((size_t)out_size > final_elems) ? (out + final_elems) : gattn;

    static cudaStream_t s2 = nullptr;
    static cudaEvent_t evA = nullptr, evB = nullptr;
    if (s2 == nullptr) {
        cudaStreamCreateWithFlags(&s2, cudaStreamNonBlocking);
        cudaEventCreateWithFlags(&evA, cudaEventDisableTiming);
        cudaEventCreateWithFlags(&evB, cudaEventDisableTiming);
    }

    constexpr int SM_GEMM = 2 * (128 * 64 * 2 + 128 * 64 * 2);
    cudaFuncSetAttribute(hgemm,      cudaFuncAttributeMaxDynamicSharedMemorySize, SM_GEMM);
    cudaFuncSetAttribute(fused_attn, cudaFuncAttributeMaxDynamicSharedMemorySize, FSM_BYTES);

    // pack inputs (Wq|Wk|Wv into one row-concatenated packed buffer)
    {
        size_t pairs = (size_t)MROWS * (DMODEL / 2);
        pack_a<<<(unsigned)((pairs + 255) / 256), 256>>>(x, xP);
        dim3 tb(32, 8), tg(DMODEL / 32, DMODEL / 32);
        pack_w<<<tg, tb>>>(Wq, wP);
        pack_w<<<tg, tb>>>(Wk, wP + (size_t)DMODEL * KP);
        pack_w<<<tg, tb>>>(Wv, wP + (size_t)2 * DMODEL * KP);
        pack_w<<<tg, tb>>>(Wo, woP);
    }

    // merged QKV projection: one launch, N = 2304
    dim3 gqkv(3 * DMODEL / 128, MROWS / 128);     // (18, 64)
    hgemm<<<gqkv, 256, SM_GEMM>>>(xP, wP, bq, bk, bv, qP, kP, vhl, 0);

    // fused scores + softmax + AV
    dim3 gf(SSEQ / 128, NBH);                     // (8, 96)
    fused_attn<<<gf, 256, FSM_BYTES>>>(qP, kP, vhl, attn, gl, cP);

    // fork: rescale attn on s2, overlapped with the final GEMM on the main stream
    cudaEventRecord(evA, 0);
    cudaStreamWaitEvent(s2, evA, 0);
    rescale_attn<<<NBH * SSEQ, 256, 0, s2>>>(attn, gl);
    cudaEventRecord(evB, s2);

    // out = ctx @ Wo + bo (independent of attn rescale)
    dim3 gfin(DMODEL / 128, MROWS / 128);         // (6, 64)
    hgemm<<<gfin, 256, SM_GEMM>>>(cP, woP, bo, nullptr, nullptr, out, nullptr, nullptr, 1);

    // join
    cudaStreamWaitEvent(0, evB, 0);
}

// round 6
// speedup vs baseline: 2.7780x; 1.0641x over previous
#include <cuda_runtime.h>
#include <cuda_fp16.h>
#include <cstdint>

#define BBATCH 8
#define SSEQ   1024
#define DMODEL 768
#define NHEAD  12
#define DHEAD  64
#define MROWS  (BBATCH*SSEQ)     // 8192
#define NBH    (BBATCH*NHEAD)    // 96
#define KP     (3*DMODEL)        // 2304
#define KSC    (3*DHEAD)         // 192
#define WSC    32.0f             // weight pre-scale (keeps fp16 lo-residual normal)
#define WSCI   0.03125f

// ---------------- scratch (device globals; no allocations allowed) ----------
__device__ float g_attn[(size_t)NBH*SSEQ*SSEQ];
__device__ float g_l[(size_t)NBH*SSEQ];
__device__ __half g_xP   [(size_t)MROWS*KP];
__device__ __half g_wqkvP[(size_t)3*DMODEL*KP];          // Wq|Wk|Wv rows (x32, [hi|hi|lo])
__device__ __half g_woP  [(size_t)DMODEL*KP];
__device__ __half g_qP [(size_t)NBH*SSEQ*KSC];           // q*0.125, [hi|lo|hi]
__device__ __half g_kP [(size_t)NBH*SSEQ*KSC];           // [hi|hi|lo]
__device__ __half g_v  [(size_t)NBH*SSEQ*DHEAD];         // V single fp16
__device__ __half g_cP [(size_t)MROWS*KP];               // ctx [hi|lo|hi]

// ============================ PTX helpers ===================================
__device__ __forceinline__ uint32_t smem_u32(const void* p) {
    uint32_t a;
    asm("{ .reg .u64 t; cvta.to.shared.u64 t, %1; cvt.u32.u64 %0, t; }" : "=r"(a) : "l"(p));
    return a;
}
#define SWZ(o) ((uint32_t)(o) ^ ((((uint32_t)(o)) >> 3) & 0x70))

__device__ __forceinline__ void cp16(uint32_t s, const void* g) {
    asm volatile("cp.async.cg.shared.global [%0], [%1], 16;" :: "r"(s), "l"(g));
}
#define CP_COMMIT() asm volatile("cp.async.commit_group;")
#define CP_WAIT(n)  asm volatile("cp.async.wait_group %0;" :: "n"(n))

__device__ __forceinline__ void ldsm4(uint32_t& r0, uint32_t& r1, uint32_t& r2, uint32_t& r3, uint32_t a) {
    asm volatile("ldmatrix.sync.aligned.m8n8.x4.shared.b16 {%0,%1,%2,%3}, [%4];"
                 : "=r"(r0), "=r"(r1), "=r"(r2), "=r"(r3) : "r"(a));
}
__device__ __forceinline__ void ldsm4t(uint32_t& r0, uint32_t& r1, uint32_t& r2, uint32_t& r3, uint32_t a) {
    asm volatile("ldmatrix.sync.aligned.m8n8.x4.trans.shared.b16 {%0,%1,%2,%3}, [%4];"
                 : "=r"(r0), "=r"(r1), "=r"(r2), "=r"(r3) : "r"(a));
}
__device__ __forceinline__ void mma16816(float* c, const uint32_t* a, const uint32_t* b) {
    asm volatile("mma.sync.aligned.m16n8k16.row.col.f32.f16.f16.f32 "
                 "{%0,%1,%2,%3}, {%4,%5,%6,%7}, {%8,%9}, {%0,%1,%2,%3};"
                 : "+f"(c[0]), "+f"(c[1]), "+f"(c[2]), "+f"(c[3])
                 : "r"(a[0]), "r"(a[1]), "r"(a[2]), "r"(a[3]), "r"(b[0]), "r"(b[1]));
}

__device__ __forceinline__ void hilo2(float v0, float v1, __half2& hp, __half2& lp) {
    __half h0 = __float2half_rn(v0), h1 = __float2half_rn(v1);
    hp.x = h0; hp.y = h1;
    lp.x = __float2half_rn(v0 - __half2float(h0));
    lp.y = __float2half_rn(v1 - __half2float(h1));
}
__device__ __forceinline__ uint32_t pk_hi(float x, float y) {
    __half2 t; t.x = __float2half_rn(x); t.y = __float2half_rn(y);
    return *(uint32_t*)&t;
}
__device__ __forceinline__ uint32_t pk_lo(float x, float y, uint32_t hi) {
    __half2 h = *(__half2*)&hi;
    __half2 t;
    t.x = __float2half_rn(x - __half2float(h.x));
    t.y = __float2half_rn(y - __half2float(h.y));
    return *(uint32_t*)&t;
}

// ============================ unified GEMM (HMMA fp16) ======================
// mode 0: QKV merged (N=2304, per-block sel -> q/k/v epilogues)
// mode 1: final     (N=768, fp32 out + bias)
__global__ __launch_bounds__(256) void hgemm(
    const __half* __restrict__ Ag, const __half* __restrict__ Bg,
    const float* __restrict__ b0p, const float* __restrict__ b1p, const float* __restrict__ b2p,
    void* __restrict__ o0, void* __restrict__ o1, void* __restrict__ o2,
    int mode)
{
    constexpr int BM = 128, BN = 128, BK = 64, K = KP;
    constexpr int MI = 4, NI = 4;
    constexpr int SA = BM * BK * 2, SB = BN * BK * 2, STG = SA + SB;

    extern __shared__ char smem[];
    const uint32_t sbase = smem_u32(smem);
    const int tid = threadIdx.x, l = tid & 31, wid = tid >> 5;
    const int row0 = blockIdx.y * BM, col0 = blockIdx.x * BN;
    const int wm0 = (wid / 4) * 64, wn0 = (wid % 4) * 32;

    auto issue = [&](int ch, int st) {
        const int k0 = ch * BK;
        const uint32_t sA = sbase + st * STG;
        const uint32_t sB = sA + SA;
        for (int i = tid; i < BM * 8; i += 256) {
            int r = i >> 3, v = i & 7;
            cp16(sA + SWZ(r * 128 + v * 16), Ag + (size_t)(row0 + r) * K + k0 + v * 8);
        }
        for (int i = tid; i < BN * 8; i += 256) {
            int r = i >> 3, v = i & 7;
            cp16(sB + SWZ(r * 128 + v * 16), Bg + (size_t)(col0 + r) * K + k0 + v * 8);
        }
    };

    float c[MI][NI][4] = {};
    const int nch = K / BK;
    issue(0, 0); CP_COMMIT();

    for (int ch = 0; ch < nch; ch++) {
        if (ch + 1 < nch) { issue(ch + 1, (ch + 1) & 1); CP_COMMIT(); CP_WAIT(1); }
        else              { CP_WAIT(0); }
        __syncthreads();

        const uint32_t sA = sbase + (ch & 1) * STG;
        const uint32_t sB = sA + SA;

        #pragma unroll
        for (int ks = 0; ks < 4; ks++) {
            uint32_t af[MI][4];
            #pragma unroll
            for (int im = 0; im < MI; im++)
                ldsm4(af[im][0], af[im][1], af[im][2], af[im][3],
                      sA + SWZ((wm0 + im * 16 + (l & 15)) * 128 + ks * 32 + ((l >> 4) & 1) * 16));
            uint32_t bf[NI][2];
            #pragma unroll
            for (int i2 = 0; i2 < NI / 2; i2++) {
                int g = l >> 3;
                uint32_t r0, r1, r2, r3;
                ldsm4(r0, r1, r2, r3,
                      sB + SWZ((wn0 + i2 * 16 + ((g >> 1) & 1) * 8 + (l & 7)) * 128 + ks * 32 + (g & 1) * 16));
                bf[2 * i2][0] = r0; bf[2 * i2][1] = r1;
                bf[2 * i2 + 1][0] = r2; bf[2 * i2 + 1][1] = r3;
            }
            #pragma unroll
            for (int im = 0; im < MI; im++)
                #pragma unroll
                for (int in = 0; in < NI; in++)
                    mma16816(c[im][in], af[im], bf[in]);
        }
        __syncthreads();
    }

    // ---- epilogue (sel hoisted per block: 768 % 128 == 0) ----
    const int sel = (mode == 1) ? -1 : col0 / DMODEL;
    const int dcol0 = col0 % DMODEL;
    const float* bs = (mode == 1) ? b0p : (sel == 0) ? b0p : (sel == 1) ? b1p : b2p;

    #pragma unroll
    for (int im = 0; im < MI; im++)
        #pragma unroll
        for (int in = 0; in < NI; in++)
            #pragma unroll
            for (int half_ = 0; half_ < 2; half_++) {
                int m = row0 + wm0 + im * 16 + (l >> 2) + half_ * 8;
                int nd = dcol0 + wn0 + in * 8 + (l & 3) * 2;
                float v0 = c[im][in][2 * half_] * WSCI + bs[nd];
                float v1 = c[im][in][2 * half_ + 1] * WSCI + bs[nd + 1];
                if (mode == 1) {
                    float2 w; w.x = v0; w.y = v1;
                    *(float2*)((float*)o0 + (size_t)m * DMODEL + nd) = w;
                    continue;
                }
                int b = m >> 10, s = m & 1023, h = nd >> 6, dd = nd & 63;
                if (sel == 2) {
                    __half2 t; t.x = __float2half_rn(v0); t.y = __float2half_rn(v1);
                    *(__half2*)((__half*)o2 + ((size_t)(b * NHEAD + h) * SSEQ + s) * DHEAD + dd) = t;
                } else if (sel == 0) {
                    v0 *= 0.125f; v1 *= 0.125f;          // fold score scale into Q
                    __half2 hp, lp;
                    hilo2(v0, v1, hp, lp);
                    __half* ob = (__half*)o0;
                    size_t base = ((size_t)(b * NHEAD + h) * SSEQ + s) * KSC + dd;
                    *(__half2*)(ob + base)              = hp;
                    *(__half2*)(ob + base + DHEAD)      = lp;
                    *(__half2*)(ob + base + 2 * DHEAD)  = hp;
                } else {
                    __half2 hp, lp;
                    hilo2(v0, v1, hp, lp);
                    __half* ob = (__half*)o1;
                    size_t base = ((size_t)(b * NHEAD + h) * SSEQ + s) * KSC + dd;
                    *(__half2*)(ob + base)              = hp;
                    *(__half2*)(ob + base + DHEAD)      = hp;
                    *(__half2*)(ob + base + 2 * DHEAD)  = lp;
                }
            }
}

// ============================ fused attention ===============================
#define SQ_OFF  0
#define SK_OFF  49152
#define SV_OFF  (49152 + 98304)
#define FSM_BYTES (SV_OFF + 16384)       // 163840

__global__ __launch_bounds__(256, 1) void fused_attn(
    const __half* __restrict__ Qp, const __half* __restrict__ Kp,
    const __half* __restrict__ Vp,
    float* __restrict__ attn, float* __restrict__ lbuf,
    __half* __restrict__ cP)
{
    extern __shared__ char smem[];
    const uint32_t sbase = smem_u32(smem);
    const int tid = threadIdx.x, l = tid & 31, wid = tid >> 5;
    const int bh = blockIdx.y, q0 = blockIdx.x * 128;
    const int wm0 = wid * 16;

    const __half* Qb = Qp + (size_t)bh * SSEQ * KSC;
    const __half* Kb = Kp + (size_t)bh * SSEQ * KSC;
    const __half* Vb = Vp + (size_t)bh * SSEQ * DHEAD;

    auto issueK = [&](int t, int st) {
        const uint32_t kb = sbase + SK_OFF + st * 49152;
        for (int i = tid; i < 3072; i += 256) {
            int c = i >> 10, r = (i >> 3) & 127, v = i & 7;
            cp16(kb + c * 16384 + SWZ(r * 128 + v * 16),
                 Kb + (size_t)(t * 128 + r) * KSC + c * 64 + v * 8);
        }
    };
    auto issueV = [&](int t) {
        for (int i = tid; i < 1024; i += 256) {
            int r = i >> 3, v = i & 7;
            cp16(sbase + SV_OFF + SWZ(r * 128 + v * 16),
                 Vb + (size_t)(t * 128 + r) * DHEAD + v * 8);
        }
    };

    for (int i = tid; i < 3072; i += 256) {
        int c = i >> 10, r = (i >> 3) & 127, v = i & 7;
        cp16(sbase + SQ_OFF + c * 16384 + SWZ(r * 128 + v * 16),
             Qb + (size_t)(q0 + r) * KSC + c * 64 + v * 8);
    }
    issueK(0, 0);
    CP_COMMIT();

    float c_o[8][4] = {};
    float lsum0 = 0.f, lsum1 = 0.f;

    for (int t = 0; t < 8; t++) {
        CP_WAIT(0);
        __syncthreads();
        issueV(t); CP_COMMIT();
        if (t < 7) { issueK(t + 1, (t + 1) & 1); CP_COMMIT(); }

        // ---- S tile (3-term fp16, scale pre-folded into Q) ----
        float cs[16][4] = {};
        const uint32_t kb = sbase + SK_OFF + (t & 1) * 49152;
        #pragma unroll
        for (int cch = 0; cch < 3; cch++) {
            const uint32_t sQ = sbase + SQ_OFF + cch * 16384;
            const uint32_t sK = kb + cch * 16384;
            #pragma unroll
            for (int ks = 0; ks < 4; ks++) {
                uint32_t af[4];
                ldsm4(af[0], af[1], af[2], af[3],
                      sQ + SWZ((wm0 + (l & 15)) * 128 + ks * 32 + ((l >> 4) & 1) * 16));
                #pragma unroll
                for (int i2 = 0; i2 < 8; i2++) {
                    int g = l >> 3;
                    uint32_t r0, r1, r2, r3;
                    ldsm4(r0, r1, r2, r3,
                          sK + SWZ((i2 * 16 + ((g >> 1) & 1) * 8 + (l & 7)) * 128 + ks * 32 + (g & 1) * 16));
                    uint32_t b0[2] = {r0, r1}, b1[2] = {r2, r3};
                    mma16816(cs[2 * i2],     af, b0);
                    mma16816(cs[2 * i2 + 1], af, b1);
                }
            }
        }

        // ---- exp + row-sum + unnormalized attn write ----
        #pragma unroll
        for (int in = 0; in < 16; in++) {
            cs[in][0] = __expf(cs[in][0]);
            cs[in][1] = __expf(cs[in][1]);
            cs[in][2] = __expf(cs[in][2]);
            cs[in][3] = __expf(cs[in][3]);
            lsum0 += cs[in][0] + cs[in][1];
            lsum1 += cs[in][2] + cs[in][3];
        }
        {
            float* a0 = attn + ((size_t)bh << 20) + (size_t)(q0 + wm0 + (l >> 2)) * SSEQ
                        + t * 128 + 2 * (l & 3);
            float* a1 = a0 + 8 * SSEQ;
            #pragma unroll
            for (int in = 0; in < 16; in++) {
                float2 w0; w0.x = cs[in][0]; w0.y = cs[in][1];
                float2 w1; w1.x = cs[in][2]; w1.y = cs[in][3];
                *(float2*)(a0 + in * 8) = w0;
                *(float2*)(a1 + in * 8) = w1;
            }
        }

        if (t < 7) CP_WAIT(1); else CP_WAIT(0);
        __syncthreads();

        // ---- O += P~ @ V (2-term: P hi/lo fp16, V single fp16) ----
        const uint32_t sVh = sbase + SV_OFF;
        #pragma unroll
        for (int j = 0; j < 8; j++) {
            uint32_t ah[4], al[4];
            ah[0] = pk_hi(cs[2*j][0],   cs[2*j][1]);   al[0] = pk_lo(cs[2*j][0],   cs[2*j][1],   ah[0]);
            ah[1] = pk_hi(cs[2*j][2],   cs[2*j][3]);   al[1] = pk_lo(cs[2*j][2],   cs[2*j][3],   ah[1]);
            ah[2] = pk_hi(cs[2*j+1][0], cs[2*j+1][1]); al[2] = pk_lo(cs[2*j+1][0], cs[2*j+1][1], ah[2]);
            ah[3] = pk_hi(cs[2*j+1][2], cs[2*j+1][3]); al[3] = pk_lo(cs[2*j+1][2], cs[2*j+1][3], ah[3]);
            uint32_t vrow = (uint32_t)(j * 16 + ((l >> 3) & 1) * 8 + (l & 7)) * 128
                          + ((uint32_t)(l >> 4)) * 16;
            #pragma unroll
            for (int in = 0; in < 8; in += 2) {
                uint32_t h0, h1, h2, h3;
                ldsm4t(h0, h1, h2, h3, sVh + SWZ(vrow + in * 16));
                uint32_t bh2[2] = {h0, h1}, bh3[2] = {h2, h3};
                mma16816(c_o[in],     ah, bh2);
                mma16816(c_o[in],     al, bh2);
                mma16816(c_o[in + 1], ah, bh3);
                mma16816(c_o[in + 1], al, bh3);
            }
        }
        __syncthreads();
    }

    // ---- finalize ----
    lsum0 += __shfl_xor_sync(0xffffffffu, lsum0, 1);
    lsum0 += __shfl_xor_sync(0xffffffffu, lsum0, 2);
    lsum1 += __shfl_xor_sync(0xffffffffu, lsum1, 1);
    lsum1 += __shfl_xor_sync(0xffffffffu, lsum1, 2);

    const int r0g = q0 + wm0 + (l >> 2);
    if ((l & 3) == 0) {
        lbuf[(size_t)bh * SSEQ + r0g]     = lsum0;
        lbuf[(size_t)bh * SSEQ + r0g + 8] = lsum1;
    }
    const float inv0 = 1.0f / lsum0, inv1 = 1.0f / lsum1;

    const int b = bh / NHEAD, h = bh % NHEAD;
    const size_t gm0 = (size_t)(b * SSEQ + r0g) * KP;
    const size_t gm1 = gm0 + (size_t)8 * KP;
    #pragma unroll
    for (int in = 0; in < 8; in++) {
        int d = h * DHEAD + in * 8 + 2 * (l & 3);
        __half2 hp, lp;
        hilo2(c_o[in][0] * inv0, c_o[in][1] * inv0, hp, lp);
        *(__half2*)(cP + gm0 + d)              = hp;
        *(__half2*)(cP + gm0 + d + DMODEL)     = lp;
        *(__half2*)(cP + gm0 + d + 2 * DMODEL) = hp;
        hilo2(c_o[in][2] * inv1, c_o[in][3] * inv1, hp, lp);
        *(__half2*)(cP + gm1 + d)              = hp;
        *(__half2*)(cP + gm1 + d + DMODEL)     = lp;
        *(__half2*)(cP + gm1 + d + 2 * DMODEL) = hp;
    }
}

__global__ __launch_bounds__(256) void rescale_attn(float* __restrict__ attn,
                                                    const float* __restrict__ lbuf)
{
    const size_t row = blockIdx.x;
    const float inv = 1.0f / lbuf[row];
    float4* p = (float4*)(attn + row * SSEQ);
    float4 v = p[threadIdx.x];
    v.x *= inv; v.y *= inv; v.z *= inv; v.w *= inv;
    p[threadIdx.x] = v;
}

// ============================ prep kernels ==================================
__global__ __launch_bounds__(256) void pack_a(const float* __restrict__ in, __half* __restrict__ o)
{
    size_t i = (size_t)blockIdx.x * 256 + threadIdx.x;
    size_t m = i / (DMODEL / 2);
    int kk = (int)(i % (DMODEL / 2)) * 2;
    if (m >= MROWS) return;
    float2 v = *(const float2*)(in + m * DMODEL + kk);
    __half2 hp, lp;
    hilo2(v.x, v.y, hp, lp);
    size_t base = m * KP + kk;
    *(__half2*)(o + base)              = hp;
    *(__half2*)(o + base + DMODEL)     = lp;
    *(__half2*)(o + base + 2 * DMODEL) = hp;
}

// all 4 weights in one launch (z = 0..3), scaled by 32, [hi|hi|lo]
__global__ void pack_w_all(const float* __restrict__ Wq, const float* __restrict__ Wk,
                           const float* __restrict__ Wv, const float* __restrict__ Wo,
                           __half* __restrict__ wqkv, __half* __restrict__ wo)
{
    __shared__ float t[32][33];
    const int z = blockIdx.z;
    const float* W = (z == 0) ? Wq : (z == 1) ? Wk : (z == 2) ? Wv : Wo;
    __half* o = (z == 3) ? wo : wqkv + (size_t)z * DMODEL * KP;
    int n0 = blockIdx.x * 32, k0 = blockIdx.y * 32;
    int x = threadIdx.x, y = threadIdx.y;
    #pragma unroll
    for (int j = 0; j < 32; j += 8)
        t[y + j][x] = W[(size_t)(k0 + y + j) * DMODEL + n0 + x] * WSC;
    __syncthreads();
    #pragma unroll
    for (int j = 0; j < 32; j += 8) {
        float v = t[x][y + j];
        size_t base = (size_t)(n0 + y + j) * KP + k0 + x;
        __half h = __float2half_rn(v);
        o[base] = h;
        o[base + DMODEL] = h;
        o[base + 2 * DMODEL] = __float2half_rn(v - __half2float(h));
    }
}

// ============================ host launcher =================================
extern "C" void kernel_launch(void* const* d_in, const int* in_sizes, int n_in,
                              void* d_out, int out_size)
{
    (void)in_sizes; (void)n_in;
    const float* x  = (const float*)d_in[0];
    const float* Wq = (const float*)d_in[1];
    const float* bq = (const float*)d_in[2];
    const float* Wk = (const float*)d_in[3];
    const float* bk = (const float*)d_in[4];
    const float* Wv = (const float*)d_in[5];
    const float* bv = (const float*)d_in[6];
    const float* Wo = (const float*)d_in[7];
    const float* bo = (const float*)d_in[8];
    float* out = (float*)d_out;

    float *gattn, *gl;
    __half *xP, *wP, *woP, *qP, *kP, *vP, *cP;
    cudaGetSymbolAddress((void**)&gattn, g_attn);
    cudaGetSymbolAddress((void**)&gl,  g_l);
    cudaGetSymbolAddress((void**)&xP,  g_xP);
    cudaGetSymbolAddress((void**)&wP,  g_wqkvP);
    cudaGetSymbolAddress((void**)&woP, g_woP);
    cudaGetSymbolAddress((void**)&qP,  g_qP);
    cudaGetSymbolAddress((void**)&kP,  g_kP);
    cudaGetSymbolAddress((void**)&vP,  g_v);
    cudaGetSymbolAddress((void**)&cP,  g_cP);

    const size_t final_elems = (size_t)MROWS * DMODEL;
    float* attn = ((size_t)out_size > final_elems) ? (out + final_elems) : gattn;

    static cudaStream_t s2 = nullptr;
    static cudaEvent_t evA = nullptr, evB = nullptr;
    if (s2 == nullptr) {
        cudaStreamCreateWithFlags(&s2, cudaStreamNonBlocking);
        cudaEventCreateWithFlags(&evA, cudaEventDisableTiming);
        cudaEventCreateWithFlags(&evB, cudaEventDisableTiming);
    }

    constexpr int SM_GEMM = 2 * (128 * 64 * 2 + 128 * 64 * 2);
    cudaFuncSetAttribute(hgemm,      cudaFuncAttributeMaxDynamicSharedMemorySize, SM_GEMM);
    cudaFuncSetAttribute(fused_attn, cudaFuncAttributeMaxDynamicSharedMemorySize, FSM_BYTES);

    // launch 1: pack x
    {
        size_t pairs = (size_t)MROWS * (DMODEL / 2);
        pack_a<<<(unsigned)((pairs + 255) / 256), 256>>>(x, xP);
    }
    // launch 2: pack all weights
    {
        dim3 tb(32, 8), tg(DMODEL / 32, DMODEL / 32, 4);
        pack_w_all<<<tg, tb>>>(Wq, Wk, Wv, Wo, wP, woP);
    }

    // launch 3: merged QKV projection (N = 2304)
    dim3 gqkv(3 * DMODEL / 128, MROWS / 128);     // (18, 64)
    hgemm<<<gqkv, 256, SM_GEMM>>>(xP, wP, bq, bk, bv, qP, kP, vP, 0);

    // launch 4: fused scores + softmax + AV
    dim3 gf(SSEQ / 128, NBH);                     // (8, 96)
    fused_attn<<<gf, 256, FSM_BYTES>>>(qP, kP, vP, attn, gl, cP);

    // launch 5 (s2): rescale attn, overlapped with final GEMM
    cudaEventRecord(evA, 0);
    cudaStreamWaitEvent(s2, evA, 0);
    rescale_attn<<<NBH * SSEQ, 256, 0, s2>>>(attn, gl);
    cudaEventRecord(evB, s2);

    // launch 6: out = ctx @ Wo + bo   (ncu -s 5 -c 1 profiles this one)
    dim3 gfin(DMODEL / 128, MROWS / 128);         // (6, 64)
    hgemm<<<gfin, 256, SM_GEMM>>>(cP, woP, bo, nullptr, nullptr, out, nullptr, nullptr, 1);

    cudaStreamWaitEvent(0, evB, 0);
}

// round 7
// speedup vs baseline: 2.8262x; 1.0174x over previous
#include <cuda_runtime.h>
#include <cuda_fp16.h>
#include <cstdint>

#define BBATCH 8
#define SSEQ   1024
#define DMODEL 768
#define NHEAD  12
#define DHEAD  64
#define MROWS  (BBATCH*SSEQ)     // 8192
#define NBH    (BBATCH*NHEAD)    // 96
#define KP     (3*DMODEL)        // 2304
#define KSC    (3*DHEAD)         // 192
#define WSC    32.0f
#define WSCI   0.03125f

// ---------------- scratch (device globals; no allocations allowed) ----------
__device__ float g_attn[(size_t)NBH*SSEQ*SSEQ];
__device__ float g_l[(size_t)NBH*SSEQ];
__device__ __half g_xP  [(size_t)MROWS*KP];
__device__ __half g_wqkP[(size_t)2*DMODEL*KP];           // Wq|Wk rows (x32, [hi|hi|lo])
__device__ __half g_wvh [(size_t)DMODEL*DMODEL];         // Wv hi only (x32)
__device__ __half g_woP [(size_t)DMODEL*KP];
__device__ __half g_qP [(size_t)NBH*SSEQ*KSC];           // q*0.125, [hi|lo|hi]
__device__ __half g_kP [(size_t)NBH*SSEQ*KSC];           // [hi|hi|lo]
__device__ __half g_v  [(size_t)NBH*SSEQ*DHEAD];         // V single fp16
__device__ __half g_cP [(size_t)MROWS*KP];               // ctx [hi|lo|hi]

// ============================ PTX helpers ===================================
__device__ __forceinline__ uint32_t smem_u32(const void* p) {
    uint32_t a;
    asm("{ .reg .u64 t; cvta.to.shared.u64 t, %1; cvt.u32.u64 %0, t; }" : "=r"(a) : "l"(p));
    return a;
}
#define SWZ(o) ((uint32_t)(o) ^ ((((uint32_t)(o)) >> 3) & 0x70))

__device__ __forceinline__ void cp16(uint32_t s, const void* g) {
    asm volatile("cp.async.cg.shared.global [%0], [%1], 16;" :: "r"(s), "l"(g));
}
#define CP_COMMIT() asm volatile("cp.async.commit_group;")
#define CP_WAIT(n)  asm volatile("cp.async.wait_group %0;" :: "n"(n))

__device__ __forceinline__ void ldsm4(uint32_t& r0, uint32_t& r1, uint32_t& r2, uint32_t& r3, uint32_t a) {
    asm volatile("ldmatrix.sync.aligned.m8n8.x4.shared.b16 {%0,%1,%2,%3}, [%4];"
                 : "=r"(r0), "=r"(r1), "=r"(r2), "=r"(r3) : "r"(a));
}
__device__ __forceinline__ void ldsm4t(uint32_t& r0, uint32_t& r1, uint32_t& r2, uint32_t& r3, uint32_t a) {
    asm volatile("ldmatrix.sync.aligned.m8n8.x4.trans.shared.b16 {%0,%1,%2,%3}, [%4];"
                 : "=r"(r0), "=r"(r1), "=r"(r2), "=r"(r3) : "r"(a));
}
__device__ __forceinline__ void mma16816(float* c, const uint32_t* a, const uint32_t* b) {
    asm volatile("mma.sync.aligned.m16n8k16.row.col.f32.f16.f16.f32 "
                 "{%0,%1,%2,%3}, {%4,%5,%6,%7}, {%8,%9}, {%0,%1,%2,%3};"
                 : "+f"(c[0]), "+f"(c[1]), "+f"(c[2]), "+f"(c[3])
                 : "r"(a[0]), "r"(a[1]), "r"(a[2]), "r"(a[3]), "r"(b[0]), "r"(b[1]));
}

__device__ __forceinline__ void hilo2(float v0, float v1, __half2& hp, __half2& lp) {
    __half h0 = __float2half_rn(v0), h1 = __float2half_rn(v1);
    hp.x = h0; hp.y = h1;
    lp.x = __float2half_rn(v0 - __half2float(h0));
    lp.y = __float2half_rn(v1 - __half2float(h1));
}
__device__ __forceinline__ uint32_t pk_hi(float x, float y) {
    __half2 t; t.x = __float2half_rn(x); t.y = __float2half_rn(y);
    return *(uint32_t*)&t;
}
__device__ __forceinline__ uint32_t pk_lo(float x, float y, uint32_t hi) {
    __half2 h = *(__half2*)&hi;
    __half2 t;
    t.x = __float2half_rn(x - __half2float(h.x));
    t.y = __float2half_rn(y - __half2float(h.y));
    return *(uint32_t*)&t;
}

// ============================ unified GEMM (HMMA fp16) ======================
// mode 0: QK merged (N=1536, per-block sel 0/1)
// mode 1: final (fp32 out + bias)     mode 2: V proj (fp16 out + bias)
__global__ __launch_bounds__(256) void hgemm(
    const __half* __restrict__ Ag, const __half* __restrict__ Bg,
    const float* __restrict__ b0p, const float* __restrict__ b1p,
    void* __restrict__ o0, void* __restrict__ o1,
    int K, int ldB, int mode)
{
    constexpr int BM = 128, BN = 128, BK = 64;
    constexpr int MI = 4, NI = 4;
    constexpr int SA = BM * BK * 2, SB = BN * BK * 2, STG = SA + SB;

    extern __shared__ char smem[];
    const uint32_t sbase = smem_u32(smem);
    const int tid = threadIdx.x, l = tid & 31, wid = tid >> 5;
    const int row0 = blockIdx.y * BM, col0 = blockIdx.x * BN;
    const int wm0 = (wid / 4) * 64, wn0 = (wid % 4) * 32;

    auto issue = [&](int ch, int st) {
        const int k0 = ch * BK;
        const uint32_t sA = sbase + st * STG;
        const uint32_t sB = sA + SA;
        for (int i = tid; i < BM * 8; i += 256) {
            int r = i >> 3, v = i & 7;
            cp16(sA + SWZ(r * 128 + v * 16), Ag + (size_t)(row0 + r) * KP + k0 + v * 8);
        }
        for (int i = tid; i < BN * 8; i += 256) {
            int r = i >> 3, v = i & 7;
            cp16(sB + SWZ(r * 128 + v * 16), Bg + (size_t)(col0 + r) * ldB + k0 + v * 8);
        }
    };

    float c[MI][NI][4] = {};
    const int nch = K / BK;
    issue(0, 0); CP_COMMIT();

    for (int ch = 0; ch < nch; ch++) {
        if (ch + 1 < nch) { issue(ch + 1, (ch + 1) & 1); CP_COMMIT(); CP_WAIT(1); }
        else              { CP_WAIT(0); }
        __syncthreads();

        const uint32_t sA = sbase + (ch & 1) * STG;
        const uint32_t sB = sA + SA;

        #pragma unroll
        for (int ks = 0; ks < 4; ks++) {
            uint32_t af[MI][4];
            #pragma unroll
            for (int im = 0; im < MI; im++)
                ldsm4(af[im][0], af[im][1], af[im][2], af[im][3],
                      sA + SWZ((wm0 + im * 16 + (l & 15)) * 128 + ks * 32 + ((l >> 4) & 1) * 16));
            uint32_t bf[NI][2];
            #pragma unroll
            for (int i2 = 0; i2 < NI / 2; i2++) {
                int g = l >> 3;
                uint32_t r0, r1, r2, r3;
                ldsm4(r0, r1, r2, r3,
                      sB + SWZ((wn0 + i2 * 16 + ((g >> 1) & 1) * 8 + (l & 7)) * 128 + ks * 32 + (g & 1) * 16));
                bf[2 * i2][0] = r0; bf[2 * i2][1] = r1;
                bf[2 * i2 + 1][0] = r2; bf[2 * i2 + 1][1] = r3;
            }
            #pragma unroll
            for (int im = 0; im < MI; im++)
                #pragma unroll
                for (int in = 0; in < NI; in++)
                    mma16816(c[im][in], af[im], bf[in]);
        }
        __syncthreads();
    }

    const int sel = (mode == 0) ? col0 / DMODEL : mode + 1;   // 0/1 QK, 2 final, 3 V
    const int dcol0 = col0 % DMODEL;
    const float* bs = (sel == 1) ? b1p : b0p;

    #pragma unroll
    for (int im = 0; im < MI; im++)
        #pragma unroll
        for (int in = 0; in < NI; in++)
            #pragma unroll
            for (int half_ = 0; half_ < 2; half_++) {
                int m = row0 + wm0 + im * 16 + (l >> 2) + half_ * 8;
                int nd = dcol0 + wn0 + in * 8 + (l & 3) * 2;
                float v0 = c[im][in][2 * half_] * WSCI + bs[nd];
                float v1 = c[im][in][2 * half_ + 1] * WSCI + bs[nd + 1];
                if (sel == 2) {
                    float2 w; w.x = v0; w.y = v1;
                    *(float2*)((float*)o0 + (size_t)m * DMODEL + nd) = w;
                    continue;
                }
                int b = m >> 10, s = m & 1023, h = nd >> 6, dd = nd & 63;
                if (sel == 3) {
                    __half2 t; t.x = __float2half_rn(v0); t.y = __float2half_rn(v1);
                    *(__half2*)((__half*)o0 + ((size_t)(b * NHEAD + h) * SSEQ + s) * DHEAD + dd) = t;
                } else if (sel == 0) {
                    v0 *= 0.125f; v1 *= 0.125f;
                    __half2 hp, lp;
                    hilo2(v0, v1, hp, lp);
                    __half* ob = (__half*)o0;
                    size_t base = ((size_t)(b * NHEAD + h) * SSEQ + s) * KSC + dd;
                    *(__half2*)(ob + base)              = hp;
                    *(__half2*)(ob + base + DHEAD)      = lp;
                    *(__half2*)(ob + base + 2 * DHEAD)  = hp;
                } else {
                    __half2 hp, lp;
                    hilo2(v0, v1, hp, lp);
                    __half* ob = (__half*)o1;
                    size_t base = ((size_t)(b * NHEAD + h) * SSEQ + s) * KSC + dd;
                    *(__half2*)(ob + base)              = hp;
                    *(__half2*)(ob + base + DHEAD)      = hp;
                    *(__half2*)(ob + base + 2 * DHEAD)  = lp;
                }
            }
}

// ============================ fused attention (16 warps) ====================
// Warp w: rg = w>>1 owns q-rows [rg*16, +16); ch = w&1 owns kv cols [ch*64, +64).
#define SQ_OFF  0
#define SK_OFF  49152
#define SV_OFF  (49152 + 98304)
#define FSM_BYTES (SV_OFF + 16384)       // 163840

__global__ __launch_bounds__(512, 1) void fused_attn(
    const __half* __restrict__ Qp, const __half* __restrict__ Kp,
    const __half* __restrict__ Vp,
    float* __restrict__ attn, float* __restrict__ lbuf,
    __half* __restrict__ cP)
{
    extern __shared__ char smem[];
    const uint32_t sbase = smem_u32(smem);
    const int tid = threadIdx.x, l = tid & 31, wid = tid >> 5;
    const int rg = wid >> 1, ch = wid & 1;
    const int bh = blockIdx.y, q0 = blockIdx.x * 128;
    const int wm0 = rg * 16;

    const __half* Qb = Qp + (size_t)bh * SSEQ * KSC;
    const __half* Kb = Kp + (size_t)bh * SSEQ * KSC;
    const __half* Vb = Vp + (size_t)bh * SSEQ * DHEAD;

    auto issueK = [&](int t, int st) {
        const uint32_t kb = sbase + SK_OFF + st * 49152;
        for (int i = tid; i < 3072; i += 512) {
            int c = i >> 10, r = (i >> 3) & 127, v = i & 7;
            cp16(kb + c * 16384 + SWZ(r * 128 + v * 16),
                 Kb + (size_t)(t * 128 + r) * KSC + c * 64 + v * 8);
        }
    };
    auto issueV = [&](int t) {
        for (int i = tid; i < 1024; i += 512) {
            int r = i >> 3, v = i & 7;
            cp16(sbase + SV_OFF + SWZ(r * 128 + v * 16),
                 Vb + (size_t)(t * 128 + r) * DHEAD + v * 8);
        }
    };

    for (int i = tid; i < 3072; i += 512) {
        int c = i >> 10, r = (i >> 3) & 127, v = i & 7;
        cp16(sbase + SQ_OFF + c * 16384 + SWZ(r * 128 + v * 16),
             Qb + (size_t)(q0 + r) * KSC + c * 64 + v * 8);
    }
    issueK(0, 0);
    CP_COMMIT();

    float c_o[8][4] = {};
    float lsum0 = 0.f, lsum1 = 0.f;

    for (int t = 0; t < 8; t++) {
        CP_WAIT(0);
        __syncthreads();
        issueV(t); CP_COMMIT();
        if (t < 7) { issueK(t + 1, (t + 1) & 1); CP_COMMIT(); }

        // ---- S: 16 q-rows x 64 kv-cols per warp (3-term) ----
        float cs[8][4] = {};
        const uint32_t kb = sbase + SK_OFF + (t & 1) * 49152;
        #pragma unroll
        for (int cch = 0; cch < 3; cch++) {
            const uint32_t sQ = sbase + SQ_OFF + cch * 16384;
            const uint32_t sK = kb + cch * 16384;
            #pragma unroll
            for (int ks = 0; ks < 4; ks++) {
                uint32_t af[4];
                ldsm4(af[0], af[1], af[2], af[3],
                      sQ + SWZ((wm0 + (l & 15)) * 128 + ks * 32 + ((l >> 4) & 1) * 16));
                #pragma unroll
                for (int i2 = 0; i2 < 4; i2++) {
                    int g = l >> 3;
                    uint32_t r0, r1, r2, r3;
                    ldsm4(r0, r1, r2, r3,
                          sK + SWZ((ch * 64 + i2 * 16 + ((g >> 1) & 1) * 8 + (l & 7)) * 128
                                   + ks * 32 + (g & 1) * 16));
                    uint32_t b0[2] = {r0, r1}, b1[2] = {r2, r3};
                    mma16816(cs[2 * i2],     af, b0);
                    mma16816(cs[2 * i2 + 1], af, b1);
                }
            }
        }

        // ---- exp + row-sum + unnormalized attn write ----
        #pragma unroll
        for (int in = 0; in < 8; in++) {
            cs[in][0] = __expf(cs[in][0]);
            cs[in][1] = __expf(cs[in][1]);
            cs[in][2] = __expf(cs[in][2]);
            cs[in][3] = __expf(cs[in][3]);
            lsum0 += cs[in][0] + cs[in][1];
            lsum1 += cs[in][2] + cs[in][3];
        }
        {
            float* a0 = attn + ((size_t)bh << 20) + (size_t)(q0 + wm0 + (l >> 2)) * SSEQ
                        + t * 128 + ch * 64 + 2 * (l & 3);
            float* a1 = a0 + 8 * SSEQ;
            #pragma unroll
            for (int in = 0; in < 8; in++) {
                float2 w0; w0.x = cs[in][0]; w0.y = cs[in][1];
                float2 w1; w1.x = cs[in][2]; w1.y = cs[in][3];
                *(float2*)(a0 + in * 8) = w0;
                *(float2*)(a1 + in * 8) = w1;
            }
        }

        if (t < 7) CP_WAIT(1); else CP_WAIT(0);
        __syncthreads();

        // ---- partial O += P~ @ V over warp's 64 kv (2-term) ----
        const uint32_t sVh = sbase + SV_OFF;
        #pragma unroll
        for (int kk = 0; kk < 4; kk++) {
            uint32_t ah[4], al[4];
            ah[0] = pk_hi(cs[2*kk][0],   cs[2*kk][1]);   al[0] = pk_lo(cs[2*kk][0],   cs[2*kk][1],   ah[0]);
            ah[1] = pk_hi(cs[2*kk][2],   cs[2*kk][3]);   al[1] = pk_lo(cs[2*kk][2],   cs[2*kk][3],   ah[1]);
            ah[2] = pk_hi(cs[2*kk+1][0], cs[2*kk+1][1]); al[2] = pk_lo(cs[2*kk+1][0], cs[2*kk+1][1], ah[2]);
            ah[3] = pk_hi(cs[2*kk+1][2], cs[2*kk+1][3]); al[3] = pk_lo(cs[2*kk+1][2], cs[2*kk+1][3], ah[3]);
            uint32_t vrow = (uint32_t)((ch * 4 + kk) * 16 + ((l >> 3) & 1) * 8 + (l & 7)) * 128
                          + ((uint32_t)(l >> 4)) * 16;
            #pragma unroll
            for (int in = 0; in < 8; in += 2) {
                uint32_t h0, h1, h2, h3;
                ldsm4t(h0, h1, h2, h3, sVh + SWZ(vrow + in * 16));
                uint32_t bh2[2] = {h0, h1}, bh3[2] = {h2, h3};
                mma16816(c_o[in],     ah, bh2);
                mma16816(c_o[in],     al, bh2);
                mma16816(c_o[in + 1], ah, bh3);
                mma16816(c_o[in + 1], al, bh3);
            }
        }
        __syncthreads();
    }

    // ---- pair reduction (ch=1 -> smem -> ch=0), then finalize ----
    lsum0 += __shfl_xor_sync(0xffffffffu, lsum0, 1);
    lsum0 += __shfl_xor_sync(0xffffffffu, lsum0, 2);
    lsum1 += __shfl_xor_sync(0xffffffffu, lsum1, 1);
    lsum1 += __shfl_xor_sync(0xffffffffu, lsum1, 2);

    float* redO = (float*)(smem + SK_OFF);             // [8][16][64] = 32KB
    float* redL = (float*)(smem + SK_OFF + 32768);     // [8][16]
    __syncthreads();
    if (ch == 1) {
        #pragma unroll
        for (int in = 0; in < 8; in++) {
            int cidx = in * 8 + 2 * (l & 3);
            int r = l >> 2;
            redO[rg * 1024 + r * 64 + cidx]           = c_o[in][0];
            redO[rg * 1024 + r * 64 + cidx + 1]       = c_o[in][1];
            redO[rg * 1024 + (r + 8) * 64 + cidx]     = c_o[in][2];
            redO[rg * 1024 + (r + 8) * 64 + cidx + 1] = c_o[in][3];
        }
        if ((l & 3) == 0) {
            redL[rg * 16 + (l >> 2)]     = lsum0;
            redL[rg * 16 + (l >> 2) + 8] = lsum1;
        }
    }
    __syncthreads();
    if (ch == 0) {
        lsum0 += redL[rg * 16 + (l >> 2)];
        lsum1 += redL[rg * 16 + (l >> 2) + 8];

        const int r0g = q0 + wm0 + (l >> 2);
        if ((l & 3) == 0) {
            lbuf[(size_t)bh * SSEQ + r0g]     = lsum0;
            lbuf[(size_t)bh * SSEQ + r0g + 8] = lsum1;
        }
        const float inv0 = 1.0f / lsum0, inv1 = 1.0f / lsum1;

        const int b = bh / NHEAD, h = bh % NHEAD;
        const size_t gm0 = (size_t)(b * SSEQ + r0g) * KP;
        const size_t gm1 = gm0 + (size_t)8 * KP;
        #pragma unroll
        for (int in = 0; in < 8; in++) {
            int cidx = in * 8 + 2 * (l & 3);
            int r = l >> 2;
            float o0 = (c_o[in][0] + redO[rg * 1024 + r * 64 + cidx])           * inv0;
            float o1 = (c_o[in][1] + redO[rg * 1024 + r * 64 + cidx + 1])       * inv0;
            float o2 = (c_o[in][2] + redO[rg * 1024 + (r + 8) * 64 + cidx])     * inv1;
            float o3 = (c_o[in][3] + redO[rg * 1024 + (r + 8) * 64 + cidx + 1]) * inv1;
            int d = h * DHEAD + cidx;
            __half2 hp, lp;
            hilo2(o0, o1, hp, lp);
            *(__half2*)(cP + gm0 + d)              = hp;
            *(__half2*)(cP + gm0 + d + DMODEL)     = lp;
            *(__half2*)(cP + gm0 + d + 2 * DMODEL) = hp;
            hilo2(o2, o3, hp, lp);
            *(__half2*)(cP + gm1 + d)              = hp;
            *(__half2*)(cP + gm1 + d + DMODEL)     = lp;
            *(__half2*)(cP + gm1 + d + 2 * DMODEL) = hp;
        }
    }
}

__global__ __launch_bounds__(256) void rescale_attn(float* __restrict__ attn,
                                                    const float* __restrict__ lbuf)
{
    const size_t row = blockIdx.x;
    const float inv = 1.0f / lbuf[row];
    float4* p = (float4*)(attn + row * SSEQ);
    float4 v = p[threadIdx.x];
    v.x *= inv; v.y *= inv; v.z *= inv; v.w *= inv;
    p[threadIdx.x] = v;
}

// ============================ prep kernels ==================================
__global__ __launch_bounds__(256) void pack_a(const float* __restrict__ in, __half* __restrict__ o)
{
    size_t i = (size_t)blockIdx.x * 256 + threadIdx.x;
    size_t m = i / (DMODEL / 2);
    int kk = (int)(i % (DMODEL / 2)) * 2;
    if (m >= MROWS) return;
    float2 v = *(const float2*)(in + m * DMODEL + kk);
    __half2 hp, lp;
    hilo2(v.x, v.y, hp, lp);
    size_t base = m * KP + kk;
    *(__half2*)(o + base)              = hp;
    *(__half2*)(o + base + DMODEL)     = lp;
    *(__half2*)(o + base + 2 * DMODEL) = hp;
}

__global__ void pack_w_all(const float* __restrict__ Wq, const float* __restrict__ Wk,
                           const float* __restrict__ Wv, const float* __restrict__ Wo,
                           __half* __restrict__ wqk, __half* __restrict__ wvh,
                           __half* __restrict__ wo)
{
    __shared__ float t[32][33];
    const int z = blockIdx.z;
    const float* W = (z == 0) ? Wq : (z == 1) ? Wk : (z == 2) ? Wv : Wo;
    int n0 = blockIdx.x * 32, k0 = blockIdx.y * 32;
    int x = threadIdx.x, y = threadIdx.y;
    #pragma unroll
    for (int j = 0; j < 32; j += 8)
        t[y + j][x] = W[(size_t)(k0 + y + j) * DMODEL + n0 + x] * WSC;
    __syncthreads();
    if (z == 2) {
        #pragma unroll
        for (int j = 0; j < 32; j += 8) {
            float v = t[x][y + j];
            wvh[(size_t)(n0 + y + j) * DMODEL + k0 + x] = __float2half_rn(v);
        }
        return;
    }
    __half* o = (z == 3) ? wo : wqk + (size_t)z * DMODEL * KP;
    #pragma unroll
    for (int j = 0; j < 32; j += 8) {
        float v = t[x][y + j];
        size_t base = (size_t)(n0 + y + j) * KP + k0 + x;
        __half h = __float2half_rn(v);
        o[base] = h;
        o[base + DMODEL] = h;
        o[base + 2 * DMODEL] = __float2half_rn(v - __half2float(h));
    }
}

// ============================ host launcher =================================
extern "C" void kernel_launch(void* const* d_in, const int* in_sizes, int n_in,
                              void* d_out, int out_size)
{
    (void)in_sizes; (void)n_in;
    const float* x  = (const float*)d_in[0];
    const float* Wq = (const float*)d_in[1];
    const float* bq = (const float*)d_in[2];
    const float* Wk = (const float*)d_in[3];
    const float* bk = (const float*)d_in[4];
    const float* Wv = (const float*)d_in[5];
    const float* bv = (const float*)d_in[6];
    const float* Wo = (const float*)d_in[7];
    const float* bo = (const float*)d_in[8];
    float* out = (float*)d_out;

    float *gattn, *gl;
    __half *xP, *wqkP, *wvh, *woP, *qP, *kP, *vP, *cP;
    cudaGetSymbolAddress((void**)&gattn, g_attn);
    cudaGetSymbolAddress((void**)&gl,   g_l);
    cudaGetSymbolAddress((void**)&xP,   g_xP);
    cudaGetSymbolAddress((void**)&wqkP, g_wqkP);
    cudaGetSymbolAddress((void**)&wvh,  g_wvh);
    cudaGetSymbolAddress((void**)&woP,  g_woP);
    cudaGetSymbolAddress((void**)&qP,   g_qP);
    cudaGetSymbolAddress((void**)&kP,   g_kP);
    cudaGetSymbolAddress((void**)&vP,   g_v);
    cudaGetSymbolAddress((void**)&cP,   g_cP);

    const size_t final_elems = (size_t)MROWS * DMODEL;
    float* attn = ((size_t)out_size > final_elems) ? (out + final_elems) : gattn;

    static cudaStream_t s2 = nullptr;
    static cudaEvent_t evA = nullptr, evB = nullptr;
    if (s2 == nullptr) {
        cudaStreamCreateWithFlags(&s2, cudaStreamNonBlocking);
        cudaEventCreateWithFlags(&evA, cudaEventDisableTiming);
        cudaEventCreateWithFlags(&evB, cudaEventDisableTiming);
    }

    constexpr int SM_GEMM = 2 * (128 * 64 * 2 + 128 * 64 * 2);
    cudaFuncSetAttribute(hgemm,      cudaFuncAttributeMaxDynamicSharedMemorySize, SM_GEMM);
    cudaFuncSetAttribute(fused_attn, cudaFuncAttributeMaxDynamicSharedMemorySize, FSM_BYTES);

    // pack
    {
        size_t pairs = (size_t)MROWS * (DMODEL / 2);
        pack_a<<<(unsigned)((pairs + 255) / 256), 256>>>(x, xP);
        dim3 tb(32, 8), tg(DMODEL / 32, DMODEL / 32, 4);
        pack_w_all<<<tg, tb>>>(Wq, Wk, Wv, Wo, wqkP, wvh, woP);
    }

    // QK merged projection (N = 1536, 3-term)
    dim3 gqk(2 * DMODEL / 128, MROWS / 128);      // (12, 64)
    hgemm<<<gqk, 256, SM_GEMM>>>(xP, wqkP, bq, bk, qP, kP, KP, KP, 0);

    // V projection (N = 768, 1-term: x_hi @ Wv_hi)
    dim3 gv(DMODEL / 128, MROWS / 128);           // (6, 64)
    hgemm<<<gv, 256, SM_GEMM>>>(xP, wvh, bv, nullptr, vP, nullptr, DMODEL, DMODEL, 2);

    // fused scores + softmax + AV (16 warps)
    dim3 gf(SSEQ / 128, NBH);                     // (8, 96)
    fused_attn<<<gf, 512, FSM_BYTES>>>(qP, kP, vP, attn, gl, cP);

    // rescale attn on s2, overlapped with final GEMM
    cudaEventRecord(evA, 0);
    cudaStreamWaitEvent(s2, evA, 0);
    rescale_attn<<<NBH * SSEQ, 256, 0, s2>>>(attn, gl);
    cudaEventRecord(evB, s2);

    // out = ctx @ Wo + bo (3-term)
    hgemm<<<gv, 256, SM_GEMM>>>(cP, woP, bo, nullptr, out, nullptr, KP, KP, 1);

    cudaStreamWaitEvent(0, evB, 0);
}

// round 8
// speedup vs baseline: 3.5002x; 1.2385x over previous
#include <cuda_runtime.h>
#include <cuda_fp16.h>
#include <cstdint>

#define BBATCH 8
#define SSEQ   1024
#define DMODEL 768
#define NHEAD  12
#define DHEAD  64
#define MROWS  (BBATCH*SSEQ)     // 8192
#define NBH    (BBATCH*NHEAD)    // 96
#define KP2    1536              // [hi|lo] packed K
#define QSC    128               // q per-row dims [hi(64)|lo(64)]
#define WSC    32.0f
#define WSCI   0.03125f

// ---------------- scratch (device globals; no allocations allowed) ----------
__device__ float g_attn[(size_t)NBH*SSEQ*SSEQ];
__device__ float g_l[(size_t)NBH*SSEQ];
__device__ __half g_xP  [(size_t)MROWS*KP2];             // x [hi|lo]
__device__ __half g_wqkP[(size_t)2*DMODEL*KP2];          // Wq|Wk rows (x32, [wh|wh])
__device__ __half g_wvh [(size_t)DMODEL*DMODEL];         // Wv hi
__device__ __half g_woP [(size_t)DMODEL*KP2];            // Wo [wh|wh]
__device__ __half g_qP [(size_t)NBH*SSEQ*QSC];           // q*0.125 [hi|lo]
__device__ __half g_k  [(size_t)NBH*SSEQ*DHEAD];         // k single fp16
__device__ __half g_v  [(size_t)NBH*SSEQ*DHEAD];         // V single fp16
__device__ __half g_cP [(size_t)MROWS*KP2];              // ctx [hi|lo]

// ============================ PTX helpers ===================================
__device__ __forceinline__ uint32_t smem_u32(const void* p) {
    uint32_t a;
    asm("{ .reg .u64 t; cvta.to.shared.u64 t, %1; cvt.u32.u64 %0, t; }" : "=r"(a) : "l"(p));
    return a;
}
#define SWZ(o) ((uint32_t)(o) ^ ((((uint32_t)(o)) >> 3) & 0x70))

__device__ __forceinline__ void cp16(uint32_t s, const void* g) {
    asm volatile("cp.async.cg.shared.global [%0], [%1], 16;" :: "r"(s), "l"(g));
}
#define CP_COMMIT() asm volatile("cp.async.commit_group;")
#define CP_WAIT(n)  asm volatile("cp.async.wait_group %0;" :: "n"(n))

__device__ __forceinline__ void ldsm4(uint32_t& r0, uint32_t& r1, uint32_t& r2, uint32_t& r3, uint32_t a) {
    asm volatile("ldmatrix.sync.aligned.m8n8.x4.shared.b16 {%0,%1,%2,%3}, [%4];"
                 : "=r"(r0), "=r"(r1), "=r"(r2), "=r"(r3) : "r"(a));
}
__device__ __forceinline__ void ldsm4t(uint32_t& r0, uint32_t& r1, uint32_t& r2, uint32_t& r3, uint32_t a) {
    asm volatile("ldmatrix.sync.aligned.m8n8.x4.trans.shared.b16 {%0,%1,%2,%3}, [%4];"
                 : "=r"(r0), "=r"(r1), "=r"(r2), "=r"(r3) : "r"(a));
}
__device__ __forceinline__ void mma16816(float* c, const uint32_t* a, const uint32_t* b) {
    asm volatile("mma.sync.aligned.m16n8k16.row.col.f32.f16.f16.f32 "
                 "{%0,%1,%2,%3}, {%4,%5,%6,%7}, {%8,%9}, {%0,%1,%2,%3};"
                 : "+f"(c[0]), "+f"(c[1]), "+f"(c[2]), "+f"(c[3])
                 : "r"(a[0]), "r"(a[1]), "r"(a[2]), "r"(a[3]), "r"(b[0]), "r"(b[1]));
}

__device__ __forceinline__ void hilo2(float v0, float v1, __half2& hp, __half2& lp) {
    __half h0 = __float2half_rn(v0), h1 = __float2half_rn(v1);
    hp.x = h0; hp.y = h1;
    lp.x = __float2half_rn(v0 - __half2float(h0));
    lp.y = __float2half_rn(v1 - __half2float(h1));
}
__device__ __forceinline__ uint32_t pk_hi(float x, float y) {
    __half2 t; t.x = __float2half_rn(x); t.y = __float2half_rn(y);
    return *(uint32_t*)&t;
}
__device__ __forceinline__ uint32_t pk_lo(float x, float y, uint32_t hi) {
    __half2 h = *(__half2*)&hi;
    __half2 t;
    t.x = __float2half_rn(x - __half2float(h.x));
    t.y = __float2half_rn(y - __half2float(h.y));
    return *(uint32_t*)&t;
}

// ============================ unified GEMM (HMMA fp16) ======================
// mode 0: QK merged (N=1536: q [hi|lo] / k single)   mode 1: final (fp32)
// mode 2: V (single fp16)
__global__ __launch_bounds__(256) void hgemm(
    const __half* __restrict__ Ag, const __half* __restrict__ Bg,
    const float* __restrict__ b0p, const float* __restrict__ b1p,
    void* __restrict__ o0, void* __restrict__ o1,
    int K, int ldB, int mode)
{
    constexpr int BM = 128, BN = 128, BK = 64;
    constexpr int MI = 4, NI = 4;
    constexpr int SA = BM * BK * 2, SB = BN * BK * 2, STG = SA + SB;

    extern __shared__ char smem[];
    const uint32_t sbase = smem_u32(smem);
    const int tid = threadIdx.x, l = tid & 31, wid = tid >> 5;
    const int row0 = blockIdx.y * BM, col0 = blockIdx.x * BN;
    const int wm0 = (wid / 4) * 64, wn0 = (wid % 4) * 32;

    auto issue = [&](int ch, int st) {
        const int k0 = ch * BK;
        const uint32_t sA = sbase + st * STG;
        const uint32_t sB = sA + SA;
        for (int i = tid; i < BM * 8; i += 256) {
            int r = i >> 3, v = i & 7;
            cp16(sA + SWZ(r * 128 + v * 16), Ag + (size_t)(row0 + r) * KP2 + k0 + v * 8);
        }
        for (int i = tid; i < BN * 8; i += 256) {
            int r = i >> 3, v = i & 7;
            cp16(sB + SWZ(r * 128 + v * 16), Bg + (size_t)(col0 + r) * ldB + k0 + v * 8);
        }
    };

    float c[MI][NI][4] = {};
    const int nch = K / BK;
    issue(0, 0); CP_COMMIT();

    for (int ch = 0; ch < nch; ch++) {
        if (ch + 1 < nch) { issue(ch + 1, (ch + 1) & 1); CP_COMMIT(); CP_WAIT(1); }
        else              { CP_WAIT(0); }
        __syncthreads();

        const uint32_t sA = sbase + (ch & 1) * STG;
        const uint32_t sB = sA + SA;

        #pragma unroll
        for (int ks = 0; ks < 4; ks++) {
            uint32_t af[MI][4];
            #pragma unroll
            for (int im = 0; im < MI; im++)
                ldsm4(af[im][0], af[im][1], af[im][2], af[im][3],
                      sA + SWZ((wm0 + im * 16 + (l & 15)) * 128 + ks * 32 + ((l >> 4) & 1) * 16));
            uint32_t bf[NI][2];
            #pragma unroll
            for (int i2 = 0; i2 < NI / 2; i2++) {
                int g = l >> 3;
                uint32_t r0, r1, r2, r3;
                ldsm4(r0, r1, r2, r3,
                      sB + SWZ((wn0 + i2 * 16 + ((g >> 1) & 1) * 8 + (l & 7)) * 128 + ks * 32 + (g & 1) * 16));
                bf[2 * i2][0] = r0; bf[2 * i2][1] = r1;
                bf[2 * i2 + 1][0] = r2; bf[2 * i2 + 1][1] = r3;
            }
            #pragma unroll
            for (int im = 0; im < MI; im++)
                #pragma unroll
                for (int in = 0; in < NI; in++)
                    mma16816(c[im][in], af[im], bf[in]);
        }
        __syncthreads();
    }

    const int sel = (mode == 0) ? col0 / DMODEL : mode + 1;   // 0 q, 1 k, 2 final, 3 V
    const int dcol0 = col0 % DMODEL;
    const float* bs = (sel == 1) ? b1p : b0p;

    #pragma unroll
    for (int im = 0; im < MI; im++)
        #pragma unroll
        for (int in = 0; in < NI; in++)
            #pragma unroll
            for (int half_ = 0; half_ < 2; half_++) {
                int m = row0 + wm0 + im * 16 + (l >> 2) + half_ * 8;
                int nd = dcol0 + wn0 + in * 8 + (l & 3) * 2;
                float v0 = c[im][in][2 * half_] * WSCI + bs[nd];
                float v1 = c[im][in][2 * half_ + 1] * WSCI + bs[nd + 1];
                if (sel == 2) {
                    float2 w; w.x = v0; w.y = v1;
                    *(float2*)((float*)o0 + (size_t)m * DMODEL + nd) = w;
                    continue;
                }
                int b = m >> 10, s = m & 1023, h = nd >> 6, dd = nd & 63;
                if (sel == 0) {
                    v0 *= 0.125f; v1 *= 0.125f;
                    __half2 hp, lp;
                    hilo2(v0, v1, hp, lp);
                    __half* ob = (__half*)o0;
                    size_t base = ((size_t)(b * NHEAD + h) * SSEQ + s) * QSC + dd;
                    *(__half2*)(ob + base)         = hp;
                    *(__half2*)(ob + base + DHEAD) = lp;
                } else {          // k (sel==1) or V (sel==3): single fp16
                    __half2 t; t.x = __float2half_rn(v0); t.y = __float2half_rn(v1);
                    __half* ob = (sel == 1) ? (__half*)o1 : (__half*)o0;
                    *(__half2*)(ob + ((size_t)(b * NHEAD + h) * SSEQ + s) * DHEAD + dd) = t;
                }
            }
}

// ============================ fused attention v3 ============================
// CTA: (bh, 64 q-rows). 8 warps: rg=w>>1 rows [rg*16,+16), ch=w&1 kv half.
// S = 2-term (q hi/lo vs k single); PV = 2-term (P hi/lo vs V single).
#define SQ_OFF  0                         // 2 x 8KB q chunks (hi, lo)
#define SK_OFF  16384                     // 2 x 16KB K buffers
#define SV_OFF  49152                     // 16KB V
#define FSM_BYTES 65536

__global__ __launch_bounds__(256, 2) void fused_attn(
    const __half* __restrict__ Qp, const __half* __restrict__ Kp,
    const __half* __restrict__ Vp,
    float* __restrict__ attn, float* __restrict__ lbuf,
    __half* __restrict__ cP)
{
    extern __shared__ char smem[];
    const uint32_t sbase = smem_u32(smem);
    const int tid = threadIdx.x, l = tid & 31, wid = tid >> 5;
    const int rg = wid >> 1, ch = wid & 1;
    const int bh = blockIdx.y, q0 = blockIdx.x * 64;
    const int wm0 = rg * 16;

    const __half* Qb = Qp + (size_t)bh * SSEQ * QSC;
    const __half* Kb = Kp + (size_t)bh * SSEQ * DHEAD;
    const __half* Vb = Vp + (size_t)bh * SSEQ * DHEAD;

    auto issueK = [&](int t, int st) {
        const uint32_t kb = sbase + SK_OFF + st * 16384;
        for (int i = tid; i < 1024; i += 256) {
            int r = i >> 3, v = i & 7;
            cp16(kb + SWZ(r * 128 + v * 16), Kb + (size_t)(t * 128 + r) * DHEAD + v * 8);
        }
    };
    auto issueV = [&](int t) {
        for (int i = tid; i < 1024; i += 256) {
            int r = i >> 3, v = i & 7;
            cp16(sbase + SV_OFF + SWZ(r * 128 + v * 16),
                 Vb + (size_t)(t * 128 + r) * DHEAD + v * 8);
        }
    };

    // preload Q (64 rows x [hi|lo]) into 2 chunks of 64 dims
    for (int i = tid; i < 1024; i += 256) {
        int r = i >> 4, v = i & 15;
        int c = v >> 3, vv = v & 7;
        cp16(sbase + SQ_OFF + c * 8192 + SWZ(r * 128 + vv * 16),
             Qb + (size_t)(q0 + r) * QSC + v * 8);
    }
    issueK(0, 0);
    CP_COMMIT();

    float c_o[8][4] = {};
    float lsum0 = 0.f, lsum1 = 0.f;

    for (int t = 0; t < 8; t++) {
        CP_WAIT(0);
        __syncthreads();
        issueV(t); CP_COMMIT();
        if (t < 7) { issueK(t + 1, (t + 1) & 1); CP_COMMIT(); }

        // ---- S: 16 q-rows x 64 kv (this warp's half), 2-term ----
        float cs[8][4] = {};
        const uint32_t kb = sbase + SK_OFF + (t & 1) * 16384;
        #pragma unroll
        for (int cch = 0; cch < 2; cch++) {
            const uint32_t sQ = sbase + SQ_OFF + cch * 8192;
            #pragma unroll
            for (int ks = 0; ks < 4; ks++) {
                uint32_t af[4];
                ldsm4(af[0], af[1], af[2], af[3],
                      sQ + SWZ((wm0 + (l & 15)) * 128 + ks * 32 + ((l >> 4) & 1) * 16));
                #pragma unroll
                for (int i2 = 0; i2 < 4; i2++) {
                    int g = l >> 3;
                    uint32_t r0, r1, r2, r3;
                    ldsm4(r0, r1, r2, r3,
                          kb + SWZ((ch * 64 + i2 * 16 + ((g >> 1) & 1) * 8 + (l & 7)) * 128
                                   + ks * 32 + (g & 1) * 16));
                    uint32_t b0[2] = {r0, r1}, b1[2] = {r2, r3};
                    mma16816(cs[2 * i2],     af, b0);
                    mma16816(cs[2 * i2 + 1], af, b1);
                }
            }
        }

        // ---- exp + row-sum + unnormalized attn write ----
        #pragma unroll
        for (int in = 0; in < 8; in++) {
            cs[in][0] = __expf(cs[in][0]);
            cs[in][1] = __expf(cs[in][1]);
            cs[in][2] = __expf(cs[in][2]);
            cs[in][3] = __expf(cs[in][3]);
            lsum0 += cs[in][0] + cs[in][1];
            lsum1 += cs[in][2] + cs[in][3];
        }
        {
            float* a0 = attn + ((size_t)bh << 20) + (size_t)(q0 + wm0 + (l >> 2)) * SSEQ
                        + t * 128 + ch * 64 + 2 * (l & 3);
            float* a1 = a0 + 8 * SSEQ;
            #pragma unroll
            for (int in = 0; in < 8; in++) {
                float2 w0; w0.x = cs[in][0]; w0.y = cs[in][1];
                float2 w1; w1.x = cs[in][2]; w1.y = cs[in][3];
                *(float2*)(a0 + in * 8) = w0;
                *(float2*)(a1 + in * 8) = w1;
            }
        }

        if (t < 7) CP_WAIT(1); else CP_WAIT(0);
        __syncthreads();

        // ---- partial O += P~ @ V over warp's 64 kv (2-term) ----
        const uint32_t sVh = sbase + SV_OFF;
        #pragma unroll
        for (int kk = 0; kk < 4; kk++) {
            uint32_t ah[4], al[4];
            ah[0] = pk_hi(cs[2*kk][0],   cs[2*kk][1]);   al[0] = pk_lo(cs[2*kk][0],   cs[2*kk][1],   ah[0]);
            ah[1] = pk_hi(cs[2*kk][2],   cs[2*kk][3]);   al[1] = pk_lo(cs[2*kk][2],   cs[2*kk][3],   ah[1]);
            ah[2] = pk_hi(cs[2*kk+1][0], cs[2*kk+1][1]); al[2] = pk_lo(cs[2*kk+1][0], cs[2*kk+1][1], ah[2]);
            ah[3] = pk_hi(cs[2*kk+1][2], cs[2*kk+1][3]); al[3] = pk_lo(cs[2*kk+1][2], cs[2*kk+1][3], ah[3]);
            uint32_t vrow = (uint32_t)(ch * 64 + kk * 16 + ((l >> 3) & 1) * 8 + (l & 7)) * 128
                          + ((uint32_t)(l >> 4)) * 16;
            #pragma unroll
            for (int in = 0; in < 8; in += 2) {
                uint32_t h0, h1, h2, h3;
                ldsm4t(h0, h1, h2, h3, sVh + SWZ(vrow + in * 16));
                uint32_t bh2[2] = {h0, h1}, bh3[2] = {h2, h3};
                mma16816(c_o[in],     ah, bh2);
                mma16816(c_o[in],     al, bh2);
                mma16816(c_o[in + 1], ah, bh3);
                mma16816(c_o[in + 1], al, bh3);
            }
        }
        __syncthreads();
    }

    // ---- pair reduction (ch=1 -> smem -> ch=0), then finalize ----
    lsum0 += __shfl_xor_sync(0xffffffffu, lsum0, 1);
    lsum0 += __shfl_xor_sync(0xffffffffu, lsum0, 2);
    lsum1 += __shfl_xor_sync(0xffffffffu, lsum1, 1);
    lsum1 += __shfl_xor_sync(0xffffffffu, lsum1, 2);

    float* redO = (float*)(smem + SK_OFF);             // 4 rg x 16 x 64 = 16KB
    float* redL = (float*)(smem + SK_OFF + 16384);     // 4 rg x 16
    __syncthreads();
    if (ch == 1) {
        #pragma unroll
        for (int in = 0; in < 8; in++) {
            int cidx = in * 8 + 2 * (l & 3);
            int r = l >> 2;
            redO[rg * 1024 + r * 64 + cidx]           = c_o[in][0];
            redO[rg * 1024 + r * 64 + cidx + 1]       = c_o[in][1];
            redO[rg * 1024 + (r + 8) * 64 + cidx]     = c_o[in][2];
            redO[rg * 1024 + (r + 8) * 64 + cidx + 1] = c_o[in][3];
        }
        if ((l & 3) == 0) {
            redL[rg * 16 + (l >> 2)]     = lsum0;
            redL[rg * 16 + (l >> 2) + 8] = lsum1;
        }
    }
    __syncthreads();
    if (ch == 0) {
        lsum0 += redL[rg * 16 + (l >> 2)];
        lsum1 += redL[rg * 16 + (l >> 2) + 8];

        const int r0g = q0 + wm0 + (l >> 2);
        if ((l & 3) == 0) {
            lbuf[(size_t)bh * SSEQ + r0g]     = lsum0;
            lbuf[(size_t)bh * SSEQ + r0g + 8] = lsum1;
        }
        const float inv0 = 1.0f / lsum0, inv1 = 1.0f / lsum1;

        const int b = bh / NHEAD, h = bh % NHEAD;
        const size_t gm0 = (size_t)(b * SSEQ + r0g) * KP2;
        const size_t gm1 = gm0 + (size_t)8 * KP2;
        #pragma unroll
        for (int in = 0; in < 8; in++) {
            int cidx = in * 8 + 2 * (l & 3);
            int r = l >> 2;
            float o0 = (c_o[in][0] + redO[rg * 1024 + r * 64 + cidx])           * inv0;
            float o1 = (c_o[in][1] + redO[rg * 1024 + r * 64 + cidx + 1])       * inv0;
            float o2 = (c_o[in][2] + redO[rg * 1024 + (r + 8) * 64 + cidx])     * inv1;
            float o3 = (c_o[in][3] + redO[rg * 1024 + (r + 8) * 64 + cidx + 1]) * inv1;
            int d = h * DHEAD + cidx;
            __half2 hp, lp;
            hilo2(o0, o1, hp, lp);
            *(__half2*)(cP + gm0 + d)          = hp;
            *(__half2*)(cP + gm0 + d + DMODEL) = lp;
            hilo2(o2, o3, hp, lp);
            *(__half2*)(cP + gm1 + d)          = hp;
            *(__half2*)(cP + gm1 + d + DMODEL) = lp;
        }
    }
}

__global__ __launch_bounds__(256) void rescale_attn(float* __restrict__ attn,
                                                    const float* __restrict__ lbuf)
{
    const size_t row = blockIdx.x;
    const float inv = 1.0f / lbuf[row];
    float4* p = (float4*)(attn + row * SSEQ);
    float4 v = p[threadIdx.x];
    v.x *= inv; v.y *= inv; v.z *= inv; v.w *= inv;
    p[threadIdx.x] = v;
}

// ============================ prep kernels ==================================
__global__ __launch_bounds__(256) void pack_a(const float* __restrict__ in, __half* __restrict__ o)
{
    size_t i = (size_t)blockIdx.x * 256 + threadIdx.x;
    size_t m = i / (DMODEL / 2);
    int kk = (int)(i % (DMODEL / 2)) * 2;
    if (m >= MROWS) return;
    float2 v = *(const float2*)(in + m * DMODEL + kk);
    __half2 hp, lp;
    hilo2(v.x, v.y, hp, lp);
    size_t base = m * KP2 + kk;
    *(__half2*)(o + base)          = hp;
    *(__half2*)(o + base + DMODEL) = lp;
}

__global__ void pack_w_all(const float* __restrict__ Wq, const float* __restrict__ Wk,
                           const float* __restrict__ Wv, const float* __restrict__ Wo,
                           __half* __restrict__ wqk, __half* __restrict__ wvh,
                           __half* __restrict__ wo)
{
    __shared__ float t[32][33];
    const int z = blockIdx.z;
    const float* W = (z == 0) ? Wq : (z == 1) ? Wk : (z == 2) ? Wv : Wo;
    int n0 = blockIdx.x * 32, k0 = blockIdx.y * 32;
    int x = threadIdx.x, y = threadIdx.y;
    #pragma unroll
    for (int j = 0; j < 32; j += 8)
        t[y + j][x] = W[(size_t)(k0 + y + j) * DMODEL + n0 + x] * WSC;
    __syncthreads();
    if (z == 2) {
        #pragma unroll
        for (int j = 0; j < 32; j += 8)
            wvh[(size_t)(n0 + y + j) * DMODEL + k0 + x] = __float2half_rn(t[x][y + j]);
        return;
    }
    __half* o = (z == 3) ? wo : wqk + (size_t)z * DMODEL * KP2;
    #pragma unroll
    for (int j = 0; j < 32; j += 8) {
        __half h = __float2half_rn(t[x][y + j]);
        size_t base = (size_t)(n0 + y + j) * KP2 + k0 + x;
        o[base] = h;
        o[base + DMODEL] = h;     // duplicate hi ([wh|wh])
    }
}

// ============================ host launcher =================================
extern "C" void kernel_launch(void* const* d_in, const int* in_sizes, int n_in,
                              void* d_out, int out_size)
{
    (void)in_sizes; (void)n_in;
    const float* x  = (const float*)d_in[0];
    const float* Wq = (const float*)d_in[1];
    const float* bq = (const float*)d_in[2];
    const float* Wk = (const float*)d_in[3];
    const float* bk = (const float*)d_in[4];
    const float* Wv = (const float*)d_in[5];
    const float* bv = (const float*)d_in[6];
    const float* Wo = (const float*)d_in[7];
    const float* bo = (const float*)d_in[8];
    float* out = (float*)d_out;

    float *gattn, *gl;
    __half *xP, *wqkP, *wvh, *woP, *qP, *kP, *vP, *cP;
    cudaGetSymbolAddress((void**)&gattn, g_attn);
    cudaGetSymbolAddress((void**)&gl,   g_l);
    cudaGetSymbolAddress((void**)&xP,   g_xP);
    cudaGetSymbolAddress((void**)&wqkP, g_wqkP);
    cudaGetSymbolAddress((void**)&wvh,  g_wvh);
    cudaGetSymbolAddress((void**)&woP,  g_woP);
    cudaGetSymbolAddress((void**)&qP,   g_qP);
    cudaGetSymbolAddress((void**)&kP,   g_k);
    cudaGetSymbolAddress((void**)&vP,   g_v);
    cudaGetSymbolAddress((void**)&cP,   g_cP);

    const size_t final_elems = (size_t)MROWS * DMODEL;
    float* attn = ((size_t)out_size > final_elems) ? (out + final_elems) : gattn;

    static cudaStream_t s2 = nullptr;
    static cudaEvent_t evA = nullptr, evB = nullptr;
    if (s2 == nullptr) {
        cudaStreamCreateWithFlags(&s2, cudaStreamNonBlocking);
        cudaEventCreateWithFlags(&evA, cudaEventDisableTiming);
        cudaEventCreateWithFlags(&evB, cudaEventDisableTiming);
    }

    constexpr int SM_GEMM = 2 * (128 * 64 * 2 + 128 * 64 * 2);
    cudaFuncSetAttribute(hgemm,      cudaFuncAttributeMaxDynamicSharedMemorySize, SM_GEMM);
    cudaFuncSetAttribute(fused_attn, cudaFuncAttributeMaxDynamicSharedMemorySize, FSM_BYTES);

    // pack
    {
        size_t pairs = (size_t)MROWS * (DMODEL / 2);
        pack_a<<<(unsigned)((pairs + 255) / 256), 256>>>(x, xP);
        dim3 tb(32, 8), tg(DMODEL / 32, DMODEL / 32, 4);
        pack_w_all<<<tg, tb>>>(Wq, Wk, Wv, Wo, wqkP, wvh, woP);
    }

    // QK merged projection (N = 1536, K = 1536, 2-term)
    dim3 gqk(2 * DMODEL / 128, MROWS / 128);      // (12, 64)
    hgemm<<<gqk, 256, SM_GEMM>>>(xP, wqkP, bq, bk, qP, kP, KP2, KP2, 0);

    // V projection (N = 768, K = 768, 1-term)
    dim3 gv(DMODEL / 128, MROWS / 128);           // (6, 64)
    hgemm<<<gv, 256, SM_GEMM>>>(xP, wvh, bv, nullptr, vP, nullptr, DMODEL, DMODEL, 2);

    // fused scores + softmax + AV (64-row q-tiles, 2 CTAs/SM)
    dim3 gf(SSEQ / 64, NBH);                      // (16, 96)
    fused_attn<<<gf, 256, FSM_BYTES>>>(qP, kP, vP, attn, gl, cP);

    // rescale attn on s2, overlapped with final GEMM
    cudaEventRecord(evA, 0);
    cudaStreamWaitEvent(s2, evA, 0);
    rescale_attn<<<NBH * SSEQ, 256, 0, s2>>>(attn, gl);
    cudaEventRecord(evB, s2);

    // out = ctx @ Wo + bo (K = 1536, 2-term)
    hgemm<<<gv, 256, SM_GEMM>>>(cP, woP, bo, nullptr, out, nullptr, KP2, KP2, 1);

    cudaStreamWaitEvent(0, evB, 0);
}

// round 9
// speedup vs baseline: 3.9002x; 1.1143x over previous
#include <cuda_runtime.h>
#include <cuda_fp16.h>
#include <cstdint>

#define BBATCH 8
#define SSEQ   1024
#define DMODEL 768
#define NHEAD  12
#define DHEAD  64
#define MROWS  (BBATCH*SSEQ)     // 8192
#define NBH    (BBATCH*NHEAD)    // 96
#define KP2    1536              // [hi|lo] packed K
#define QSC    128               // q per-row dims [hi(64)|lo(64)]
#define WSC    32.0f
#define WSCI   0.03125f

// ---------------- scratch (device globals; no allocations allowed) ----------
__device__ float g_attn[(size_t)NBH*SSEQ*SSEQ];          // fallback attn (fp32)
__device__ float g_l[(size_t)NBH*SSEQ];
__device__ __half g_pt [(size_t)NBH*SSEQ*SSEQ];          // unnormalized exp(S), fp16 (201MB)
__device__ __half g_xP  [(size_t)MROWS*KP2];             // x [hi|lo]
__device__ __half g_wqkP[(size_t)2*DMODEL*KP2];          // Wq|Wk rows (x32, [wh|wh])
__device__ __half g_wvh [(size_t)DMODEL*DMODEL];         // Wv hi
__device__ __half g_woP [(size_t)DMODEL*KP2];            // Wo [wh|wh]
__device__ __half g_qP [(size_t)NBH*SSEQ*QSC];           // q*0.125 [hi|lo]
__device__ __half g_k  [(size_t)NBH*SSEQ*DHEAD];         // k single fp16
__device__ __half g_v  [(size_t)NBH*SSEQ*DHEAD];         // V single fp16
__device__ __half g_cP [(size_t)MROWS*KP2];              // ctx [hi|lo]

// ============================ PTX helpers ===================================
__device__ __forceinline__ uint32_t smem_u32(const void* p) {
    uint32_t a;
    asm("{ .reg .u64 t; cvta.to.shared.u64 t, %1; cvt.u32.u64 %0, t; }" : "=r"(a) : "l"(p));
    return a;
}
#define SWZ(o) ((uint32_t)(o) ^ ((((uint32_t)(o)) >> 3) & 0x70))

__device__ __forceinline__ void cp16(uint32_t s, const void* g) {
    asm volatile("cp.async.cg.shared.global [%0], [%1], 16;" :: "r"(s), "l"(g));
}
#define CP_COMMIT() asm volatile("cp.async.commit_group;")
#define CP_WAIT(n)  asm volatile("cp.async.wait_group %0;" :: "n"(n))

__device__ __forceinline__ void ldsm4(uint32_t& r0, uint32_t& r1, uint32_t& r2, uint32_t& r3, uint32_t a) {
    asm volatile("ldmatrix.sync.aligned.m8n8.x4.shared.b16 {%0,%1,%2,%3}, [%4];"
                 : "=r"(r0), "=r"(r1), "=r"(r2), "=r"(r3) : "r"(a));
}
__device__ __forceinline__ void ldsm4t(uint32_t& r0, uint32_t& r1, uint32_t& r2, uint32_t& r3, uint32_t a) {
    asm volatile("ldmatrix.sync.aligned.m8n8.x4.trans.shared.b16 {%0,%1,%2,%3}, [%4];"
                 : "=r"(r0), "=r"(r1), "=r"(r2), "=r"(r3) : "r"(a));
}
__device__ __forceinline__ void mma16816(float* c, const uint32_t* a, const uint32_t* b) {
    asm volatile("mma.sync.aligned.m16n8k16.row.col.f32.f16.f16.f32 "
                 "{%0,%1,%2,%3}, {%4,%5,%6,%7}, {%8,%9}, {%0,%1,%2,%3};"
                 : "+f"(c[0]), "+f"(c[1]), "+f"(c[2]), "+f"(c[3])
                 : "r"(a[0]), "r"(a[1]), "r"(a[2]), "r"(a[3]), "r"(b[0]), "r"(b[1]));
}

__device__ __forceinline__ void hilo2(float v0, float v1, __half2& hp, __half2& lp) {
    __half h0 = __float2half_rn(v0), h1 = __float2half_rn(v1);
    hp.x = h0; hp.y = h1;
    lp.x = __float2half_rn(v0 - __half2float(h0));
    lp.y = __float2half_rn(v1 - __half2float(h1));
}
__device__ __forceinline__ uint32_t pk_hi(float x, float y) {
    __half2 t; t.x = __float2half_rn(x); t.y = __float2half_rn(y);
    return *(uint32_t*)&t;
}
__device__ __forceinline__ uint32_t pk_lo(float x, float y, uint32_t hi) {
    __half2 h = *(__half2*)&hi;
    __half2 t;
    t.x = __float2half_rn(x - __half2float(h.x));
    t.y = __float2half_rn(y - __half2float(h.y));
    return *(uint32_t*)&t;
}

// ============================ unified GEMM (HMMA fp16, 3-stage) =============
// mode 0: QK merged (N=1536: q [hi|lo] / k single)  mode 1: final (fp32)
// mode 2: V (single fp16)
__global__ __launch_bounds__(256, 2) void hgemm(
    const __half* __restrict__ Ag, const __half* __restrict__ Bg,
    const float* __restrict__ b0p, const float* __restrict__ b1p,
    void* __restrict__ o0, void* __restrict__ o1,
    int K, int ldB, int mode)
{
    constexpr int BM = 128, BN = 128, BK = 64;
    constexpr int MI = 4, NI = 4;
    constexpr int SA = BM * BK * 2, SB = BN * BK * 2, STG = SA + SB;  // 32KB/stage

    extern __shared__ char smem[];
    const uint32_t sbase = smem_u32(smem);
    const int tid = threadIdx.x, l = tid & 31, wid = tid >> 5;
    const int row0 = blockIdx.y * BM, col0 = blockIdx.x * BN;
    const int wm0 = (wid / 4) * 64, wn0 = (wid % 4) * 32;

    auto issue = [&](int ch, int st) {
        const int k0 = ch * BK;
        const uint32_t sA = sbase + st * STG;
        const uint32_t sB = sA + SA;
        for (int i = tid; i < BM * 8; i += 256) {
            int r = i >> 3, v = i & 7;
            cp16(sA + SWZ(r * 128 + v * 16), Ag + (size_t)(row0 + r) * KP2 + k0 + v * 8);
        }
        for (int i = tid; i < BN * 8; i += 256) {
            int r = i >> 3, v = i & 7;
            cp16(sB + SWZ(r * 128 + v * 16), Bg + (size_t)(col0 + r) * ldB + k0 + v * 8);
        }
    };

    float c[MI][NI][4] = {};
    const int nch = K / BK;
    issue(0, 0); CP_COMMIT();
    if (nch > 1) { issue(1, 1); CP_COMMIT(); }

    for (int ch = 0; ch < nch; ch++) {
        if (ch + 1 < nch) { CP_WAIT(1); } else { CP_WAIT(0); }
        __syncthreads();
        if (ch + 2 < nch) { issue(ch + 2, (ch + 2) % 3); CP_COMMIT(); }

        const uint32_t sA = sbase + (ch % 3) * STG;
        const uint32_t sB = sA + SA;

        #pragma unroll
        for (int ks = 0; ks < 4; ks++) {
            uint32_t af[MI][4];
            #pragma unroll
            for (int im = 0; im < MI; im++)
                ldsm4(af[im][0], af[im][1], af[im][2], af[im][3],
                      sA + SWZ((wm0 + im * 16 + (l & 15)) * 128 + ks * 32 + ((l >> 4) & 1) * 16));
            uint32_t bf[NI][2];
            #pragma unroll
            for (int i2 = 0; i2 < NI / 2; i2++) {
                int g = l >> 3;
                uint32_t r0, r1, r2, r3;
                ldsm4(r0, r1, r2, r3,
                      sB + SWZ((wn0 + i2 * 16 + ((g >> 1) & 1) * 8 + (l & 7)) * 128 + ks * 32 + (g & 1) * 16));
                bf[2 * i2][0] = r0; bf[2 * i2][1] = r1;
                bf[2 * i2 + 1][0] = r2; bf[2 * i2 + 1][1] = r3;
            }
            #pragma unroll
            for (int im = 0; im < MI; im++)
                #pragma unroll
                for (int in = 0; in < NI; in++)
                    mma16816(c[im][in], af[im], bf[in]);
        }
    }
    __syncthreads();

    const int sel = (mode == 0) ? col0 / DMODEL : mode + 1;   // 0 q, 1 k, 2 final, 3 V
    const int dcol0 = col0 % DMODEL;
    const float* bs = (sel == 1) ? b1p : b0p;

    #pragma unroll
    for (int im = 0; im < MI; im++)
        #pragma unroll
        for (int in = 0; in < NI; in++)
            #pragma unroll
            for (int half_ = 0; half_ < 2; half_++) {
                int m = row0 + wm0 + im * 16 + (l >> 2) + half_ * 8;
                int nd = dcol0 + wn0 + in * 8 + (l & 3) * 2;
                float v0 = c[im][in][2 * half_] * WSCI + bs[nd];
                float v1 = c[im][in][2 * half_ + 1] * WSCI + bs[nd + 1];
                if (sel == 2) {
                    float2 w; w.x = v0; w.y = v1;
                    *(float2*)((float*)o0 + (size_t)m * DMODEL + nd) = w;
                    continue;
                }
                int b = m >> 10, s = m & 1023, h = nd >> 6, dd = nd & 63;
                if (sel == 0) {
                    v0 *= 0.125f; v1 *= 0.125f;
                    __half2 hp, lp;
                    hilo2(v0, v1, hp, lp);
                    __half* ob = (__half*)o0;
                    size_t base = ((size_t)(b * NHEAD + h) * SSEQ + s) * QSC + dd;
                    *(__half2*)(ob + base)         = hp;
                    *(__half2*)(ob + base + DHEAD) = lp;
                } else {          // k (sel==1) or V (sel==3): single fp16
                    __half2 t; t.x = __float2half_rn(v0); t.y = __float2half_rn(v1);
                    __half* ob = (sel == 1) ? (__half*)o1 : (__half*)o0;
                    *(__half2*)(ob + ((size_t)(b * NHEAD + h) * SSEQ + s) * DHEAD + dd) = t;
                }
            }
}

// ============================ fused attention ===============================
// CTA: (bh, 64 q-rows). 8 warps: rg=w>>1 rows [rg*16,+16), ch=w&1 kv half.
// S 2-term; PV 2-term; p~ staged fp16.
#define SQ_OFF  0                         // 2 x 8KB q chunks (hi, lo)
#define SK_OFF  16384                     // 2 x 16KB K buffers
#define SV_OFF  49152                     // 16KB V
#define FSM_BYTES 65536

__global__ __launch_bounds__(256, 2) void fused_attn(
    const __half* __restrict__ Qp, const __half* __restrict__ Kp,
    const __half* __restrict__ Vp,
    __half* __restrict__ pt, float* __restrict__ lbuf,
    __half* __restrict__ cP)
{
    extern __shared__ char smem[];
    const uint32_t sbase = smem_u32(smem);
    const int tid = threadIdx.x, l = tid & 31, wid = tid >> 5;
    const int rg = wid >> 1, ch = wid & 1;
    const int bh = blockIdx.y, q0 = blockIdx.x * 64;
    const int wm0 = rg * 16;

    const __half* Qb = Qp + (size_t)bh * SSEQ * QSC;
    const __half* Kb = Kp + (size_t)bh * SSEQ * DHEAD;
    const __half* Vb = Vp + (size_t)bh * SSEQ * DHEAD;

    auto issueK = [&](int t, int st) {
        const uint32_t kb = sbase + SK_OFF + st * 16384;
        for (int i = tid; i < 1024; i += 256) {
            int r = i >> 3, v = i & 7;
            cp16(kb + SWZ(r * 128 + v * 16), Kb + (size_t)(t * 128 + r) * DHEAD + v * 8);
        }
    };
    auto issueV = [&](int t) {
        for (int i = tid; i < 1024; i += 256) {
            int r = i >> 3, v = i & 7;
            cp16(sbase + SV_OFF + SWZ(r * 128 + v * 16),
                 Vb + (size_t)(t * 128 + r) * DHEAD + v * 8);
        }
    };

    for (int i = tid; i < 1024; i += 256) {
        int r = i >> 4, v = i & 15;
        int c = v >> 3, vv = v & 7;
        cp16(sbase + SQ_OFF + c * 8192 + SWZ(r * 128 + vv * 16),
             Qb + (size_t)(q0 + r) * QSC + v * 8);
    }
    issueK(0, 0);
    CP_COMMIT();

    float c_o[8][4] = {};
    float lsum0 = 0.f, lsum1 = 0.f;

    for (int t = 0; t < 8; t++) {
        CP_WAIT(0);
        __syncthreads();
        issueV(t); CP_COMMIT();
        if (t < 7) { issueK(t + 1, (t + 1) & 1); CP_COMMIT(); }

        // ---- S: 16 q-rows x 64 kv (this warp's half), 2-term ----
        float cs[8][4] = {};
        const uint32_t kb = sbase + SK_OFF + (t & 1) * 16384;
        #pragma unroll
        for (int cch = 0; cch < 2; cch++) {
            const uint32_t sQ = sbase + SQ_OFF + cch * 8192;
            #pragma unroll
            for (int ks = 0; ks < 4; ks++) {
                uint32_t af[4];
                ldsm4(af[0], af[1], af[2], af[3],
                      sQ + SWZ((wm0 + (l & 15)) * 128 + ks * 32 + ((l >> 4) & 1) * 16));
                #pragma unroll
                for (int i2 = 0; i2 < 4; i2++) {
                    int g = l >> 3;
                    uint32_t r0, r1, r2, r3;
                    ldsm4(r0, r1, r2, r3,
                          kb + SWZ((ch * 64 + i2 * 16 + ((g >> 1) & 1) * 8 + (l & 7)) * 128
                                   + ks * 32 + (g & 1) * 16));
                    uint32_t b0[2] = {r0, r1}, b1[2] = {r2, r3};
                    mma16816(cs[2 * i2],     af, b0);
                    mma16816(cs[2 * i2 + 1], af, b1);
                }
            }
        }

        // ---- exp + row-sum + fp16 p~ write ----
        #pragma unroll
        for (int in = 0; in < 8; in++) {
            cs[in][0] = __expf(cs[in][0]);
            cs[in][1] = __expf(cs[in][1]);
            cs[in][2] = __expf(cs[in][2]);
            cs[in][3] = __expf(cs[in][3]);
            lsum0 += cs[in][0] + cs[in][1];
            lsum1 += cs[in][2] + cs[in][3];
        }
        {
            __half* p0 = pt + ((size_t)bh << 20) + (size_t)(q0 + wm0 + (l >> 2)) * SSEQ
                         + t * 128 + ch * 64 + 2 * (l & 3);
            __half* p1 = p0 + 8 * SSEQ;
            #pragma unroll
            for (int in = 0; in < 8; in++) {
                uint32_t w0 = pk_hi(cs[in][0], cs[in][1]);
                uint32_t w1 = pk_hi(cs[in][2], cs[in][3]);
                *(uint32_t*)(p0 + in * 8) = w0;
                *(uint32_t*)(p1 + in * 8) = w1;
            }
        }

        if (t < 7) CP_WAIT(1); else CP_WAIT(0);
        __syncthreads();

        // ---- partial O += P~ @ V over warp's 64 kv (2-term) ----
        const uint32_t sVh = sbase + SV_OFF;
        #pragma unroll
        for (int kk = 0; kk < 4; kk++) {
            uint32_t ah[4], al[4];
            ah[0] = pk_hi(cs[2*kk][0],   cs[2*kk][1]);   al[0] = pk_lo(cs[2*kk][0],   cs[2*kk][1],   ah[0]);
            ah[1] = pk_hi(cs[2*kk][2],   cs[2*kk][3]);   al[1] = pk_lo(cs[2*kk][2],   cs[2*kk][3],   ah[1]);
            ah[2] = pk_hi(cs[2*kk+1][0], cs[2*kk+1][1]); al[2] = pk_lo(cs[2*kk+1][0], cs[2*kk+1][1], ah[2]);
            ah[3] = pk_hi(cs[2*kk+1][2], cs[2*kk+1][3]); al[3] = pk_lo(cs[2*kk+1][2], cs[2*kk+1][3], ah[3]);
            uint32_t vrow = (uint32_t)(ch * 64 + kk * 16 + ((l >> 3) & 1) * 8 + (l & 7)) * 128
                          + ((uint32_t)(l >> 4)) * 16;
            #pragma unroll
            for (int in = 0; in < 8; in += 2) {
                uint32_t h0, h1, h2, h3;
                ldsm4t(h0, h1, h2, h3, sVh + SWZ(vrow + in * 16));
                uint32_t bh2[2] = {h0, h1}, bh3[2] = {h2, h3};
                mma16816(c_o[in],     ah, bh2);
                mma16816(c_o[in],     al, bh2);
                mma16816(c_o[in + 1], ah, bh3);
                mma16816(c_o[in + 1], al, bh3);
            }
        }
        __syncthreads();
    }

    // ---- pair reduction (ch=1 -> smem -> ch=0), then finalize ----
    lsum0 += __shfl_xor_sync(0xffffffffu, lsum0, 1);
    lsum0 += __shfl_xor_sync(0xffffffffu, lsum0, 2);
    lsum1 += __shfl_xor_sync(0xffffffffu, lsum1, 1);
    lsum1 += __shfl_xor_sync(0xffffffffu, lsum1, 2);

    float* redO = (float*)(smem + SK_OFF);             // 4 rg x 16 x 64 = 16KB
    float* redL = (float*)(smem + SK_OFF + 16384);     // 4 rg x 16
    __syncthreads();
    if (ch == 1) {
        #pragma unroll
        for (int in = 0; in < 8; in++) {
            int cidx = in * 8 + 2 * (l & 3);
            int r = l >> 2;
            redO[rg * 1024 + r * 64 + cidx]           = c_o[in][0];
            redO[rg * 1024 + r * 64 + cidx + 1]       = c_o[in][1];
            redO[rg * 1024 + (r + 8) * 64 + cidx]     = c_o[in][2];
            redO[rg * 1024 + (r + 8) * 64 + cidx + 1] = c_o[in][3];
        }
        if ((l & 3) == 0) {
            redL[rg * 16 + (l >> 2)]     = lsum0;
            redL[rg * 16 + (l >> 2) + 8] = lsum1;
        }
    }
    __syncthreads();
    if (ch == 0) {
        lsum0 += redL[rg * 16 + (l >> 2)];
        lsum1 += redL[rg * 16 + (l >> 2) + 8];

        const int r0g = q0 + wm0 + (l >> 2);
        if ((l & 3) == 0) {
            lbuf[(size_t)bh * SSEQ + r0g]     = lsum0;
            lbuf[(size_t)bh * SSEQ + r0g + 8] = lsum1;
        }
        const float inv0 = 1.0f / lsum0, inv1 = 1.0f / lsum1;

        const int b = bh / NHEAD, h = bh % NHEAD;
        const size_t gm0 = (size_t)(b * SSEQ + r0g) * KP2;
        const size_t gm1 = gm0 + (size_t)8 * KP2;
        #pragma unroll
        for (int in = 0; in < 8; in++) {
            int cidx = in * 8 + 2 * (l & 3);
            int r = l >> 2;
            float o0 = (c_o[in][0] + redO[rg * 1024 + r * 64 + cidx])           * inv0;
            float o1 = (c_o[in][1] + redO[rg * 1024 + r * 64 + cidx + 1])       * inv0;
            float o2 = (c_o[in][2] + redO[rg * 1024 + (r + 8) * 64 + cidx])     * inv1;
            float o3 = (c_o[in][3] + redO[rg * 1024 + (r + 8) * 64 + cidx + 1]) * inv1;
            int d = h * DHEAD + cidx;
            __half2 hp, lp;
            hilo2(o0, o1, hp, lp);
            *(__half2*)(cP + gm0 + d)          = hp;
            *(__half2*)(cP + gm0 + d + DMODEL) = lp;
            hilo2(o2, o3, hp, lp);
            *(__half2*)(cP + gm1 + d)          = hp;
            *(__half2*)(cP + gm1 + d + DMODEL) = lp;
        }
    }
}

// rescale: read fp16 p~, normalize, write fp32 attn
__global__ __launch_bounds__(256) void rescale_attn(const __half* __restrict__ pt,
                                                    float* __restrict__ attn,
                                                    const float* __restrict__ lbuf)
{
    const size_t row = blockIdx.x;
    const float inv = 1.0f / lbuf[row];
    const __half2* s = (const __half2*)(pt + row * SSEQ);
    float4* d = (float4*)(attn + row * SSEQ);
    const int i = threadIdx.x;
    __half2 a = s[2 * i], b = s[2 * i + 1];
    float4 v;
    v.x = __half2float(a.x) * inv;
    v.y = __half2float(a.y) * inv;
    v.z = __half2float(b.x) * inv;
    v.w = __half2float(b.y) * inv;
    d[i] = v;
}

// ============================ prep kernels ==================================
__global__ __launch_bounds__(256) void pack_a(const float* __restrict__ in, __half* __restrict__ o)
{
    size_t i = (size_t)blockIdx.x * 256 + threadIdx.x;
    size_t m = i / (DMODEL / 2);
    int kk = (int)(i % (DMODEL / 2)) * 2;
    if (m >= MROWS) return;
    float2 v = *(const float2*)(in + m * DMODEL + kk);
    __half2 hp, lp;
    hilo2(v.x, v.y, hp, lp);
    size_t base = m * KP2 + kk;
    *(__half2*)(o + base)          = hp;
    *(__half2*)(o + base + DMODEL) = lp;
}

__global__ void pack_w_all(const float* __restrict__ Wq, const float* __restrict__ Wk,
                           const float* __restrict__ Wv, const float* __restrict__ Wo,
                           __half* __restrict__ wqk, __half* __restrict__ wvh,
                           __half* __restrict__ wo)
{
    __shared__ float t[32][33];
    const int z = blockIdx.z;
    const float* W = (z == 0) ? Wq : (z == 1) ? Wk : (z == 2) ? Wv : Wo;
    int n0 = blockIdx.x * 32, k0 = blockIdx.y * 32;
    int x = threadIdx.x, y = threadIdx.y;
    #pragma unroll
    for (int j = 0; j < 32; j += 8)
        t[y + j][x] = W[(size_t)(k0 + y + j) * DMODEL + n0 + x] * WSC;
    __syncthreads();
    if (z == 2) {
        #pragma unroll
        for (int j = 0; j < 32; j += 8)
            wvh[(size_t)(n0 + y + j) * DMODEL + k0 + x] = __float2half_rn(t[x][y + j]);
        return;
    }
    __half* o = (z == 3) ? wo : wqk + (size_t)z * DMODEL * KP2;
    #pragma unroll
    for (int j = 0; j < 32; j += 8) {
        __half h = __float2half_rn(t[x][y + j]);
        size_t base = (size_t)(n0 + y + j) * KP2 + k0 + x;
        o[base] = h;
        o[base + DMODEL] = h;
    }
}

// ============================ host launcher =================================
extern "C" void kernel_launch(void* const* d_in, const int* in_sizes, int n_in,
                              void* d_out, int out_size)
{
    (void)in_sizes; (void)n_in;
    const float* x  = (const float*)d_in[0];
    const float* Wq = (const float*)d_in[1];
    const float* bq = (const float*)d_in[2];
    const float* Wk = (const float*)d_in[3];
    const float* bk = (const float*)d_in[4];
    const float* Wv = (const float*)d_in[5];
    const float* bv = (const float*)d_in[6];
    const float* Wo = (const float*)d_in[7];
    const float* bo = (const float*)d_in[8];
    float* out = (float*)d_out;

    float *gattn, *gl;
    __half *pt, *xP, *wqkP, *wvh, *woP, *qP, *kP, *vP, *cP;
    cudaGetSymbolAddress((void**)&gattn, g_attn);
    cudaGetSymbolAddress((void**)&gl,   g_l);
    cudaGetSymbolAddress((void**)&pt,   g_pt);
    cudaGetSymbolAddress((void**)&xP,   g_xP);
    cudaGetSymbolAddress((void**)&wqkP, g_wqkP);
    cudaGetSymbolAddress((void**)&wvh,  g_wvh);
    cudaGetSymbolAddress((void**)&woP,  g_woP);
    cudaGetSymbolAddress((void**)&qP,   g_qP);
    cudaGetSymbolAddress((void**)&kP,   g_k);
    cudaGetSymbolAddress((void**)&vP,   g_v);
    cudaGetSymbolAddress((void**)&cP,   g_cP);

    const size_t final_elems = (size_t)MROWS * DMODEL;
    float* attn = ((size_t)out_size > final_elems) ? (out + final_elems) : gattn;

    static cudaStream_t s2 = nullptr;
    static cudaEvent_t evA = nullptr, evB = nullptr;
    if (s2 == nullptr) {
        cudaStreamCreateWithFlags(&s2, cudaStreamNonBlocking);
        cudaEventCreateWithFlags(&evA, cudaEventDisableTiming);
        cudaEventCreateWithFlags(&evB, cudaEventDisableTiming);
    }

    constexpr int SM_GEMM = 3 * (128 * 64 * 2 + 128 * 64 * 2);   // 96KB, 3-stage
    cudaFuncSetAttribute(hgemm,      cudaFuncAttributeMaxDynamicSharedMemorySize, SM_GEMM);
    cudaFuncSetAttribute(fused_attn, cudaFuncAttributeMaxDynamicSharedMemorySize, FSM_BYTES);

    // pack
    {
        size_t pairs = (size_t)MROWS * (DMODEL / 2);
        pack_a<<<(unsigned)((pairs + 255) / 256), 256>>>(x, xP);
        dim3 tb(32, 8), tg(DMODEL / 32, DMODEL / 32, 4);
        pack_w_all<<<tg, tb>>>(Wq, Wk, Wv, Wo, wqkP, wvh, woP);
    }

    // QK merged projection (N = 1536, K = 1536, 2-term)
    dim3 gqk(2 * DMODEL / 128, MROWS / 128);      // (12, 64)
    hgemm<<<gqk, 256, SM_GEMM>>>(xP, wqkP, bq, bk, qP, kP, KP2, KP2, 0);

    // V projection (N = 768, K = 768, 1-term)
    dim3 gv(DMODEL / 128, MROWS / 128);           // (6, 64)
    hgemm<<<gv, 256, SM_GEMM>>>(xP, wvh, bv, nullptr, vP, nullptr, DMODEL, DMODEL, 2);

    // fused scores + softmax + AV
    dim3 gf(SSEQ / 64, NBH);                      // (16, 96)
    fused_attn<<<gf, 256, FSM_BYTES>>>(qP, kP, vP, pt, gl, cP);

    // rescale attn on s2, overlapped with final GEMM
    cudaEventRecord(evA, 0);
    cudaStreamWaitEvent(s2, evA, 0);
    rescale_attn<<<NBH * SSEQ, 256, 0, s2>>>(pt, attn, gl);
    cudaEventRecord(evB, s2);

    // out = ctx @ Wo + bo (K = 1536, 2-term)
    hgemm<<<gv, 256, SM_GEMM>>>(cP, woP, bo, nullptr, out, nullptr, KP2, KP2, 1);

    cudaStreamWaitEvent(0, evB, 0);
}

// round 10
// speedup vs baseline: 4.1634x; 1.0675x over previous
#include <cuda_runtime.h>
#include <cuda_fp16.h>
#include <cstdint>

#define BBATCH 8
#define SSEQ   1024
#define DMODEL 768
#define NHEAD  12
#define DHEAD  64
#define MROWS  (BBATCH*SSEQ)     // 8192
#define NBH    (BBATCH*NHEAD)    // 96
#define KP2    1536              // [hi|lo] packed K
#define WSC    32.0f
#define WSCI   0.03125f

// ---------------- scratch (device globals; no allocations allowed) ----------
__device__ float g_attn[(size_t)NBH*SSEQ*SSEQ];          // fallback attn (fp32)
__device__ __half g_pt [(size_t)NBH*SSEQ*SSEQ];          // unnormalized exp(S), fp16
__device__ __half g_xP  [(size_t)MROWS*KP2];             // x [hi|lo]
__device__ __half g_wqkP[(size_t)2*DMODEL*KP2];          // Wq|Wk rows (x32, [wh|wh])
__device__ __half g_wvh [(size_t)DMODEL*DMODEL];         // Wv hi
__device__ __half g_woP [(size_t)DMODEL*KP2];            // Wo [wh|wh]
__device__ __half g_q  [(size_t)NBH*SSEQ*DHEAD];         // q*0.125 single fp16
__device__ __half g_k  [(size_t)NBH*SSEQ*DHEAD];         // k single fp16
__device__ __half g_v  [(size_t)NBH*SSEQ*DHEAD];         // V single fp16
__device__ __half g_cP [(size_t)MROWS*KP2];              // ctx [hi|lo]

// ============================ PTX helpers ===================================
__device__ __forceinline__ uint32_t smem_u32(const void* p) {
    uint32_t a;
    asm("{ .reg .u64 t; cvta.to.shared.u64 t, %1; cvt.u32.u64 %0, t; }" : "=r"(a) : "l"(p));
    return a;
}
#define SWZ(o) ((uint32_t)(o) ^ ((((uint32_t)(o)) >> 3) & 0x70))

__device__ __forceinline__ void cp16(uint32_t s, const void* g) {
    asm volatile("cp.async.cg.shared.global [%0], [%1], 16;" :: "r"(s), "l"(g));
}
#define CP_COMMIT() asm volatile("cp.async.commit_group;")
#define CP_WAIT(n)  asm volatile("cp.async.wait_group %0;" :: "n"(n))

__device__ __forceinline__ void ldsm4(uint32_t& r0, uint32_t& r1, uint32_t& r2, uint32_t& r3, uint32_t a) {
    asm volatile("ldmatrix.sync.aligned.m8n8.x4.shared.b16 {%0,%1,%2,%3}, [%4];"
                 : "=r"(r0), "=r"(r1), "=r"(r2), "=r"(r3) : "r"(a));
}
__device__ __forceinline__ void ldsm4t(uint32_t& r0, uint32_t& r1, uint32_t& r2, uint32_t& r3, uint32_t a) {
    asm volatile("ldmatrix.sync.aligned.m8n8.x4.trans.shared.b16 {%0,%1,%2,%3}, [%4];"
                 : "=r"(r0), "=r"(r1), "=r"(r2), "=r"(r3) : "r"(a));
}
__device__ __forceinline__ void mma16816(float* c, const uint32_t* a, const uint32_t* b) {
    asm volatile("mma.sync.aligned.m16n8k16.row.col.f32.f16.f16.f32 "
                 "{%0,%1,%2,%3}, {%4,%5,%6,%7}, {%8,%9}, {%0,%1,%2,%3};"
                 : "+f"(c[0]), "+f"(c[1]), "+f"(c[2]), "+f"(c[3])
                 : "r"(a[0]), "r"(a[1]), "r"(a[2]), "r"(a[3]), "r"(b[0]), "r"(b[1]));
}

__device__ __forceinline__ void hilo2(float v0, float v1, __half2& hp, __half2& lp) {
    __half h0 = __float2half_rn(v0), h1 = __float2half_rn(v1);
    hp.x = h0; hp.y = h1;
    lp.x = __float2half_rn(v0 - __half2float(h0));
    lp.y = __float2half_rn(v1 - __half2float(h1));
}
__device__ __forceinline__ uint32_t pk_hi(float x, float y) {
    __half2 t; t.x = __float2half_rn(x); t.y = __float2half_rn(y);
    return *(uint32_t*)&t;
}
__device__ __forceinline__ uint32_t pk_lo(float x, float y, uint32_t hi) {
    __half2 h = *(__half2*)&hi;
    __half2 t;
    t.x = __float2half_rn(x - __half2float(h.x));
    t.y = __float2half_rn(y - __half2float(h.y));
    return *(uint32_t*)&t;
}

// ============================ unified GEMM (HMMA fp16, 3-stage) =============
// mode 0: QK merged (N=1536, both outputs single fp16; q gets *0.125)
// mode 1: final (fp32)   mode 2: V (single fp16)
__global__ __launch_bounds__(256, 2) void hgemm(
    const __half* __restrict__ Ag, const __half* __restrict__ Bg,
    const float* __restrict__ b0p, const float* __restrict__ b1p,
    void* __restrict__ o0, void* __restrict__ o1,
    int K, int ldB, int mode)
{
    constexpr int BM = 128, BN = 128, BK = 64;
    constexpr int MI = 4, NI = 4;
    constexpr int SA = BM * BK * 2, SB = BN * BK * 2, STG = SA + SB;  // 32KB/stage

    extern __shared__ char smem[];
    const uint32_t sbase = smem_u32(smem);
    const int tid = threadIdx.x, l = tid & 31, wid = tid >> 5;
    const int row0 = blockIdx.y * BM, col0 = blockIdx.x * BN;
    const int wm0 = (wid / 4) * 64, wn0 = (wid % 4) * 32;

    auto issue = [&](int ch, int st) {
        const int k0 = ch * BK;
        const uint32_t sA = sbase + st * STG;
        const uint32_t sB = sA + SA;
        for (int i = tid; i < BM * 8; i += 256) {
            int r = i >> 3, v = i & 7;
            cp16(sA + SWZ(r * 128 + v * 16), Ag + (size_t)(row0 + r) * KP2 + k0 + v * 8);
        }
        for (int i = tid; i < BN * 8; i += 256) {
            int r = i >> 3, v = i & 7;
            cp16(sB + SWZ(r * 128 + v * 16), Bg + (size_t)(col0 + r) * ldB + k0 + v * 8);
        }
    };

    float c[MI][NI][4] = {};
    const int nch = K / BK;
    issue(0, 0); CP_COMMIT();
    if (nch > 1) { issue(1, 1); CP_COMMIT(); }

    for (int ch = 0; ch < nch; ch++) {
        if (ch + 1 < nch) { CP_WAIT(1); } else { CP_WAIT(0); }
        __syncthreads();
        if (ch + 2 < nch) { issue(ch + 2, (ch + 2) % 3); CP_COMMIT(); }

        const uint32_t sA = sbase + (ch % 3) * STG;
        const uint32_t sB = sA + SA;

        #pragma unroll
        for (int ks = 0; ks < 4; ks++) {
            uint32_t af[MI][4];
            #pragma unroll
            for (int im = 0; im < MI; im++)
                ldsm4(af[im][0], af[im][1], af[im][2], af[im][3],
                      sA + SWZ((wm0 + im * 16 + (l & 15)) * 128 + ks * 32 + ((l >> 4) & 1) * 16));
            uint32_t bf[NI][2];
            #pragma unroll
            for (int i2 = 0; i2 < NI / 2; i2++) {
                int g = l >> 3;
                uint32_t r0, r1, r2, r3;
                ldsm4(r0, r1, r2, r3,
                      sB + SWZ((wn0 + i2 * 16 + ((g >> 1) & 1) * 8 + (l & 7)) * 128 + ks * 32 + (g & 1) * 16));
                bf[2 * i2][0] = r0; bf[2 * i2][1] = r1;
                bf[2 * i2 + 1][0] = r2; bf[2 * i2 + 1][1] = r3;
            }
            #pragma unroll
            for (int im = 0; im < MI; im++)
                #pragma unroll
                for (int in = 0; in < NI; in++)
                    mma16816(c[im][in], af[im], bf[in]);
        }
    }
    __syncthreads();

    const int sel = (mode == 0) ? col0 / DMODEL : mode + 1;   // 0 q, 1 k, 2 final, 3 V
    const int dcol0 = col0 % DMODEL;
    const float* bs = (sel == 1) ? b1p : b0p;

    #pragma unroll
    for (int im = 0; im < MI; im++)
        #pragma unroll
        for (int in = 0; in < NI; in++)
            #pragma unroll
            for (int half_ = 0; half_ < 2; half_++) {
                int m = row0 + wm0 + im * 16 + (l >> 2) + half_ * 8;
                int nd = dcol0 + wn0 + in * 8 + (l & 3) * 2;
                float v0 = c[im][in][2 * half_] * WSCI + bs[nd];
                float v1 = c[im][in][2 * half_ + 1] * WSCI + bs[nd + 1];
                if (sel == 2) {
                    float2 w; w.x = v0; w.y = v1;
                    *(float2*)((float*)o0 + (size_t)m * DMODEL + nd) = w;
                    continue;
                }
                if (sel == 0) { v0 *= 0.125f; v1 *= 0.125f; }
                int b = m >> 10, s = m & 1023, h = nd >> 6, dd = nd & 63;
                __half2 t; t.x = __float2half_rn(v0); t.y = __float2half_rn(v1);
                __half* ob = (sel == 1) ? (__half*)o1 : (__half*)o0;
                *(__half2*)(ob + ((size_t)(b * NHEAD + h) * SSEQ + s) * DHEAD + dd) = t;
            }
}

// ============================ fused attention ===============================
// CTA: (bh, 64 q-rows). 8 warps: rg=w>>1 rows [rg*16,+16), ch=w&1 kv half.
// S 1-term; PV 2-term (P hi/lo); p~ staged fp16; normalized attn written in-kernel.
#define SQ_OFF  0                         // 8KB q
#define SK_OFF  8192                      // 2 x 16KB K buffers
#define SV_OFF  40960                     // 16KB V
#define SRED_O  8192                      // reuse K region post-loop (16KB)
#define SRED_L  (8192 + 16384)
#define SLINV   40960                     // reuse V region post-loop (64 floats)
#define FSM_BYTES 57344

__global__ __launch_bounds__(256, 2) void fused_attn(
    const __half* __restrict__ Qp, const __half* __restrict__ Kp,
    const __half* __restrict__ Vp,
    __half* __restrict__ pt, float* __restrict__ attn,
    __half* __restrict__ cP)
{
    extern __shared__ char smem[];
    const uint32_t sbase = smem_u32(smem);
    const int tid = threadIdx.x, l = tid & 31, wid = tid >> 5;
    const int rg = wid >> 1, ch = wid & 1;
    const int bh = blockIdx.y, q0 = blockIdx.x * 64;
    const int wm0 = rg * 16;

    const __half* Qb = Qp + (size_t)bh * SSEQ * DHEAD;
    const __half* Kb = Kp + (size_t)bh * SSEQ * DHEAD;
    const __half* Vb = Vp + (size_t)bh * SSEQ * DHEAD;

    auto issueK = [&](int t, int st) {
        const uint32_t kb = sbase + SK_OFF + st * 16384;
        for (int i = tid; i < 1024; i += 256) {
            int r = i >> 3, v = i & 7;
            cp16(kb + SWZ(r * 128 + v * 16), Kb + (size_t)(t * 128 + r) * DHEAD + v * 8);
        }
    };
    auto issueV = [&](int t) {
        for (int i = tid; i < 1024; i += 256) {
            int r = i >> 3, v = i & 7;
            cp16(sbase + SV_OFF + SWZ(r * 128 + v * 16),
                 Vb + (size_t)(t * 128 + r) * DHEAD + v * 8);
        }
    };

    // preload Q (64 rows x 64 dims, single fp16)
    for (int i = tid; i < 512; i += 256) {
        int r = i >> 3, v = i & 7;
        cp16(sbase + SQ_OFF + SWZ(r * 128 + v * 16), Qb + (size_t)(q0 + r) * DHEAD + v * 8);
    }
    issueK(0, 0);
    CP_COMMIT();

    float c_o[8][4] = {};
    float lsum0 = 0.f, lsum1 = 0.f;

    for (int t = 0; t < 8; t++) {
        CP_WAIT(0);
        __syncthreads();
        issueV(t); CP_COMMIT();
        if (t < 7) { issueK(t + 1, (t + 1) & 1); CP_COMMIT(); }

        // ---- S: 16 q-rows x 64 kv (this warp's half), 1-term ----
        float cs[8][4] = {};
        const uint32_t kb = sbase + SK_OFF + (t & 1) * 16384;
        const uint32_t sQ = sbase + SQ_OFF;
        #pragma unroll
        for (int ks = 0; ks < 4; ks++) {
            uint32_t af[4];
            ldsm4(af[0], af[1], af[2], af[3],
                  sQ + SWZ((wm0 + (l & 15)) * 128 + ks * 32 + ((l >> 4) & 1) * 16));
            #pragma unroll
            for (int i2 = 0; i2 < 4; i2++) {
                int g = l >> 3;
                uint32_t r0, r1, r2, r3;
                ldsm4(r0, r1, r2, r3,
                      kb + SWZ((ch * 64 + i2 * 16 + ((g >> 1) & 1) * 8 + (l & 7)) * 128
                               + ks * 32 + (g & 1) * 16));
                uint32_t b0[2] = {r0, r1}, b1[2] = {r2, r3};
                mma16816(cs[2 * i2],     af, b0);
                mma16816(cs[2 * i2 + 1], af, b1);
            }
        }

        // ---- exp + row-sum + fp16 p~ write ----
        #pragma unroll
        for (int in = 0; in < 8; in++) {
            cs[in][0] = __expf(cs[in][0]);
            cs[in][1] = __expf(cs[in][1]);
            cs[in][2] = __expf(cs[in][2]);
            cs[in][3] = __expf(cs[in][3]);
            lsum0 += cs[in][0] + cs[in][1];
            lsum1 += cs[in][2] + cs[in][3];
        }
        {
            __half* p0 = pt + ((size_t)bh << 20) + (size_t)(q0 + wm0 + (l >> 2)) * SSEQ
                         + t * 128 + ch * 64 + 2 * (l & 3);
            __half* p1 = p0 + 8 * SSEQ;
            #pragma unroll
            for (int in = 0; in < 8; in++) {
                uint32_t w0 = pk_hi(cs[in][0], cs[in][1]);
                uint32_t w1 = pk_hi(cs[in][2], cs[in][3]);
                *(uint32_t*)(p0 + in * 8) = w0;
                *(uint32_t*)(p1 + in * 8) = w1;
            }
        }

        if (t < 7) CP_WAIT(1); else CP_WAIT(0);
        __syncthreads();

        // ---- partial O += P~ @ V over warp's 64 kv (2-term) ----
        const uint32_t sVh = sbase + SV_OFF;
        #pragma unroll
        for (int kk = 0; kk < 4; kk++) {
            uint32_t ah[4], al[4];
            ah[0] = pk_hi(cs[2*kk][0],   cs[2*kk][1]);   al[0] = pk_lo(cs[2*kk][0],   cs[2*kk][1],   ah[0]);
            ah[1] = pk_hi(cs[2*kk][2],   cs[2*kk][3]);   al[1] = pk_lo(cs[2*kk][2],   cs[2*kk][3],   ah[1]);
            ah[2] = pk_hi(cs[2*kk+1][0], cs[2*kk+1][1]); al[2] = pk_lo(cs[2*kk+1][0], cs[2*kk+1][1], ah[2]);
            ah[3] = pk_hi(cs[2*kk+1][2], cs[2*kk+1][3]); al[3] = pk_lo(cs[2*kk+1][2], cs[2*kk+1][3], ah[3]);
            uint32_t vrow = (uint32_t)(ch * 64 + kk * 16 + ((l >> 3) & 1) * 8 + (l & 7)) * 128
                          + ((uint32_t)(l >> 4)) * 16;
            #pragma unroll
            for (int in = 0; in < 8; in += 2) {
                uint32_t h0, h1, h2, h3;
                ldsm4t(h0, h1, h2, h3, sVh + SWZ(vrow + in * 16));
                uint32_t bh2[2] = {h0, h1}, bh3[2] = {h2, h3};
                mma16816(c_o[in],     ah, bh2);
                mma16816(c_o[in],     al, bh2);
                mma16816(c_o[in + 1], ah, bh3);
                mma16816(c_o[in + 1], al, bh3);
            }
        }
        __syncthreads();
    }

    // ---- pair reduction (ch=1 -> smem -> ch=0), then finalize ----
    lsum0 += __shfl_xor_sync(0xffffffffu, lsum0, 1);
    lsum0 += __shfl_xor_sync(0xffffffffu, lsum0, 2);
    lsum1 += __shfl_xor_sync(0xffffffffu, lsum1, 1);
    lsum1 += __shfl_xor_sync(0xffffffffu, lsum1, 2);

    float* redO = (float*)(smem + SRED_O);             // 4 rg x 16 x 64 = 16KB
    float* redL = (float*)(smem + SRED_L);             // 4 rg x 16
    float* linv = (float*)(smem + SLINV);              // 64 floats
    __syncthreads();
    if (ch == 1) {
        #pragma unroll
        for (int in = 0; in < 8; in++) {
            int cidx = in * 8 + 2 * (l & 3);
            int r = l >> 2;
            redO[rg * 1024 + r * 64 + cidx]           = c_o[in][0];
            redO[rg * 1024 + r * 64 + cidx + 1]       = c_o[in][1];
            redO[rg * 1024 + (r + 8) * 64 + cidx]     = c_o[in][2];
            redO[rg * 1024 + (r + 8) * 64 + cidx + 1] = c_o[in][3];
        }
        if ((l & 3) == 0) {
            redL[rg * 16 + (l >> 2)]     = lsum0;
            redL[rg * 16 + (l >> 2) + 8] = lsum1;
        }
    }
    __syncthreads();
    if (ch == 0) {
        lsum0 += redL[rg * 16 + (l >> 2)];
        lsum1 += redL[rg * 16 + (l >> 2) + 8];
        const float inv0 = 1.0f / lsum0, inv1 = 1.0f / lsum1;
        if ((l & 3) == 0) {
            linv[wm0 + (l >> 2)]     = inv0;
            linv[wm0 + (l >> 2) + 8] = inv1;
        }

        const int r0g = q0 + wm0 + (l >> 2);
        const int b = bh / NHEAD, h = bh % NHEAD;
        const size_t gm0 = (size_t)(b * SSEQ + r0g) * KP2;
        const size_t gm1 = gm0 + (size_t)8 * KP2;
        #pragma unroll
        for (int in = 0; in < 8; in++) {
            int cidx = in * 8 + 2 * (l & 3);
            int r = l >> 2;
            float o0 = (c_o[in][0] + redO[rg * 1024 + r * 64 + cidx])           * inv0;
            float o1 = (c_o[in][1] + redO[rg * 1024 + r * 64 + cidx + 1])       * inv0;
            float o2 = (c_o[in][2] + redO[rg * 1024 + (r + 8) * 64 + cidx])     * inv1;
            float o3 = (c_o[in][3] + redO[rg * 1024 + (r + 8) * 64 + cidx + 1]) * inv1;
            int d = h * DHEAD + cidx;
            __half2 hp, lp;
            hilo2(o0, o1, hp, lp);
            *(__half2*)(cP + gm0 + d)          = hp;
            *(__half2*)(cP + gm0 + d + DMODEL) = lp;
            hilo2(o2, o3, hp, lp);
            *(__half2*)(cP + gm1 + d)          = hp;
            *(__half2*)(cP + gm1 + d + DMODEL) = lp;
        }
    }
    __syncthreads();

    // ---- normalize + emit fp32 attn (p~ re-read hits L2) ----
    {
        const __half2* ps = (const __half2*)(pt + ((size_t)bh << 20) + (size_t)q0 * SSEQ);
        float4* ad = (float4*)(attn + ((size_t)bh << 20) + (size_t)q0 * SSEQ);
        for (int idx = tid; idx < 64 * 256; idx += 256) {
            int r = idx >> 8, cc = idx & 255;        // cc: float4 index within row
            float iv = linv[r];
            __half2 a = ps[r * 512 + 2 * cc];
            __half2 b = ps[r * 512 + 2 * cc + 1];
            float4 v;
            v.x = __half2float(a.x) * iv;
            v.y = __half2float(a.y) * iv;
            v.z = __half2float(b.x) * iv;
            v.w = __half2float(b.y) * iv;
            ad[r * 256 + cc] = v;
        }
    }
}

// ============================ prep kernels ==================================
__global__ __launch_bounds__(256) void pack_a(const float* __restrict__ in, __half* __restrict__ o)
{
    size_t i = (size_t)blockIdx.x * 256 + threadIdx.x;
    size_t m = i / (DMODEL / 2);
    int kk = (int)(i % (DMODEL / 2)) * 2;
    if (m >= MROWS) return;
    float2 v = *(const float2*)(in + m * DMODEL + kk);
    __half2 hp, lp;
    hilo2(v.x, v.y, hp, lp);
    size_t base = m * KP2 + kk;
    *(__half2*)(o + base)          = hp;
    *(__half2*)(o + base + DMODEL) = lp;
}

__global__ void pack_w_all(const float* __restrict__ Wq, const float* __restrict__ Wk,
                           const float* __restrict__ Wv, const float* __restrict__ Wo,
                           __half* __restrict__ wqk, __half* __restrict__ wvh,
                           __half* __restrict__ wo)
{
    __shared__ float t[32][33];
    const int z = blockIdx.z;
    const float* W = (z == 0) ? Wq : (z == 1) ? Wk : (z == 2) ? Wv : Wo;
    int n0 = blockIdx.x * 32, k0 = blockIdx.y * 32;
    int x = threadIdx.x, y = threadIdx.y;
    #pragma unroll
    for (int j = 0; j < 32; j += 8)
        t[y + j][x] = W[(size_t)(k0 + y + j) * DMODEL + n0 + x] * WSC;
    __syncthreads();
    if (z == 2) {
        #pragma unroll
        for (int j = 0; j < 32; j += 8)
            wvh[(size_t)(n0 + y + j) * DMODEL + k0 + x] = __float2half_rn(t[x][y + j]);
        return;
    }
    __half* o = (z == 3) ? wo : wqk + (size_t)z * DMODEL * KP2;
    #pragma unroll
    for (int j = 0; j < 32; j += 8) {
        __half h = __float2half_rn(t[x][y + j]);
        size_t base = (size_t)(n0 + y + j) * KP2 + k0 + x;
        o[base] = h;
        o[base + DMODEL] = h;
    }
}

// ============================ host launcher =================================
extern "C" void kernel_launch(void* const* d_in, const int* in_sizes, int n_in,
                              void* d_out, int out_size)
{
    (void)in_sizes; (void)n_in;
    const float* x  = (const float*)d_in[0];
    const float* Wq = (const float*)d_in[1];
    const float* bq = (const float*)d_in[2];
    const float* Wk = (const float*)d_in[3];
    const float* bk = (const float*)d_in[4];
    const float* Wv = (const float*)d_in[5];
    const float* bv = (const float*)d_in[6];
    const float* Wo = (const float*)d_in[7];
    const float* bo = (const float*)d_in[8];
    float* out = (float*)d_out;

    float* gattn;
    __half *pt, *xP, *wqkP, *wvh, *woP, *qP, *kP, *vP, *cP;
    cudaGetSymbolAddress((void**)&gattn, g_attn);
    cudaGetSymbolAddress((void**)&pt,   g_pt);
    cudaGetSymbolAddress((void**)&xP,   g_xP);
    cudaGetSymbolAddress((void**)&wqkP, g_wqkP);
    cudaGetSymbolAddress((void**)&wvh,  g_wvh);
    cudaGetSymbolAddress((void**)&woP,  g_woP);
    cudaGetSymbolAddress((void**)&qP,   g_q);
    cudaGetSymbolAddress((void**)&kP,   g_k);
    cudaGetSymbolAddress((void**)&vP,   g_v);
    cudaGetSymbolAddress((void**)&cP,   g_cP);

    const size_t final_elems = (size_t)MROWS * DMODEL;
    float* attn = ((size_t)out_size > final_elems) ? (out + final_elems) : gattn;

    constexpr int SM_GEMM = 3 * (128 * 64 * 2 + 128 * 64 * 2);   // 96KB, 3-stage
    cudaFuncSetAttribute(hgemm,      cudaFuncAttributeMaxDynamicSharedMemorySize, SM_GEMM);
    cudaFuncSetAttribute(fused_attn, cudaFuncAttributeMaxDynamicSharedMemorySize, FSM_BYTES);

    // pack
    {
        size_t pairs = (size_t)MROWS * (DMODEL / 2);
        pack_a<<<(unsigned)((pairs + 255) / 256), 256>>>(x, xP);
        dim3 tb(32, 8), tg(DMODEL / 32, DMODEL / 32, 4);
        pack_w_all<<<tg, tb>>>(Wq, Wk, Wv, Wo, wqkP, wvh, woP);
    }

    // QK merged projection (N = 1536, K = 1536, 2-term; outputs single fp16)
    dim3 gqk(2 * DMODEL / 128, MROWS / 128);      // (12, 64)
    hgemm<<<gqk, 256, SM_GEMM>>>(xP, wqkP, bq, bk, qP, kP, KP2, KP2, 0);

    // V projection (N = 768, K = 768, 1-term)
    dim3 gv(DMODEL / 128, MROWS / 128);           // (6, 64)
    hgemm<<<gv, 256, SM_GEMM>>>(xP, wvh, bv, nullptr, vP, nullptr, DMODEL, DMODEL, 2);

    // fused scores + softmax + AV + in-kernel attn normalization
    dim3 gf(SSEQ / 64, NBH);                      // (16, 96)
    fused_attn<<<gf, 256, FSM_BYTES>>>(qP, kP, vP, pt, attn, cP);

    // out = ctx @ Wo + bo (K = 1536, 2-term)
    hgemm<<<gv, 256, SM_GEMM>>>(cP, woP, bo, nullptr, out, nullptr, KP2, KP2, 1);
}

// round 11
// speedup vs baseline: 4.6211x; 1.1099x over previous
#include <cuda_runtime.h>
#include <cuda_fp16.h>
#include <cstdint>

#define BBATCH 8
#define SSEQ   1024
#define DMODEL 768
#define NHEAD  12
#define DHEAD  64
#define MROWS  (BBATCH*SSEQ)     // 8192
#define NBH    (BBATCH*NHEAD)    // 96
#define KP2    1536              // [hi|lo] packed K (ctx / Wo)
#define WSC    32.0f
#define WSCI   0.03125f

// ---------------- scratch (device globals; no allocations allowed) ----------
__device__ float g_attn[(size_t)NBH*SSEQ*SSEQ];          // fallback attn (fp32)
__device__ __half g_pt  [(size_t)NBH*SSEQ*SSEQ];         // unnormalized exp(S), fp16
__device__ __half g_xh  [(size_t)MROWS*DMODEL];          // x hi
__device__ __half g_wqkvh[(size_t)3*DMODEL*DMODEL];      // Wq|Wk|Wv rows, hi (x32)
__device__ __half g_woP [(size_t)DMODEL*KP2];            // Wo [wh|wh]
__device__ __half g_q  [(size_t)NBH*SSEQ*DHEAD];         // q*0.125 single fp16
__device__ __half g_k  [(size_t)NBH*SSEQ*DHEAD];         // k single fp16
__device__ __half g_v  [(size_t)NBH*SSEQ*DHEAD];         // V single fp16
__device__ __half g_cP [(size_t)MROWS*KP2];              // ctx [hi|lo]

// ============================ PTX helpers ===================================
__device__ __forceinline__ uint32_t smem_u32(const void* p) {
    uint32_t a;
    asm("{ .reg .u64 t; cvta.to.shared.u64 t, %1; cvt.u32.u64 %0, t; }" : "=r"(a) : "l"(p));
    return a;
}
#define SWZ(o) ((uint32_t)(o) ^ ((((uint32_t)(o)) >> 3) & 0x70))

__device__ __forceinline__ void cp16(uint32_t s, const void* g) {
    asm volatile("cp.async.cg.shared.global [%0], [%1], 16;" :: "r"(s), "l"(g));
}
#define CP_COMMIT() asm volatile("cp.async.commit_group;")
#define CP_WAIT(n)  asm volatile("cp.async.wait_group %0;" :: "n"(n))

__device__ __forceinline__ void ldsm4(uint32_t& r0, uint32_t& r1, uint32_t& r2, uint32_t& r3, uint32_t a) {
    asm volatile("ldmatrix.sync.aligned.m8n8.x4.shared.b16 {%0,%1,%2,%3}, [%4];"
                 : "=r"(r0), "=r"(r1), "=r"(r2), "=r"(r3) : "r"(a));
}
__device__ __forceinline__ void ldsm4t(uint32_t& r0, uint32_t& r1, uint32_t& r2, uint32_t& r3, uint32_t a) {
    asm volatile("ldmatrix.sync.aligned.m8n8.x4.trans.shared.b16 {%0,%1,%2,%3}, [%4];"
                 : "=r"(r0), "=r"(r1), "=r"(r2), "=r"(r3) : "r"(a));
}
__device__ __forceinline__ void mma16816(float* c, const uint32_t* a, const uint32_t* b) {
    asm volatile("mma.sync.aligned.m16n8k16.row.col.f32.f16.f16.f32 "
                 "{%0,%1,%2,%3}, {%4,%5,%6,%7}, {%8,%9}, {%0,%1,%2,%3};"
                 : "+f"(c[0]), "+f"(c[1]), "+f"(c[2]), "+f"(c[3])
                 : "r"(a[0]), "r"(a[1]), "r"(a[2]), "r"(a[3]), "r"(b[0]), "r"(b[1]));
}

__device__ __forceinline__ void hilo2(float v0, float v1, __half2& hp, __half2& lp) {
    __half h0 = __float2half_rn(v0), h1 = __float2half_rn(v1);
    hp.x = h0; hp.y = h1;
    lp.x = __float2half_rn(v0 - __half2float(h0));
    lp.y = __float2half_rn(v1 - __half2float(h1));
}
__device__ __forceinline__ uint32_t pk_hi(float x, float y) {
    __half2 t; t.x = __float2half_rn(x); t.y = __float2half_rn(y);
    return *(uint32_t*)&t;
}
__device__ __forceinline__ uint32_t pk_lo(float x, float y, uint32_t hi) {
    __half2 h = *(__half2*)&hi;
    __half2 t;
    t.x = __float2half_rn(x - __half2float(h.x));
    t.y = __float2half_rn(y - __half2float(h.y));
    return *(uint32_t*)&t;
}

// ============================ unified GEMM (HMMA fp16, 3-stage) =============
// mode 0: QKV merged (N=2304, K=768, 1-term; sel 0=q(*0.125)/1=k/2=v, single fp16)
// mode 1: final (N=768, K=1536, 2-term ctx; fp32 out + bias)
__global__ __launch_bounds__(256, 2) void hgemm(
    const __half* __restrict__ Ag, const __half* __restrict__ Bg,
    const float* __restrict__ b0p, const float* __restrict__ b1p, const float* __restrict__ b2p,
    void* __restrict__ o0, void* __restrict__ o1, void* __restrict__ o2,
    int K, int ldA, int ldB, int mode)
{
    constexpr int BM = 128, BN = 128, BK = 64;
    constexpr int MI = 4, NI = 4;
    constexpr int SA = BM * BK * 2, SB = BN * BK * 2, STG = SA + SB;  // 32KB/stage

    extern __shared__ char smem[];
    const uint32_t sbase = smem_u32(smem);
    const int tid = threadIdx.x, l = tid & 31, wid = tid >> 5;
    const int row0 = blockIdx.y * BM, col0 = blockIdx.x * BN;
    const int wm0 = (wid / 4) * 64, wn0 = (wid % 4) * 32;

    auto issue = [&](int ch, int st) {
        const int k0 = ch * BK;
        const uint32_t sA = sbase + st * STG;
        const uint32_t sB = sA + SA;
        for (int i = tid; i < BM * 8; i += 256) {
            int r = i >> 3, v = i & 7;
            cp16(sA + SWZ(r * 128 + v * 16), Ag + (size_t)(row0 + r) * ldA + k0 + v * 8);
        }
        for (int i = tid; i < BN * 8; i += 256) {
            int r = i >> 3, v = i & 7;
            cp16(sB + SWZ(r * 128 + v * 16), Bg + (size_t)(col0 + r) * ldB + k0 + v * 8);
        }
    };

    float c[MI][NI][4] = {};
    const int nch = K / BK;
    issue(0, 0); CP_COMMIT();
    if (nch > 1) { issue(1, 1); CP_COMMIT(); }

    for (int ch = 0; ch < nch; ch++) {
        if (ch + 1 < nch) { CP_WAIT(1); } else { CP_WAIT(0); }
        __syncthreads();
        if (ch + 2 < nch) { issue(ch + 2, (ch + 2) % 3); CP_COMMIT(); }

        const uint32_t sA = sbase + (ch % 3) * STG;
        const uint32_t sB = sA + SA;

        #pragma unroll
        for (int ks = 0; ks < 4; ks++) {
            uint32_t af[MI][4];
            #pragma unroll
            for (int im = 0; im < MI; im++)
                ldsm4(af[im][0], af[im][1], af[im][2], af[im][3],
                      sA + SWZ((wm0 + im * 16 + (l & 15)) * 128 + ks * 32 + ((l >> 4) & 1) * 16));
            uint32_t bf[NI][2];
            #pragma unroll
            for (int i2 = 0; i2 < NI / 2; i2++) {
                int g = l >> 3;
                uint32_t r0, r1, r2, r3;
                ldsm4(r0, r1, r2, r3,
                      sB + SWZ((wn0 + i2 * 16 + ((g >> 1) & 1) * 8 + (l & 7)) * 128 + ks * 32 + (g & 1) * 16));
                bf[2 * i2][0] = r0; bf[2 * i2][1] = r1;
                bf[2 * i2 + 1][0] = r2; bf[2 * i2 + 1][1] = r3;
            }
            #pragma unroll
            for (int im = 0; im < MI; im++)
                #pragma unroll
                for (int in = 0; in < NI; in++)
                    mma16816(c[im][in], af[im], bf[in]);
        }
    }
    __syncthreads();

    const int sel = (mode == 0) ? col0 / DMODEL : 3;          // 0 q, 1 k, 2 v, 3 final
    const int dcol0 = col0 % DMODEL;
    const float* bs = (sel == 1) ? b1p : (sel == 2) ? b2p : b0p;
    const float qsc = (sel == 0) ? 0.125f : 1.0f;

    #pragma unroll
    for (int im = 0; im < MI; im++)
        #pragma unroll
        for (int in = 0; in < NI; in++)
            #pragma unroll
            for (int half_ = 0; half_ < 2; half_++) {
                int m = row0 + wm0 + im * 16 + (l >> 2) + half_ * 8;
                int nd = dcol0 + wn0 + in * 8 + (l & 3) * 2;
                float v0 = c[im][in][2 * half_] * WSCI + bs[nd];
                float v1 = c[im][in][2 * half_ + 1] * WSCI + bs[nd + 1];
                if (sel == 3) {
                    float2 w; w.x = v0; w.y = v1;
                    *(float2*)((float*)o0 + (size_t)m * DMODEL + nd) = w;
                    continue;
                }
                v0 *= qsc; v1 *= qsc;
                int b = m >> 10, s = m & 1023, h = nd >> 6, dd = nd & 63;
                __half2 t; t.x = __float2half_rn(v0); t.y = __float2half_rn(v1);
                __half* ob = (sel == 0) ? (__half*)o0 : (sel == 1) ? (__half*)o1 : (__half*)o2;
                *(__half2*)(ob + ((size_t)(b * NHEAD + h) * SSEQ + s) * DHEAD + dd) = t;
            }
}

// ============================ fused attention ===============================
// CTA: (bh, 64 q-rows). 8 warps: rg=w>>1 rows [rg*16,+16), ch=w&1 kv half.
// S 1-term; PV 2-term (P hi/lo); p~/attn written only when wattn != 0.
#define SQ_OFF  0                         // 8KB q
#define SK_OFF  8192                      // 2 x 16KB K buffers
#define SV_OFF  40960                     // 16KB V
#define SRED_O  8192                      // reuse K region post-loop (16KB)
#define SRED_L  (8192 + 16384)
#define SLINV   40960                     // reuse V region post-loop
#define FSM_BYTES 57344

__global__ __launch_bounds__(256, 2) void fused_attn(
    const __half* __restrict__ Qp, const __half* __restrict__ Kp,
    const __half* __restrict__ Vp,
    __half* __restrict__ pt, float* __restrict__ attn,
    __half* __restrict__ cP, int wattn)
{
    extern __shared__ char smem[];
    const uint32_t sbase = smem_u32(smem);
    const int tid = threadIdx.x, l = tid & 31, wid = tid >> 5;
    const int rg = wid >> 1, ch = wid & 1;
    const int bh = blockIdx.y, q0 = blockIdx.x * 64;
    const int wm0 = rg * 16;

    const __half* Qb = Qp + (size_t)bh * SSEQ * DHEAD;
    const __half* Kb = Kp + (size_t)bh * SSEQ * DHEAD;
    const __half* Vb = Vp + (size_t)bh * SSEQ * DHEAD;

    auto issueK = [&](int t, int st) {
        const uint32_t kb = sbase + SK_OFF + st * 16384;
        for (int i = tid; i < 1024; i += 256) {
            int r = i >> 3, v = i & 7;
            cp16(kb + SWZ(r * 128 + v * 16), Kb + (size_t)(t * 128 + r) * DHEAD + v * 8);
        }
    };
    auto issueV = [&](int t) {
        for (int i = tid; i < 1024; i += 256) {
            int r = i >> 3, v = i & 7;
            cp16(sbase + SV_OFF + SWZ(r * 128 + v * 16),
                 Vb + (size_t)(t * 128 + r) * DHEAD + v * 8);
        }
    };

    // preload Q (64 rows x 64 dims, single fp16)
    for (int i = tid; i < 512; i += 256) {
        int r = i >> 3, v = i & 7;
        cp16(sbase + SQ_OFF + SWZ(r * 128 + v * 16), Qb + (size_t)(q0 + r) * DHEAD + v * 8);
    }
    issueK(0, 0);
    CP_COMMIT();

    float c_o[8][4] = {};
    float lsum0 = 0.f, lsum1 = 0.f;

    for (int t = 0; t < 8; t++) {
        CP_WAIT(0);
        __syncthreads();
        issueV(t); CP_COMMIT();
        if (t < 7) { issueK(t + 1, (t + 1) & 1); CP_COMMIT(); }

        // ---- S: 16 q-rows x 64 kv (this warp's half), 1-term ----
        float cs[8][4] = {};
        const uint32_t kb = sbase + SK_OFF + (t & 1) * 16384;
        const uint32_t sQ = sbase + SQ_OFF;
        #pragma unroll
        for (int ks = 0; ks < 4; ks++) {
            uint32_t af[4];
            ldsm4(af[0], af[1], af[2], af[3],
                  sQ + SWZ((wm0 + (l & 15)) * 128 + ks * 32 + ((l >> 4) & 1) * 16));
            #pragma unroll
            for (int i2 = 0; i2 < 4; i2++) {
                int g = l >> 3;
                uint32_t r0, r1, r2, r3;
                ldsm4(r0, r1, r2, r3,
                      kb + SWZ((ch * 64 + i2 * 16 + ((g >> 1) & 1) * 8 + (l & 7)) * 128
                               + ks * 32 + (g & 1) * 16));
                uint32_t b0[2] = {r0, r1}, b1[2] = {r2, r3};
                mma16816(cs[2 * i2],     af, b0);
                mma16816(cs[2 * i2 + 1], af, b1);
            }
        }

        // ---- exp + row-sum (+ optional fp16 p~ write) ----
        #pragma unroll
        for (int in = 0; in < 8; in++) {
            cs[in][0] = __expf(cs[in][0]);
            cs[in][1] = __expf(cs[in][1]);
            cs[in][2] = __expf(cs[in][2]);
            cs[in][3] = __expf(cs[in][3]);
            lsum0 += cs[in][0] + cs[in][1];
            lsum1 += cs[in][2] + cs[in][3];
        }
        if (wattn) {
            __half* p0 = pt + ((size_t)bh << 20) + (size_t)(q0 + wm0 + (l >> 2)) * SSEQ
                         + t * 128 + ch * 64 + 2 * (l & 3);
            __half* p1 = p0 + 8 * SSEQ;
            #pragma unroll
            for (int in = 0; in < 8; in++) {
                uint32_t w0 = pk_hi(cs[in][0], cs[in][1]);
                uint32_t w1 = pk_hi(cs[in][2], cs[in][3]);
                *(uint32_t*)(p0 + in * 8) = w0;
                *(uint32_t*)(p1 + in * 8) = w1;
            }
        }

        if (t < 7) CP_WAIT(1); else CP_WAIT(0);
        __syncthreads();

        // ---- partial O += P~ @ V over warp's 64 kv (2-term) ----
        const uint32_t sVh = sbase + SV_OFF;
        #pragma unroll
        for (int kk = 0; kk < 4; kk++) {
            uint32_t ah[4], al[4];
            ah[0] = pk_hi(cs[2*kk][0],   cs[2*kk][1]);   al[0] = pk_lo(cs[2*kk][0],   cs[2*kk][1],   ah[0]);
            ah[1] = pk_hi(cs[2*kk][2],   cs[2*kk][3]);   al[1] = pk_lo(cs[2*kk][2],   cs[2*kk][3],   ah[1]);
            ah[2] = pk_hi(cs[2*kk+1][0], cs[2*kk+1][1]); al[2] = pk_lo(cs[2*kk+1][0], cs[2*kk+1][1], ah[2]);
            ah[3] = pk_hi(cs[2*kk+1][2], cs[2*kk+1][3]); al[3] = pk_lo(cs[2*kk+1][2], cs[2*kk+1][3], ah[3]);
            uint32_t vrow = (uint32_t)(ch * 64 + kk * 16 + ((l >> 3) & 1) * 8 + (l & 7)) * 128
                          + ((uint32_t)(l >> 4)) * 16;
            #pragma unroll
            for (int in = 0; in < 8; in += 2) {
                uint32_t h0, h1, h2, h3;
                ldsm4t(h0, h1, h2, h3, sVh + SWZ(vrow + in * 16));
                uint32_t bh2[2] = {h0, h1}, bh3[2] = {h2, h3};
                mma16816(c_o[in],     ah, bh2);
                mma16816(c_o[in],     al, bh2);
                mma16816(c_o[in + 1], ah, bh3);
                mma16816(c_o[in + 1], al, bh3);
            }
        }
        __syncthreads();
    }

    // ---- pair reduction (ch=1 -> smem -> ch=0), then finalize ----
    lsum0 += __shfl_xor_sync(0xffffffffu, lsum0, 1);
    lsum0 += __shfl_xor_sync(0xffffffffu, lsum0, 2);
    lsum1 += __shfl_xor_sync(0xffffffffu, lsum1, 1);
    lsum1 += __shfl_xor_sync(0xffffffffu, lsum1, 2);

    float* redO = (float*)(smem + SRED_O);             // 4 rg x 16 x 64 = 16KB
    float* redL = (float*)(smem + SRED_L);             // 4 rg x 16
    float* linv = (float*)(smem + SLINV);              // 64 floats
    __syncthreads();
    if (ch == 1) {
        #pragma unroll
        for (int in = 0; in < 8; in++) {
            int cidx = in * 8 + 2 * (l & 3);
            int r = l >> 2;
            redO[rg * 1024 + r * 64 + cidx]           = c_o[in][0];
            redO[rg * 1024 + r * 64 + cidx + 1]       = c_o[in][1];
            redO[rg * 1024 + (r + 8) * 64 + cidx]     = c_o[in][2];
            redO[rg * 1024 + (r + 8) * 64 + cidx + 1] = c_o[in][3];
        }
        if ((l & 3) == 0) {
            redL[rg * 16 + (l >> 2)]     = lsum0;
            redL[rg * 16 + (l >> 2) + 8] = lsum1;
        }
    }
    __syncthreads();
    if (ch == 0) {
        lsum0 += redL[rg * 16 + (l >> 2)];
        lsum1 += redL[rg * 16 + (l >> 2) + 8];
        const float inv0 = 1.0f / lsum0, inv1 = 1.0f / lsum1;
        if ((l & 3) == 0) {
            linv[wm0 + (l >> 2)]     = inv0;
            linv[wm0 + (l >> 2) + 8] = inv1;
        }

        const int r0g = q0 + wm0 + (l >> 2);
        const int b = bh / NHEAD, h = bh % NHEAD;
        const size_t gm0 = (size_t)(b * SSEQ + r0g) * KP2;
        const size_t gm1 = gm0 + (size_t)8 * KP2;
        #pragma unroll
        for (int in = 0; in < 8; in++) {
            int cidx = in * 8 + 2 * (l & 3);
            int r = l >> 2;
            float o0 = (c_o[in][0] + redO[rg * 1024 + r * 64 + cidx])           * inv0;
            float o1 = (c_o[in][1] + redO[rg * 1024 + r * 64 + cidx + 1])       * inv0;
            float o2 = (c_o[in][2] + redO[rg * 1024 + (r + 8) * 64 + cidx])     * inv1;
            float o3 = (c_o[in][3] + redO[rg * 1024 + (r + 8) * 64 + cidx + 1]) * inv1;
            int d = h * DHEAD + cidx;
            __half2 hp, lp;
            hilo2(o0, o1, hp, lp);
            *(__half2*)(cP + gm0 + d)          = hp;
            *(__half2*)(cP + gm0 + d + DMODEL) = lp;
            hilo2(o2, o3, hp, lp);
            *(__half2*)(cP + gm1 + d)          = hp;
            *(__half2*)(cP + gm1 + d + DMODEL) = lp;
        }
    }

    // ---- optional: normalize + emit fp32 attn ----
    if (wattn) {
        __syncthreads();
        const __half2* ps = (const __half2*)(pt + ((size_t)bh << 20) + (size_t)q0 * SSEQ);
        float4* ad = (float4*)(attn + ((size_t)bh << 20) + (size_t)q0 * SSEQ);
        for (int idx = tid; idx < 64 * 256; idx += 256) {
            int r = idx >> 8, cc = idx & 255;
            float iv = linv[r];
            __half2 a = ps[r * 512 + 2 * cc];
            __half2 b = ps[r * 512 + 2 * cc + 1];
            float4 v;
            v.x = __half2float(a.x) * iv;
            v.y = __half2float(a.y) * iv;
            v.z = __half2float(b.x) * iv;
            v.w = __half2float(b.y) * iv;
            ad[r * 256 + cc] = v;
        }
    }
}

// ============================ prep kernels ==================================
__global__ __launch_bounds__(256) void pack_x(const float* __restrict__ in, __half* __restrict__ o)
{
    size_t i = (size_t)blockIdx.x * 256 + threadIdx.x;   // float4 index
    if (i >= (size_t)MROWS * DMODEL / 4) return;
    float4 v = ((const float4*)in)[i];
    __half2 a, b;
    a.x = __float2half_rn(v.x); a.y = __float2half_rn(v.y);
    b.x = __float2half_rn(v.z); b.y = __float2half_rn(v.w);
    ((__half2*)o)[2 * i]     = a;
    ((__half2*)o)[2 * i + 1] = b;
}

__global__ void pack_w_all(const float* __restrict__ Wq, const float* __restrict__ Wk,
                           const float* __restrict__ Wv, const float* __restrict__ Wo,
                           __half* __restrict__ wqkvh, __half* __restrict__ wo)
{
    __shared__ float t[32][33];
    const int z = blockIdx.z;
    const float* W = (z == 0) ? Wq : (z == 1) ? Wk : (z == 2) ? Wv : Wo;
    int n0 = blockIdx.x * 32, k0 = blockIdx.y * 32;
    int x = threadIdx.x, y = threadIdx.y;
    #pragma unroll
    for (int j = 0; j < 32; j += 8)
        t[y + j][x] = W[(size_t)(k0 + y + j) * DMODEL + n0 + x] * WSC;
    __syncthreads();
    if (z < 3) {
        #pragma unroll
        for (int j = 0; j < 32; j += 8)
            wqkvh[(size_t)(z * DMODEL + n0 + y + j) * DMODEL + k0 + x] = __float2half_rn(t[x][y + j]);
        return;
    }
    #pragma unroll
    for (int j = 0; j < 32; j += 8) {
        __half h = __float2half_rn(t[x][y + j]);
        size_t base = (size_t)(n0 + y + j) * KP2 + k0 + x;
        wo[base] = h;
        wo[base + DMODEL] = h;
    }
}

// ============================ host launcher =================================
extern "C" void kernel_launch(void* const* d_in, const int* in_sizes, int n_in,
                              void* d_out, int out_size)
{
    (void)in_sizes; (void)n_in;
    const float* x  = (const float*)d_in[0];
    const float* Wq = (const float*)d_in[1];
    const float* bq = (const float*)d_in[2];
    const float* Wk = (const float*)d_in[3];
    const float* bk = (const float*)d_in[4];
    const float* Wv = (const float*)d_in[5];
    const float* bv = (const float*)d_in[6];
    const float* Wo = (const float*)d_in[7];
    const float* bo = (const float*)d_in[8];
    float* out = (float*)d_out;

    float* gattn;
    __half *pt, *xh, *wqkvh, *woP, *qP, *kP, *vP, *cP;
    cudaGetSymbolAddress((void**)&gattn, g_attn);
    cudaGetSymbolAddress((void**)&pt,    g_pt);
    cudaGetSymbolAddress((void**)&xh,    g_xh);
    cudaGetSymbolAddress((void**)&wqkvh, g_wqkvh);
    cudaGetSymbolAddress((void**)&woP,   g_woP);
    cudaGetSymbolAddress((void**)&qP,    g_q);
    cudaGetSymbolAddress((void**)&kP,    g_k);
    cudaGetSymbolAddress((void**)&vP,    g_v);
    cudaGetSymbolAddress((void**)&cP,    g_cP);

    const size_t final_elems = (size_t)MROWS * DMODEL;
    const int wattn = ((size_t)out_size > final_elems) ? 1 : 0;
    float* attn = wattn ? (out + final_elems) : gattn;

    constexpr int SM_GEMM = 3 * (128 * 64 * 2 + 128 * 64 * 2);   // 96KB, 3-stage
    cudaFuncSetAttribute(hgemm,      cudaFuncAttributeMaxDynamicSharedMemorySize, SM_GEMM);
    cudaFuncSetAttribute(fused_attn, cudaFuncAttributeMaxDynamicSharedMemorySize, FSM_BYTES);

    // pack
    {
        size_t n4 = (size_t)MROWS * DMODEL / 4;
        pack_x<<<(unsigned)((n4 + 255) / 256), 256>>>(x, xh);
        dim3 tb(32, 8), tg(DMODEL / 32, DMODEL / 32, 4);
        pack_w_all<<<tg, tb>>>(Wq, Wk, Wv, Wo, wqkvh, woP);
    }

    // merged QKV projection (N = 2304, K = 768, 1-term)
    dim3 gqkv(3 * DMODEL / 128, MROWS / 128);     // (18, 64)
    hgemm<<<gqkv, 256, SM_GEMM>>>(xh, wqkvh, bq, bk, bv, qP, kP, vP,
                                  DMODEL, DMODEL, DMODEL, 0);

    // fused scores + softmax + AV (+ attn emit only if checked)
    dim3 gf(SSEQ / 64, NBH);                      // (16, 96)
    fused_attn<<<gf, 256, FSM_BYTES>>>(qP, kP, vP, pt, attn, cP, wattn);

    // out = ctx @ Wo + bo (K = 1536, 2-term)
    dim3 gfin(DMODEL / 128, MROWS / 128);         // (6, 64)
    hgemm<<<gfin, 256, SM_GEMM>>>(cP, woP, bo, nullptr, nullptr, out, nullptr, nullptr,
                                  KP2, KP2, KP2, 1);
}

// round 12
// speedup vs baseline: 4.7822x; 1.0349x over previous
#include <cuda_runtime.h>
#include <cuda_fp16.h>
#include <cstdint>

#define BBATCH 8
#define SSEQ   1024
#define DMODEL 768
#define NHEAD  12
#define DHEAD  64
#define MROWS  (BBATCH*SSEQ)     // 8192
#define NBH    (BBATCH*NHEAD)    // 96
#define KP2    1536              // [hi|lo] packed K (ctx / Wo)
#define WSC    32.0f
#define WSCI   0.03125f

// ---------------- scratch (device globals; no allocations allowed) ----------
__device__ float g_attn[(size_t)NBH*SSEQ*SSEQ];          // fallback attn (fp32)
__device__ float g_l[(size_t)NBH*SSEQ];                  // softmax denominators
__device__ __half g_pt  [(size_t)NBH*SSEQ*SSEQ];         // unnormalized exp(S), fp16
__device__ __half g_xh  [(size_t)MROWS*DMODEL];          // x hi
__device__ __half g_wqkvh[(size_t)3*DMODEL*DMODEL];      // Wq|Wk|Wv rows, hi (x32)
__device__ __half g_woP [(size_t)DMODEL*KP2];            // Wo [wh|wh]
__device__ __half g_q  [(size_t)NBH*SSEQ*DHEAD];         // q*0.125 single fp16
__device__ __half g_k  [(size_t)NBH*SSEQ*DHEAD];         // k single fp16
__device__ __half g_v  [(size_t)NBH*SSEQ*DHEAD];         // V single fp16
__device__ __half g_cP [(size_t)MROWS*KP2];              // ctx [hi|lo]

// ============================ PTX helpers ===================================
__device__ __forceinline__ uint32_t smem_u32(const void* p) {
    uint32_t a;
    asm("{ .reg .u64 t; cvta.to.shared.u64 t, %1; cvt.u32.u64 %0, t; }" : "=r"(a) : "l"(p));
    return a;
}
#define SWZ(o) ((uint32_t)(o) ^ ((((uint32_t)(o)) >> 3) & 0x70))

__device__ __forceinline__ void cp16(uint32_t s, const void* g) {
    asm volatile("cp.async.cg.shared.global [%0], [%1], 16;" :: "r"(s), "l"(g));
}
#define CP_COMMIT() asm volatile("cp.async.commit_group;")
#define CP_WAIT(n)  asm volatile("cp.async.wait_group %0;" :: "n"(n))

__device__ __forceinline__ void ldsm4(uint32_t& r0, uint32_t& r1, uint32_t& r2, uint32_t& r3, uint32_t a) {
    asm volatile("ldmatrix.sync.aligned.m8n8.x4.shared.b16 {%0,%1,%2,%3}, [%4];"
                 : "=r"(r0), "=r"(r1), "=r"(r2), "=r"(r3) : "r"(a));
}
__device__ __forceinline__ void ldsm4t(uint32_t& r0, uint32_t& r1, uint32_t& r2, uint32_t& r3, uint32_t a) {
    asm volatile("ldmatrix.sync.aligned.m8n8.x4.trans.shared.b16 {%0,%1,%2,%3}, [%4];"
                 : "=r"(r0), "=r"(r1), "=r"(r2), "=r"(r3) : "r"(a));
}
__device__ __forceinline__ void mma16816(float* c, const uint32_t* a, const uint32_t* b) {
    asm volatile("mma.sync.aligned.m16n8k16.row.col.f32.f16.f16.f32 "
                 "{%0,%1,%2,%3}, {%4,%5,%6,%7}, {%8,%9}, {%0,%1,%2,%3};"
                 : "+f"(c[0]), "+f"(c[1]), "+f"(c[2]), "+f"(c[3])
                 : "r"(a[0]), "r"(a[1]), "r"(a[2]), "r"(a[3]), "r"(b[0]), "r"(b[1]));
}

__device__ __forceinline__ void hilo2(float v0, float v1, __half2& hp, __half2& lp) {
    __half h0 = __float2half_rn(v0), h1 = __float2half_rn(v1);
    hp.x = h0; hp.y = h1;
    lp.x = __float2half_rn(v0 - __half2float(h0));
    lp.y = __float2half_rn(v1 - __half2float(h1));
}
__device__ __forceinline__ uint32_t pk_hi(float x, float y) {
    __half2 t; t.x = __float2half_rn(x); t.y = __float2half_rn(y);
    return *(uint32_t*)&t;
}

// ============================ unified GEMM (HMMA fp16, 3-stage) =============
// mode 0: QKV merged (N=2304, K=768, 1-term; sel 0=q(*0.125)/1=k/2=v, single fp16)
// mode 1: final (N=768, K=1536, 2-term ctx; fp32 out + bias)
__global__ __launch_bounds__(256, 2) void hgemm(
    const __half* __restrict__ Ag, const __half* __restrict__ Bg,
    const float* __restrict__ b0p, const float* __restrict__ b1p, const float* __restrict__ b2p,
    void* __restrict__ o0, void* __restrict__ o1, void* __restrict__ o2,
    int K, int ldA, int ldB, int mode)
{
    constexpr int BM = 128, BN = 128, BK = 64;
    constexpr int MI = 4, NI = 4;
    constexpr int SA = BM * BK * 2, SB = BN * BK * 2, STG = SA + SB;  // 32KB/stage

    extern __shared__ char smem[];
    const uint32_t sbase = smem_u32(smem);
    const int tid = threadIdx.x, l = tid & 31, wid = tid >> 5;
    const int row0 = blockIdx.y * BM, col0 = blockIdx.x * BN;
    const int wm0 = (wid / 4) * 64, wn0 = (wid % 4) * 32;

    auto issue = [&](int ch, int st) {
        const int k0 = ch * BK;
        const uint32_t sA = sbase + st * STG;
        const uint32_t sB = sA + SA;
        for (int i = tid; i < BM * 8; i += 256) {
            int r = i >> 3, v = i & 7;
            cp16(sA + SWZ(r * 128 + v * 16), Ag + (size_t)(row0 + r) * ldA + k0 + v * 8);
        }
        for (int i = tid; i < BN * 8; i += 256) {
            int r = i >> 3, v = i & 7;
            cp16(sB + SWZ(r * 128 + v * 16), Bg + (size_t)(col0 + r) * ldB + k0 + v * 8);
        }
    };

    float c[MI][NI][4] = {};
    const int nch = K / BK;
    issue(0, 0); CP_COMMIT();
    if (nch > 1) { issue(1, 1); CP_COMMIT(); }

    for (int ch = 0; ch < nch; ch++) {
        if (ch + 1 < nch) { CP_WAIT(1); } else { CP_WAIT(0); }
        __syncthreads();
        if (ch + 2 < nch) { issue(ch + 2, (ch + 2) % 3); CP_COMMIT(); }

        const uint32_t sA = sbase + (ch % 3) * STG;
        const uint32_t sB = sA + SA;

        #pragma unroll
        for (int ks = 0; ks < 4; ks++) {
            uint32_t af[MI][4];
            #pragma unroll
            for (int im = 0; im < MI; im++)
                ldsm4(af[im][0], af[im][1], af[im][2], af[im][3],
                      sA + SWZ((wm0 + im * 16 + (l & 15)) * 128 + ks * 32 + ((l >> 4) & 1) * 16));
            uint32_t bf[NI][2];
            #pragma unroll
            for (int i2 = 0; i2 < NI / 2; i2++) {
                int g = l >> 3;
                uint32_t r0, r1, r2, r3;
                ldsm4(r0, r1, r2, r3,
                      sB + SWZ((wn0 + i2 * 16 + ((g >> 1) & 1) * 8 + (l & 7)) * 128 + ks * 32 + (g & 1) * 16));
                bf[2 * i2][0] = r0; bf[2 * i2][1] = r1;
                bf[2 * i2 + 1][0] = r2; bf[2 * i2 + 1][1] = r3;
            }
            #pragma unroll
            for (int im = 0; im < MI; im++)
                #pragma unroll
                for (int in = 0; in < NI; in++)
                    mma16816(c[im][in], af[im], bf[in]);
        }
    }
    __syncthreads();

    const int sel = (mode == 0) ? col0 / DMODEL : 3;          // 0 q, 1 k, 2 v, 3 final
    const int dcol0 = col0 % DMODEL;
    const float* bs = (sel == 1) ? b1p : (sel == 2) ? b2p : b0p;
    const float qsc = (sel == 0) ? 0.125f : 1.0f;

    #pragma unroll
    for (int im = 0; im < MI; im++)
        #pragma unroll
        for (int in = 0; in < NI; in++)
            #pragma unroll
            for (int half_ = 0; half_ < 2; half_++) {
                int m = row0 + wm0 + im * 16 + (l >> 2) + half_ * 8;
                int nd = dcol0 + wn0 + in * 8 + (l & 3) * 2;
                float v0 = c[im][in][2 * half_] * WSCI + bs[nd];
                float v1 = c[im][in][2 * half_ + 1] * WSCI + bs[nd + 1];
                if (sel == 3) {
                    float2 w; w.x = v0; w.y = v1;
                    *(float2*)((float*)o0 + (size_t)m * DMODEL + nd) = w;
                    continue;
                }
                v0 *= qsc; v1 *= qsc;
                int b = m >> 10, s = m & 1023, h = nd >> 6, dd = nd & 63;
                __half2 t; t.x = __float2half_rn(v0); t.y = __float2half_rn(v1);
                __half* ob = (sel == 0) ? (__half*)o0 : (sel == 1) ? (__half*)o1 : (__half*)o2;
                *(__half2*)(ob + ((size_t)(b * NHEAD + h) * SSEQ + s) * DHEAD + dd) = t;
            }
}

// ============================ fused attention ===============================
// CTA: (bh, 64 q-rows). 8 warps: rg=w>>1 rows [rg*16,+16), ch=w&1 kv half.
// S 1-term; PV 1-term (P-hi fp16); p~ staged fp16; l written for rescale.
#define SQ_OFF  0                         // 8KB q
#define SK_OFF  8192                      // 2 x 16KB K buffers
#define SV_OFF  40960                     // 16KB V
#define SRED_O  8192                      // reuse K region post-loop (16KB)
#define SRED_L  (8192 + 16384)
#define FSM_BYTES 57344

__global__ __launch_bounds__(256, 2) void fused_attn(
    const __half* __restrict__ Qp, const __half* __restrict__ Kp,
    const __half* __restrict__ Vp,
    __half* __restrict__ pt, float* __restrict__ lbuf,
    __half* __restrict__ cP, int wattn)
{
    extern __shared__ char smem[];
    const uint32_t sbase = smem_u32(smem);
    const int tid = threadIdx.x, l = tid & 31, wid = tid >> 5;
    const int rg = wid >> 1, ch = wid & 1;
    const int bh = blockIdx.y, q0 = blockIdx.x * 64;
    const int wm0 = rg * 16;

    const __half* Qb = Qp + (size_t)bh * SSEQ * DHEAD;
    const __half* Kb = Kp + (size_t)bh * SSEQ * DHEAD;
    const __half* Vb = Vp + (size_t)bh * SSEQ * DHEAD;

    auto issueK = [&](int t, int st) {
        const uint32_t kb = sbase + SK_OFF + st * 16384;
        for (int i = tid; i < 1024; i += 256) {
            int r = i >> 3, v = i & 7;
            cp16(kb + SWZ(r * 128 + v * 16), Kb + (size_t)(t * 128 + r) * DHEAD + v * 8);
        }
    };
    auto issueV = [&](int t) {
        for (int i = tid; i < 1024; i += 256) {
            int r = i >> 3, v = i & 7;
            cp16(sbase + SV_OFF + SWZ(r * 128 + v * 16),
                 Vb + (size_t)(t * 128 + r) * DHEAD + v * 8);
        }
    };

    // preload Q (64 rows x 64 dims, single fp16)
    for (int i = tid; i < 512; i += 256) {
        int r = i >> 3, v = i & 7;
        cp16(sbase + SQ_OFF + SWZ(r * 128 + v * 16), Qb + (size_t)(q0 + r) * DHEAD + v * 8);
    }
    issueK(0, 0);
    CP_COMMIT();

    float c_o[8][4] = {};
    float lsum0 = 0.f, lsum1 = 0.f;

    for (int t = 0; t < 8; t++) {
        CP_WAIT(0);
        __syncthreads();
        issueV(t); CP_COMMIT();
        if (t < 7) { issueK(t + 1, (t + 1) & 1); CP_COMMIT(); }

        // ---- S: 16 q-rows x 64 kv (this warp's half), 1-term ----
        float cs[8][4] = {};
        const uint32_t kb = sbase + SK_OFF + (t & 1) * 16384;
        const uint32_t sQ = sbase + SQ_OFF;
        #pragma unroll
        for (int ks = 0; ks < 4; ks++) {
            uint32_t af[4];
            ldsm4(af[0], af[1], af[2], af[3],
                  sQ + SWZ((wm0 + (l & 15)) * 128 + ks * 32 + ((l >> 4) & 1) * 16));
            #pragma unroll
            for (int i2 = 0; i2 < 4; i2++) {
                int g = l >> 3;
                uint32_t r0, r1, r2, r3;
                ldsm4(r0, r1, r2, r3,
                      kb + SWZ((ch * 64 + i2 * 16 + ((g >> 1) & 1) * 8 + (l & 7)) * 128
                               + ks * 32 + (g & 1) * 16));
                uint32_t b0[2] = {r0, r1}, b1[2] = {r2, r3};
                mma16816(cs[2 * i2],     af, b0);
                mma16816(cs[2 * i2 + 1], af, b1);
            }
        }

        // ---- exp + row-sum; pack P-hi once (feeds PV and optional p~ write) ----
        uint32_t ph[8][2];
        #pragma unroll
        for (int in = 0; in < 8; in++) {
            cs[in][0] = __expf(cs[in][0]);
            cs[in][1] = __expf(cs[in][1]);
            cs[in][2] = __expf(cs[in][2]);
            cs[in][3] = __expf(cs[in][3]);
            lsum0 += cs[in][0] + cs[in][1];
            lsum1 += cs[in][2] + cs[in][3];
            ph[in][0] = pk_hi(cs[in][0], cs[in][1]);
            ph[in][1] = pk_hi(cs[in][2], cs[in][3]);
        }
        if (wattn) {
            __half* p0 = pt + ((size_t)bh << 20) + (size_t)(q0 + wm0 + (l >> 2)) * SSEQ
                         + t * 128 + ch * 64 + 2 * (l & 3);
            __half* p1 = p0 + 8 * SSEQ;
            #pragma unroll
            for (int in = 0; in < 8; in++) {
                *(uint32_t*)(p0 + in * 8) = ph[in][0];
                *(uint32_t*)(p1 + in * 8) = ph[in][1];
            }
        }

        if (t < 7) CP_WAIT(1); else CP_WAIT(0);
        __syncthreads();

        // ---- partial O += P~hi @ V over warp's 64 kv (1-term) ----
        const uint32_t sVh = sbase + SV_OFF;
        #pragma unroll
        for (int kk = 0; kk < 4; kk++) {
            uint32_t ah[4];
            ah[0] = ph[2*kk][0];   ah[1] = ph[2*kk][1];
            ah[2] = ph[2*kk+1][0]; ah[3] = ph[2*kk+1][1];
            uint32_t vrow = (uint32_t)(ch * 64 + kk * 16 + ((l >> 3) & 1) * 8 + (l & 7)) * 128
                          + ((uint32_t)(l >> 4)) * 16;
            #pragma unroll
            for (int in = 0; in < 8; in += 2) {
                uint32_t h0, h1, h2, h3;
                ldsm4t(h0, h1, h2, h3, sVh + SWZ(vrow + in * 16));
                uint32_t bh2[2] = {h0, h1}, bh3[2] = {h2, h3};
                mma16816(c_o[in],     ah, bh2);
                mma16816(c_o[in + 1], ah, bh3);
            }
        }
        __syncthreads();
    }

    // ---- pair reduction (ch=1 -> smem -> ch=0), then finalize ----
    lsum0 += __shfl_xor_sync(0xffffffffu, lsum0, 1);
    lsum0 += __shfl_xor_sync(0xffffffffu, lsum0, 2);
    lsum1 += __shfl_xor_sync(0xffffffffu, lsum1, 1);
    lsum1 += __shfl_xor_sync(0xffffffffu, lsum1, 2);

    float* redO = (float*)(smem + SRED_O);             // 4 rg x 16 x 64 = 16KB
    float* redL = (float*)(smem + SRED_L);             // 4 rg x 16
    __syncthreads();
    if (ch == 1) {
        #pragma unroll
        for (int in = 0; in < 8; in++) {
            int cidx = in * 8 + 2 * (l & 3);
            int r = l >> 2;
            redO[rg * 1024 + r * 64 + cidx]           = c_o[in][0];
            redO[rg * 1024 + r * 64 + cidx + 1]       = c_o[in][1];
            redO[rg * 1024 + (r + 8) * 64 + cidx]     = c_o[in][2];
            redO[rg * 1024 + (r + 8) * 64 + cidx + 1] = c_o[in][3];
        }
        if ((l & 3) == 0) {
            redL[rg * 16 + (l >> 2)]     = lsum0;
            redL[rg * 16 + (l >> 2) + 8] = lsum1;
        }
    }
    __syncthreads();
    if (ch == 0) {
        lsum0 += redL[rg * 16 + (l >> 2)];
        lsum1 += redL[rg * 16 + (l >> 2) + 8];
        const float inv0 = 1.0f / lsum0, inv1 = 1.0f / lsum1;

        const int r0g = q0 + wm0 + (l >> 2);
        if ((l & 3) == 0) {
            lbuf[(size_t)bh * SSEQ + r0g]     = lsum0;
            lbuf[(size_t)bh * SSEQ + r0g + 8] = lsum1;
        }
        const int b = bh / NHEAD, h = bh % NHEAD;
        const size_t gm0 = (size_t)(b * SSEQ + r0g) * KP2;
        const size_t gm1 = gm0 + (size_t)8 * KP2;
        #pragma unroll
        for (int in = 0; in < 8; in++) {
            int cidx = in * 8 + 2 * (l & 3);
            int r = l >> 2;
            float o0 = (c_o[in][0] + redO[rg * 1024 + r * 64 + cidx])           * inv0;
            float o1 = (c_o[in][1] + redO[rg * 1024 + r * 64 + cidx + 1])       * inv0;
            float o2 = (c_o[in][2] + redO[rg * 1024 + (r + 8) * 64 + cidx])     * inv1;
            float o3 = (c_o[in][3] + redO[rg * 1024 + (r + 8) * 64 + cidx + 1]) * inv1;
            int d = h * DHEAD + cidx;
            __half2 hp, lp;
            hilo2(o0, o1, hp, lp);
            *(__half2*)(cP + gm0 + d)          = hp;
            *(__half2*)(cP + gm0 + d + DMODEL) = lp;
            hilo2(o2, o3, hp, lp);
            *(__half2*)(cP + gm1 + d)          = hp;
            *(__half2*)(cP + gm1 + d + DMODEL) = lp;
        }
    }
}

// rescale: read fp16 p~, normalize by 1/l, write fp32 attn
__global__ __launch_bounds__(256) void rescale_attn(const __half* __restrict__ pt,
                                                    float* __restrict__ attn,
                                                    const float* __restrict__ lbuf)
{
    const size_t row = blockIdx.x;
    const float inv = 1.0f / lbuf[row];
    const __half2* s = (const __half2*)(pt + row * SSEQ);
    float4* d = (float4*)(attn + row * SSEQ);
    const int i = threadIdx.x;
    __half2 a = s[2 * i], b = s[2 * i + 1];
    float4 v;
    v.x = __half2float(a.x) * inv;
    v.y = __half2float(a.y) * inv;
    v.z = __half2float(b.x) * inv;
    v.w = __half2float(b.y) * inv;
    d[i] = v;
}

// ============================ prep kernels ==================================
__global__ __launch_bounds__(256) void pack_x(const float* __restrict__ in, __half* __restrict__ o)
{
    size_t i = (size_t)blockIdx.x * 256 + threadIdx.x;   // float4 index
    if (i >= (size_t)MROWS * DMODEL / 4) return;
    float4 v = ((const float4*)in)[i];
    __half2 a, b;
    a.x = __float2half_rn(v.x); a.y = __float2half_rn(v.y);
    b.x = __float2half_rn(v.z); b.y = __float2half_rn(v.w);
    ((__half2*)o)[2 * i]     = a;
    ((__half2*)o)[2 * i + 1] = b;
}

__global__ void pack_w_all(const float* __restrict__ Wq, const float* __restrict__ Wk,
                           const float* __restrict__ Wv, const float* __restrict__ Wo,
                           __half* __restrict__ wqkvh, __half* __restrict__ wo)
{
    __shared__ float t[32][33];
    const int z = blockIdx.z;
    const float* W = (z == 0) ? Wq : (z == 1) ? Wk : (z == 2) ? Wv : Wo;
    int n0 = blockIdx.x * 32, k0 = blockIdx.y * 32;
    int x = threadIdx.x, y = threadIdx.y;
    #pragma unroll
    for (int j = 0; j < 32; j += 8)
        t[y + j][x] = W[(size_t)(k0 + y + j) * DMODEL + n0 + x] * WSC;
    __syncthreads();
    if (z < 3) {
        #pragma unroll
        for (int j = 0; j < 32; j += 8)
            wqkvh[(size_t)(z * DMODEL + n0 + y + j) * DMODEL + k0 + x] = __float2half_rn(t[x][y + j]);
        return;
    }
    #pragma unroll
    for (int j = 0; j < 32; j += 8) {
        __half h = __float2half_rn(t[x][y + j]);
        size_t base = (size_t)(n0 + y + j) * KP2 + k0 + x;
        wo[base] = h;
        wo[base + DMODEL] = h;
    }
}

// ============================ host launcher =================================
extern "C" void kernel_launch(void* const* d_in, const int* in_sizes, int n_in,
                              void* d_out, int out_size)
{
    (void)in_sizes; (void)n_in;
    const float* x  = (const float*)d_in[0];
    const float* Wq = (const float*)d_in[1];
    const float* bq = (const float*)d_in[2];
    const float* Wk = (const float*)d_in[3];
    const float* bk = (const float*)d_in[4];
    const float* Wv = (const float*)d_in[5];
    const float* bv = (const float*)d_in[6];
    const float* Wo = (const float*)d_in[7];
    const float* bo = (const float*)d_in[8];
    float* out = (float*)d_out;

    float *gattn, *gl;
    __half *pt, *xh, *wqkvh, *woP, *qP, *kP, *vP, *cP;
    cudaGetSymbolAddress((void**)&gattn, g_attn);
    cudaGetSymbolAddress((void**)&gl,    g_l);
    cudaGetSymbolAddress((void**)&pt,    g_pt);
    cudaGetSymbolAddress((void**)&xh,    g_xh);
    cudaGetSymbolAddress((void**)&wqkvh, g_wqkvh);
    cudaGetSymbolAddress((void**)&woP,   g_woP);
    cudaGetSymbolAddress((void**)&qP,    g_q);
    cudaGetSymbolAddress((void**)&kP,    g_k);
    cudaGetSymbolAddress((void**)&vP,    g_v);
    cudaGetSymbolAddress((void**)&cP,    g_cP);

    const size_t final_elems = (size_t)MROWS * DMODEL;
    const int wattn = ((size_t)out_size > final_elems) ? 1 : 0;
    float* attn = wattn ? (out + final_elems) : gattn;

    static cudaStream_t s2 = nullptr;
    static cudaEvent_t evA = nullptr, evB = nullptr;
    if (s2 == nullptr) {
        cudaStreamCreateWithFlags(&s2, cudaStreamNonBlocking);
        cudaEventCreateWithFlags(&evA, cudaEventDisableTiming);
        cudaEventCreateWithFlags(&evB, cudaEventDisableTiming);
    }

    constexpr int SM_GEMM = 3 * (128 * 64 * 2 + 128 * 64 * 2);   // 96KB, 3-stage
    cudaFuncSetAttribute(hgemm,      cudaFuncAttributeMaxDynamicSharedMemorySize, SM_GEMM);
    cudaFuncSetAttribute(fused_attn, cudaFuncAttributeMaxDynamicSharedMemorySize, FSM_BYTES);

    // pack
    {
        size_t n4 = (size_t)MROWS * DMODEL / 4;
        pack_x<<<(unsigned)((n4 + 255) / 256), 256>>>(x, xh);
        dim3 tb(32, 8), tg(DMODEL / 32, DMODEL / 32, 4);
        pack_w_all<<<tg, tb>>>(Wq, Wk, Wv, Wo, wqkvh, woP);
    }

    // merged QKV projection (N = 2304, K = 768, 1-term)
    dim3 gqkv(3 * DMODEL / 128, MROWS / 128);     // (18, 64)
    hgemm<<<gqkv, 256, SM_GEMM>>>(xh, wqkvh, bq, bk, bv, qP, kP, vP,
                                  DMODEL, DMODEL, DMODEL, 0);

    // fused scores + softmax + AV (p~ + l emitted; attn normalized separately)
    dim3 gf(SSEQ / 64, NBH);                      // (16, 96)
    fused_attn<<<gf, 256, FSM_BYTES>>>(qP, kP, vP, pt, gl, cP, wattn);

    // fork: rescale attn on s2, overlapped with final GEMM
    if (wattn) {
        cudaEventRecord(evA, 0);
        cudaStreamWaitEvent(s2, evA, 0);
        rescale_attn<<<NBH * SSEQ, 256, 0, s2>>>(pt, attn, gl);
        cudaEventRecord(evB, s2);
    }

    // out = ctx @ Wo + bo (K = 1536, 2-term)
    dim3 gfin(DMODEL / 128, MROWS / 128);         // (6, 64)
    hgemm<<<gfin, 256, SM_GEMM>>>(cP, woP, bo, nullptr, nullptr, out, nullptr, nullptr,
                                  KP2, KP2, KP2, 1);

    if (wattn) cudaStreamWaitEvent(0, evB, 0);
}

// round 13
// speedup vs baseline: 5.6561x; 1.1827x over previous
#include <cuda_runtime.h>
#include <cuda_fp16.h>
#include <cstdint>

#define BBATCH 8
#define SSEQ   1024
#define DMODEL 768
#define NHEAD  12
#define DHEAD  64
#define MROWS  (BBATCH*SSEQ)     // 8192
#define NBH    (BBATCH*NHEAD)    // 96
#define WSC    32.0f
#define WSCI   0.03125f

// ---------------- scratch (device globals; no allocations allowed) ----------
__device__ float g_attn[(size_t)NBH*SSEQ*SSEQ];          // fallback attn (fp32)
__device__ float g_l[(size_t)NBH*SSEQ];                  // softmax denominators
__device__ __half g_pt  [(size_t)NBH*SSEQ*SSEQ];         // unnormalized exp(S), fp16
__device__ __half g_xh  [(size_t)MROWS*DMODEL];          // x hi
__device__ __half g_wqkvh[(size_t)3*DMODEL*DMODEL];      // Wq|Wk|Wv rows, hi (x32)
__device__ __half g_woh [(size_t)DMODEL*DMODEL];         // Wo hi (x32)
__device__ __half g_q  [(size_t)NBH*SSEQ*DHEAD];         // q*0.125 single fp16
__device__ __half g_k  [(size_t)NBH*SSEQ*DHEAD];         // k single fp16
__device__ __half g_v  [(size_t)NBH*SSEQ*DHEAD];         // V single fp16
__device__ __half g_ch [(size_t)MROWS*DMODEL];           // ctx single fp16

// ============================ PTX helpers ===================================
__device__ __forceinline__ uint32_t smem_u32(const void* p) {
    uint32_t a;
    asm("{ .reg .u64 t; cvta.to.shared.u64 t, %1; cvt.u32.u64 %0, t; }" : "=r"(a) : "l"(p));
    return a;
}
#define SWZ(o) ((uint32_t)(o) ^ ((((uint32_t)(o)) >> 3) & 0x70))

__device__ __forceinline__ void cp16(uint32_t s, const void* g) {
    asm volatile("cp.async.cg.shared.global [%0], [%1], 16;" :: "r"(s), "l"(g));
}
#define CP_COMMIT() asm volatile("cp.async.commit_group;")
#define CP_WAIT(n)  asm volatile("cp.async.wait_group %0;" :: "n"(n))

__device__ __forceinline__ void ldsm4(uint32_t& r0, uint32_t& r1, uint32_t& r2, uint32_t& r3, uint32_t a) {
    asm volatile("ldmatrix.sync.aligned.m8n8.x4.shared.b16 {%0,%1,%2,%3}, [%4];"
                 : "=r"(r0), "=r"(r1), "=r"(r2), "=r"(r3) : "r"(a));
}
__device__ __forceinline__ void ldsm4t(uint32_t& r0, uint32_t& r1, uint32_t& r2, uint32_t& r3, uint32_t a) {
    asm volatile("ldmatrix.sync.aligned.m8n8.x4.trans.shared.b16 {%0,%1,%2,%3}, [%4];"
                 : "=r"(r0), "=r"(r1), "=r"(r2), "=r"(r3) : "r"(a));
}
__device__ __forceinline__ void mma16816(float* c, const uint32_t* a, const uint32_t* b) {
    asm volatile("mma.sync.aligned.m16n8k16.row.col.f32.f16.f16.f32 "
                 "{%0,%1,%2,%3}, {%4,%5,%6,%7}, {%8,%9}, {%0,%1,%2,%3};"
                 : "+f"(c[0]), "+f"(c[1]), "+f"(c[2]), "+f"(c[3])
                 : "r"(a[0]), "r"(a[1]), "r"(a[2]), "r"(a[3]), "r"(b[0]), "r"(b[1]));
}

__device__ __forceinline__ uint32_t pk_hi(float x, float y) {
    __half2 t; t.x = __float2half_rn(x); t.y = __float2half_rn(y);
    return *(uint32_t*)&t;
}

// ============================ unified GEMM (HMMA fp16, 3-stage) =============
// mode 0: QKV merged (N=2304, K=768; sel 0=q(*0.125)/1=k/2=v, single fp16)
// mode 1: final (N=768, K=768, 1-term ctx; fp32 out + bias)
__global__ __launch_bounds__(256, 2) void hgemm(
    const __half* __restrict__ Ag, const __half* __restrict__ Bg,
    const float* __restrict__ b0p, const float* __restrict__ b1p, const float* __restrict__ b2p,
    void* __restrict__ o0, void* __restrict__ o1, void* __restrict__ o2,
    int K, int ldA, int ldB, int mode)
{
    constexpr int BM = 128, BN = 128, BK = 64;
    constexpr int MI = 4, NI = 4;
    constexpr int SA = BM * BK * 2, SB = BN * BK * 2, STG = SA + SB;  // 32KB/stage

    extern __shared__ char smem[];
    const uint32_t sbase = smem_u32(smem);
    const int tid = threadIdx.x, l = tid & 31, wid = tid >> 5;
    const int row0 = blockIdx.y * BM, col0 = blockIdx.x * BN;
    const int wm0 = (wid / 4) * 64, wn0 = (wid % 4) * 32;

    auto issue = [&](int ch, int st) {
        const int k0 = ch * BK;
        const uint32_t sA = sbase + st * STG;
        const uint32_t sB = sA + SA;
        for (int i = tid; i < BM * 8; i += 256) {
            int r = i >> 3, v = i & 7;
            cp16(sA + SWZ(r * 128 + v * 16), Ag + (size_t)(row0 + r) * ldA + k0 + v * 8);
        }
        for (int i = tid; i < BN * 8; i += 256) {
            int r = i >> 3, v = i & 7;
            cp16(sB + SWZ(r * 128 + v * 16), Bg + (size_t)(col0 + r) * ldB + k0 + v * 8);
        }
    };

    float c[MI][NI][4] = {};
    const int nch = K / BK;
    issue(0, 0); CP_COMMIT();
    if (nch > 1) { issue(1, 1); CP_COMMIT(); }

    for (int ch = 0; ch < nch; ch++) {
        if (ch + 1 < nch) { CP_WAIT(1); } else { CP_WAIT(0); }
        __syncthreads();
        if (ch + 2 < nch) { issue(ch + 2, (ch + 2) % 3); CP_COMMIT(); }

        const uint32_t sA = sbase + (ch % 3) * STG;
        const uint32_t sB = sA + SA;

        #pragma unroll
        for (int ks = 0; ks < 4; ks++) {
            uint32_t af[MI][4];
            #pragma unroll
            for (int im = 0; im < MI; im++)
                ldsm4(af[im][0], af[im][1], af[im][2], af[im][3],
                      sA + SWZ((wm0 + im * 16 + (l & 15)) * 128 + ks * 32 + ((l >> 4) & 1) * 16));
            uint32_t bf[NI][2];
            #pragma unroll
            for (int i2 = 0; i2 < NI / 2; i2++) {
                int g = l >> 3;
                uint32_t r0, r1, r2, r3;
                ldsm4(r0, r1, r2, r3,
                      sB + SWZ((wn0 + i2 * 16 + ((g >> 1) & 1) * 8 + (l & 7)) * 128 + ks * 32 + (g & 1) * 16));
                bf[2 * i2][0] = r0; bf[2 * i2][1] = r1;
                bf[2 * i2 + 1][0] = r2; bf[2 * i2 + 1][1] = r3;
            }
            #pragma unroll
            for (int im = 0; im < MI; im++)
                #pragma unroll
                for (int in = 0; in < NI; in++)
                    mma16816(c[im][in], af[im], bf[in]);
        }
    }
    __syncthreads();

    const int sel = (mode == 0) ? col0 / DMODEL : 3;          // 0 q, 1 k, 2 v, 3 final
    const int dcol0 = col0 % DMODEL;
    const float* bs = (sel == 1) ? b1p : (sel == 2) ? b2p : b0p;
    const float qsc = (sel == 0) ? 0.125f : 1.0f;

    #pragma unroll
    for (int im = 0; im < MI; im++)
        #pragma unroll
        for (int in = 0; in < NI; in++)
            #pragma unroll
            for (int half_ = 0; half_ < 2; half_++) {
                int m = row0 + wm0 + im * 16 + (l >> 2) + half_ * 8;
                int nd = dcol0 + wn0 + in * 8 + (l & 3) * 2;
                float v0 = c[im][in][2 * half_] * WSCI + bs[nd];
                float v1 = c[im][in][2 * half_ + 1] * WSCI + bs[nd + 1];
                if (sel == 3) {
                    float2 w; w.x = v0; w.y = v1;
                    *(float2*)((float*)o0 + (size_t)m * DMODEL + nd) = w;
                    continue;
                }
                v0 *= qsc; v1 *= qsc;
                int b = m >> 10, s = m & 1023, h = nd >> 6, dd = nd & 63;
                __half2 t; t.x = __float2half_rn(v0); t.y = __float2half_rn(v1);
                __half* ob = (sel == 0) ? (__half*)o0 : (sel == 1) ? (__half*)o1 : (__half*)o2;
                *(__half2*)(ob + ((size_t)(b * NHEAD + h) * SSEQ + s) * DHEAD + dd) = t;
            }
}

// ============================ fused attention ===============================
// CTA: (bh, 64 q-rows). 8 warps: rg=w>>1 rows [rg*16,+16), ch=w&1 kv half.
// S 1-term; PV 1-term (P-hi fp16); p~ staged fp16; ctx single fp16; l for rescale.
#define SQ_OFF  0                         // 8KB q
#define SK_OFF  8192                      // 2 x 16KB K buffers
#define SV_OFF  40960                     // 16KB V
#define SRED_O  8192                      // reuse K region post-loop (16KB)
#define SRED_L  (8192 + 16384)
#define FSM_BYTES 57344

__global__ __launch_bounds__(256, 2) void fused_attn(
    const __half* __restrict__ Qp, const __half* __restrict__ Kp,
    const __half* __restrict__ Vp,
    __half* __restrict__ pt, float* __restrict__ lbuf,
    __half* __restrict__ ch_out)
{
    extern __shared__ char smem[];
    const uint32_t sbase = smem_u32(smem);
    const int tid = threadIdx.x, l = tid & 31, wid = tid >> 5;
    const int rg = wid >> 1, ch = wid & 1;
    const int bh = blockIdx.y, q0 = blockIdx.x * 64;
    const int wm0 = rg * 16;

    const __half* Qb = Qp + (size_t)bh * SSEQ * DHEAD;
    const __half* Kb = Kp + (size_t)bh * SSEQ * DHEAD;
    const __half* Vb = Vp + (size_t)bh * SSEQ * DHEAD;

    auto issueK = [&](int t, int st) {
        const uint32_t kb = sbase + SK_OFF + st * 16384;
        for (int i = tid; i < 1024; i += 256) {
            int r = i >> 3, v = i & 7;
            cp16(kb + SWZ(r * 128 + v * 16), Kb + (size_t)(t * 128 + r) * DHEAD + v * 8);
        }
    };
    auto issueV = [&](int t) {
        for (int i = tid; i < 1024; i += 256) {
            int r = i >> 3, v = i & 7;
            cp16(sbase + SV_OFF + SWZ(r * 128 + v * 16),
                 Vb + (size_t)(t * 128 + r) * DHEAD + v * 8);
        }
    };

    for (int i = tid; i < 512; i += 256) {
        int r = i >> 3, v = i & 7;
        cp16(sbase + SQ_OFF + SWZ(r * 128 + v * 16), Qb + (size_t)(q0 + r) * DHEAD + v * 8);
    }
    issueK(0, 0);
    CP_COMMIT();

    float c_o[8][4] = {};
    float lsum0 = 0.f, lsum1 = 0.f;

    for (int t = 0; t < 8; t++) {
        CP_WAIT(0);
        __syncthreads();
        issueV(t); CP_COMMIT();
        if (t < 7) { issueK(t + 1, (t + 1) & 1); CP_COMMIT(); }

        // ---- S: 16 q-rows x 64 kv (this warp's half), 1-term ----
        float cs[8][4] = {};
        const uint32_t kb = sbase + SK_OFF + (t & 1) * 16384;
        const uint32_t sQ = sbase + SQ_OFF;
        #pragma unroll
        for (int ks = 0; ks < 4; ks++) {
            uint32_t af[4];
            ldsm4(af[0], af[1], af[2], af[3],
                  sQ + SWZ((wm0 + (l & 15)) * 128 + ks * 32 + ((l >> 4) & 1) * 16));
            #pragma unroll
            for (int i2 = 0; i2 < 4; i2++) {
                int g = l >> 3;
                uint32_t r0, r1, r2, r3;
                ldsm4(r0, r1, r2, r3,
                      kb + SWZ((ch * 64 + i2 * 16 + ((g >> 1) & 1) * 8 + (l & 7)) * 128
                               + ks * 32 + (g & 1) * 16));
                uint32_t b0[2] = {r0, r1}, b1[2] = {r2, r3};
                mma16816(cs[2 * i2],     af, b0);
                mma16816(cs[2 * i2 + 1], af, b1);
            }
        }

        // ---- exp + row-sum; pack P-hi (feeds PV and p~ write) ----
        uint32_t ph[8][2];
        #pragma unroll
        for (int in = 0; in < 8; in++) {
            cs[in][0] = __expf(cs[in][0]);
            cs[in][1] = __expf(cs[in][1]);
            cs[in][2] = __expf(cs[in][2]);
            cs[in][3] = __expf(cs[in][3]);
            lsum0 += cs[in][0] + cs[in][1];
            lsum1 += cs[in][2] + cs[in][3];
            ph[in][0] = pk_hi(cs[in][0], cs[in][1]);
            ph[in][1] = pk_hi(cs[in][2], cs[in][3]);
        }
        {
            __half* p0 = pt + ((size_t)bh << 20) + (size_t)(q0 + wm0 + (l >> 2)) * SSEQ
                         + t * 128 + ch * 64 + 2 * (l & 3);
            __half* p1 = p0 + 8 * SSEQ;
            #pragma unroll
            for (int in = 0; in < 8; in++) {
                *(uint32_t*)(p0 + in * 8) = ph[in][0];
                *(uint32_t*)(p1 + in * 8) = ph[in][1];
            }
        }

        if (t < 7) CP_WAIT(1); else CP_WAIT(0);
        __syncthreads();

        // ---- partial O += P~hi @ V over warp's 64 kv (1-term) ----
        const uint32_t sVh = sbase + SV_OFF;
        #pragma unroll
        for (int kk = 0; kk < 4; kk++) {
            uint32_t ah[4];
            ah[0] = ph[2*kk][0];   ah[1] = ph[2*kk][1];
            ah[2] = ph[2*kk+1][0]; ah[3] = ph[2*kk+1][1];
            uint32_t vrow = (uint32_t)(ch * 64 + kk * 16 + ((l >> 3) & 1) * 8 + (l & 7)) * 128
                          + ((uint32_t)(l >> 4)) * 16;
            #pragma unroll
            for (int in = 0; in < 8; in += 2) {
                uint32_t h0, h1, h2, h3;
                ldsm4t(h0, h1, h2, h3, sVh + SWZ(vrow + in * 16));
                uint32_t bh2[2] = {h0, h1}, bh3[2] = {h2, h3};
                mma16816(c_o[in],     ah, bh2);
                mma16816(c_o[in + 1], ah, bh3);
            }
        }
        __syncthreads();
    }

    // ---- pair reduction (ch=1 -> smem -> ch=0), then finalize ----
    lsum0 += __shfl_xor_sync(0xffffffffu, lsum0, 1);
    lsum0 += __shfl_xor_sync(0xffffffffu, lsum0, 2);
    lsum1 += __shfl_xor_sync(0xffffffffu, lsum1, 1);
    lsum1 += __shfl_xor_sync(0xffffffffu, lsum1, 2);

    float* redO = (float*)(smem + SRED_O);             // 4 rg x 16 x 64 = 16KB
    float* redL = (float*)(smem + SRED_L);             // 4 rg x 16
    __syncthreads();
    if (ch == 1) {
        #pragma unroll
        for (int in = 0; in < 8; in++) {
            int cidx = in * 8 + 2 * (l & 3);
            int r = l >> 2;
            redO[rg * 1024 + r * 64 + cidx]           = c_o[in][0];
            redO[rg * 1024 + r * 64 + cidx + 1]       = c_o[in][1];
            redO[rg * 1024 + (r + 8) * 64 + cidx]     = c_o[in][2];
            redO[rg * 1024 + (r + 8) * 64 + cidx + 1] = c_o[in][3];
        }
        if ((l & 3) == 0) {
            redL[rg * 16 + (l >> 2)]     = lsum0;
            redL[rg * 16 + (l >> 2) + 8] = lsum1;
        }
    }
    __syncthreads();
    if (ch == 0) {
        lsum0 += redL[rg * 16 + (l >> 2)];
        lsum1 += redL[rg * 16 + (l >> 2) + 8];
        const float inv0 = 1.0f / lsum0, inv1 = 1.0f / lsum1;

        const int r0g = q0 + wm0 + (l >> 2);
        if ((l & 3) == 0) {
            lbuf[(size_t)bh * SSEQ + r0g]     = lsum0;
            lbuf[(size_t)bh * SSEQ + r0g + 8] = lsum1;
        }
        const int b = bh / NHEAD, h = bh % NHEAD;
        const size_t gm0 = (size_t)(b * SSEQ + r0g) * DMODEL;
        const size_t gm1 = gm0 + (size_t)8 * DMODEL;
        #pragma unroll
        for (int in = 0; in < 8; in++) {
            int cidx = in * 8 + 2 * (l & 3);
            int r = l >> 2;
            float o0 = (c_o[in][0] + redO[rg * 1024 + r * 64 + cidx])           * inv0;
            float o1 = (c_o[in][1] + redO[rg * 1024 + r * 64 + cidx + 1])       * inv0;
            float o2 = (c_o[in][2] + redO[rg * 1024 + (r + 8) * 64 + cidx])     * inv1;
            float o3 = (c_o[in][3] + redO[rg * 1024 + (r + 8) * 64 + cidx + 1]) * inv1;
            int d = h * DHEAD + cidx;
            __half2 t0; t0.x = __float2half_rn(o0); t0.y = __float2half_rn(o1);
            __half2 t1; t1.x = __float2half_rn(o2); t1.y = __float2half_rn(o3);
            *(__half2*)(ch_out + gm0 + d) = t0;
            *(__half2*)(ch_out + gm1 + d) = t1;
        }
    }
}

// rescale: 2 rows/block, 16B p~ loads, 32B fp32 stores
__global__ __launch_bounds__(256) void rescale_attn(const __half* __restrict__ pt,
                                                    float* __restrict__ attn,
                                                    const float* __restrict__ lbuf)
{
    const int t = threadIdx.x;
    const size_t row = (size_t)blockIdx.x * 2 + (t >> 7);
    const int lane = t & 127;                 // 8 halves per lane
    const float inv = 1.0f / lbuf[row];
    const uint4* s = (const uint4*)(pt + row * SSEQ);
    float4* d = (float4*)(attn + row * SSEQ);
    uint4 pv = s[lane];
    __half2 h0 = *(__half2*)&pv.x, h1 = *(__half2*)&pv.y;
    __half2 h2 = *(__half2*)&pv.z, h3 = *(__half2*)&pv.w;
    float4 v0, v1;
    v0.x = __half2float(h0.x) * inv; v0.y = __half2float(h0.y) * inv;
    v0.z = __half2float(h1.x) * inv; v0.w = __half2float(h1.y) * inv;
    v1.x = __half2float(h2.x) * inv; v1.y = __half2float(h2.y) * inv;
    v1.z = __half2float(h3.x) * inv; v1.w = __half2float(h3.y) * inv;
    d[2 * lane]     = v0;
    d[2 * lane + 1] = v1;
}

// ============================ prep kernels ==================================
__global__ __launch_bounds__(256) void pack_x(const float* __restrict__ in, __half* __restrict__ o)
{
    size_t i = (size_t)blockIdx.x * 256 + threadIdx.x;   // float4 index
    if (i >= (size_t)MROWS * DMODEL / 4) return;
    float4 v = ((const float4*)in)[i];
    __half2 a, b;
    a.x = __float2half_rn(v.x); a.y = __float2half_rn(v.y);
    b.x = __float2half_rn(v.z); b.y = __float2half_rn(v.w);
    ((__half2*)o)[2 * i]     = a;
    ((__half2*)o)[2 * i + 1] = b;
}

__global__ void pack_w_all(const float* __restrict__ Wq, const float* __restrict__ Wk,
                           const float* __restrict__ Wv, const float* __restrict__ Wo,
                           __half* __restrict__ wqkvh, __half* __restrict__ woh)
{
    __shared__ float t[32][33];
    const int z = blockIdx.z;
    const float* W = (z == 0) ? Wq : (z == 1) ? Wk : (z == 2) ? Wv : Wo;
    int n0 = blockIdx.x * 32, k0 = blockIdx.y * 32;
    int x = threadIdx.x, y = threadIdx.y;
    #pragma unroll
    for (int j = 0; j < 32; j += 8)
        t[y + j][x] = W[(size_t)(k0 + y + j) * DMODEL + n0 + x] * WSC;
    __syncthreads();
    __half* o = (z == 3) ? woh : wqkvh + (size_t)z * DMODEL * DMODEL;
    #pragma unroll
    for (int j = 0; j < 32; j += 8)
        o[(size_t)(n0 + y + j) * DMODEL + k0 + x] = __float2half_rn(t[x][y + j]);
}

// ============================ host launcher =================================
extern "C" void kernel_launch(void* const* d_in, const int* in_sizes, int n_in,
                              void* d_out, int out_size)
{
    (void)in_sizes; (void)n_in;
    const float* x  = (const float*)d_in[0];
    const float* Wq = (const float*)d_in[1];
    const float* bq = (const float*)d_in[2];
    const float* Wk = (const float*)d_in[3];
    const float* bk = (const float*)d_in[4];
    const float* Wv = (const float*)d_in[5];
    const float* bv = (const float*)d_in[6];
    const float* Wo = (const float*)d_in[7];
    const float* bo = (const float*)d_in[8];
    float* out = (float*)d_out;

    float *gattn, *gl;
    __half *pt, *xh, *wqkvh, *woh, *qP, *kP, *vP, *chx;
    cudaGetSymbolAddress((void**)&gattn, g_attn);
    cudaGetSymbolAddress((void**)&gl,    g_l);
    cudaGetSymbolAddress((void**)&pt,    g_pt);
    cudaGetSymbolAddress((void**)&xh,    g_xh);
    cudaGetSymbolAddress((void**)&wqkvh, g_wqkvh);
    cudaGetSymbolAddress((void**)&woh,   g_woh);
    cudaGetSymbolAddress((void**)&qP,    g_q);
    cudaGetSymbolAddress((void**)&kP,    g_k);
    cudaGetSymbolAddress((void**)&vP,    g_v);
    cudaGetSymbolAddress((void**)&chx,   g_ch);

    const size_t final_elems = (size_t)MROWS * DMODEL;
    const int wattn = ((size_t)out_size > final_elems) ? 1 : 0;
    float* attn = wattn ? (out + final_elems) : gattn;

    static cudaStream_t s2 = nullptr;
    static cudaEvent_t evA = nullptr, evB = nullptr;
    if (s2 == nullptr) {
        cudaStreamCreateWithFlags(&s2, cudaStreamNonBlocking);
        cudaEventCreateWithFlags(&evA, cudaEventDisableTiming);
        cudaEventCreateWithFlags(&evB, cudaEventDisableTiming);
    }

    constexpr int SM_GEMM = 3 * (128 * 64 * 2 + 128 * 64 * 2);   // 96KB, 3-stage
    cudaFuncSetAttribute(hgemm,      cudaFuncAttributeMaxDynamicSharedMemorySize, SM_GEMM);
    cudaFuncSetAttribute(fused_attn, cudaFuncAttributeMaxDynamicSharedMemorySize, FSM_BYTES);

    // pack
    {
        size_t n4 = (size_t)MROWS * DMODEL / 4;
        pack_x<<<(unsigned)((n4 + 255) / 256), 256>>>(x, xh);
        dim3 tb(32, 8), tg(DMODEL / 32, DMODEL / 32, 4);
        pack_w_all<<<tg, tb>>>(Wq, Wk, Wv, Wo, wqkvh, woh);
    }

    // merged QKV projection (N = 2304, K = 768, 1-term)
    dim3 gqkv(3 * DMODEL / 128, MROWS / 128);     // (18, 64)
    hgemm<<<gqkv, 256, SM_GEMM>>>(xh, wqkvh, bq, bk, bv, qP, kP, vP,
                                  DMODEL, DMODEL, DMODEL, 0);

    // fused scores + softmax + AV (p~ + l + ctx emitted)
    dim3 gf(SSEQ / 64, NBH);                      // (16, 96)
    fused_attn<<<gf, 256, FSM_BYTES>>>(qP, kP, vP, pt, gl, chx);

    // fork: rescale attn on s2, overlapped with final GEMM
    if (wattn) {
        cudaEventRecord(evA, 0);
        cudaStreamWaitEvent(s2, evA, 0);
        rescale_attn<<<NBH * SSEQ / 2, 256, 0, s2>>>(pt, attn, gl);
        cudaEventRecord(evB, s2);
    }

    // out = ctx @ Wo + bo (K = 768, 1-term)
    dim3 gfin(DMODEL / 128, MROWS / 128);         // (6, 64)
    hgemm<<<gfin, 256, SM_GEMM>>>(chx, woh, bo, nullptr, nullptr, out, nullptr, nullptr,
                                  DMODEL, DMODEL, DMODEL, 1);

    if (wattn) cudaStreamWaitEvent(0, evB, 0);
}

// round 15
// speedup vs baseline: 5.7845x; 1.0227x over previous
#include <cuda_runtime.h>
#include <cuda_fp16.h>
#include <cstdint>

#define BBATCH 8
#define SSEQ   1024
#define DMODEL 768
#define NHEAD  12
#define DHEAD  64
#define MROWS  (BBATCH*SSEQ)     // 8192
#define NBH    (BBATCH*NHEAD)    // 96
#define WSC    32.0f
#define WSCI   0.03125f

// ---------------- scratch (device globals; no allocations allowed) ----------
__device__ float g_attn[(size_t)NBH*SSEQ*SSEQ];          // fallback attn (fp32)
__device__ float g_l[(size_t)NBH*SSEQ];                  // softmax denominators
__device__ __half g_pt  [(size_t)NBH*SSEQ*SSEQ];         // unnormalized exp(S), fp16
__device__ __half g_xh  [(size_t)MROWS*DMODEL];          // x hi
__device__ __half g_wqkvh[(size_t)3*DMODEL*DMODEL];      // Wq|Wk|Wv rows, hi (x32)
__device__ __half g_woh [(size_t)DMODEL*DMODEL];         // Wo hi (x32)
__device__ __half g_q  [(size_t)NBH*SSEQ*DHEAD];         // q*0.125 single fp16
__device__ __half g_k  [(size_t)NBH*SSEQ*DHEAD];         // k single fp16
__device__ __half g_v  [(size_t)NBH*SSEQ*DHEAD];         // V single fp16
__device__ __half g_ch [(size_t)MROWS*DMODEL];           // ctx single fp16

// ============================ PTX helpers ===================================
__device__ __forceinline__ uint32_t smem_u32(const void* p) {
    uint32_t a;
    asm("{ .reg .u64 t; cvta.to.shared.u64 t, %1; cvt.u32.u64 %0, t; }" : "=r"(a) : "l"(p));
    return a;
}
#define SWZ(o) ((uint32_t)(o) ^ ((((uint32_t)(o)) >> 3) & 0x70))

__device__ __forceinline__ void cp16(uint32_t s, const void* g) {
    asm volatile("cp.async.cg.shared.global [%0], [%1], 16;" :: "r"(s), "l"(g));
}
#define CP_COMMIT() asm volatile("cp.async.commit_group;")
#define CP_WAIT(n)  asm volatile("cp.async.wait_group %0;" :: "n"(n))

__device__ __forceinline__ void ldsm4(uint32_t& r0, uint32_t& r1, uint32_t& r2, uint32_t& r3, uint32_t a) {
    asm volatile("ldmatrix.sync.aligned.m8n8.x4.shared.b16 {%0,%1,%2,%3}, [%4];"
                 : "=r"(r0), "=r"(r1), "=r"(r2), "=r"(r3) : "r"(a));
}
__device__ __forceinline__ void ldsm4t(uint32_t& r0, uint32_t& r1, uint32_t& r2, uint32_t& r3, uint32_t a) {
    asm volatile("ldmatrix.sync.aligned.m8n8.x4.trans.shared.b16 {%0,%1,%2,%3}, [%4];"
                 : "=r"(r0), "=r"(r1), "=r"(r2), "=r"(r3) : "r"(a));
}
__device__ __forceinline__ void mma16816(float* c, const uint32_t* a, const uint32_t* b) {
    asm volatile("mma.sync.aligned.m16n8k16.row.col.f32.f16.f16.f32 "
                 "{%0,%1,%2,%3}, {%4,%5,%6,%7}, {%8,%9}, {%0,%1,%2,%3};"
                 : "+f"(c[0]), "+f"(c[1]), "+f"(c[2]), "+f"(c[3])
                 : "r"(a[0]), "r"(a[1]), "r"(a[2]), "r"(a[3]), "r"(b[0]), "r"(b[1]));
}

__device__ __forceinline__ uint32_t pk_hi(float x, float y) {
    __half2 t; t.x = __float2half_rn(x); t.y = __float2half_rn(y);
    return *(uint32_t*)&t;
}

// ============================ unified GEMM (HMMA fp16, 3-stage) =============
// mode 0: QKV merged (N=2304, K=768; sel 0=q(*0.125)/1=k/2=v, single fp16)
// mode 1: final (N=768, K=768, 1-term ctx; fp32 out + bias)
__global__ __launch_bounds__(256, 2) void hgemm(
    const __half* __restrict__ Ag, const __half* __restrict__ Bg,
    const float* __restrict__ b0p, const float* __restrict__ b1p, const float* __restrict__ b2p,
    void* __restrict__ o0, void* __restrict__ o1, void* __restrict__ o2,
    int K, int ldA, int ldB, int mode)
{
    constexpr int BM = 128, BN = 128, BK = 64;
    constexpr int MI = 4, NI = 4;
    constexpr int SA = BM * BK * 2, SB = BN * BK * 2, STG = SA + SB;  // 32KB/stage

    extern __shared__ char smem[];
    const uint32_t sbase = smem_u32(smem);
    const int tid = threadIdx.x, l = tid & 31, wid = tid >> 5;
    const int row0 = blockIdx.y * BM, col0 = blockIdx.x * BN;
    const int wm0 = (wid / 4) * 64, wn0 = (wid % 4) * 32;

    auto issue = [&](int ch, int st) {
        const int k0 = ch * BK;
        const uint32_t sA = sbase + st * STG;
        const uint32_t sB = sA + SA;
        for (int i = tid; i < BM * 8; i += 256) {
            int r = i >> 3, v = i & 7;
            cp16(sA + SWZ(r * 128 + v * 16), Ag + (size_t)(row0 + r) * ldA + k0 + v * 8);
        }
        for (int i = tid; i < BN * 8; i += 256) {
            int r = i >> 3, v = i & 7;
            cp16(sB + SWZ(r * 128 + v * 16), Bg + (size_t)(col0 + r) * ldB + k0 + v * 8);
        }
    };

    float c[MI][NI][4] = {};
    const int nch = K / BK;
    issue(0, 0); CP_COMMIT();
    if (nch > 1) { issue(1, 1); CP_COMMIT(); }

    for (int ch = 0; ch < nch; ch++) {
        if (ch + 1 < nch) { CP_WAIT(1); } else { CP_WAIT(0); }
        __syncthreads();
        if (ch + 2 < nch) { issue(ch + 2, (ch + 2) % 3); CP_COMMIT(); }

        const uint32_t sA = sbase + (ch % 3) * STG;
        const uint32_t sB = sA + SA;

        #pragma unroll
        for (int ks = 0; ks < 4; ks++) {
            uint32_t af[MI][4];
            #pragma unroll
            for (int im = 0; im < MI; im++)
                ldsm4(af[im][0], af[im][1], af[im][2], af[im][3],
                      sA + SWZ((wm0 + im * 16 + (l & 15)) * 128 + ks * 32 + ((l >> 4) & 1) * 16));
            uint32_t bf[NI][2];
            #pragma unroll
            for (int i2 = 0; i2 < NI / 2; i2++) {
                int g = l >> 3;
                uint32_t r0, r1, r2, r3;
                ldsm4(r0, r1, r2, r3,
                      sB + SWZ((wn0 + i2 * 16 + ((g >> 1) & 1) * 8 + (l & 7)) * 128 + ks * 32 + (g & 1) * 16));
                bf[2 * i2][0] = r0; bf[2 * i2][1] = r1;
                bf[2 * i2 + 1][0] = r2; bf[2 * i2 + 1][1] = r3;
            }
            #pragma unroll
            for (int im = 0; im < MI; im++)
                #pragma unroll
                for (int in = 0; in < NI; in++)
                    mma16816(c[im][in], af[im], bf[in]);
        }
    }
    __syncthreads();

    const int sel = (mode == 0) ? col0 / DMODEL : 3;          // 0 q, 1 k, 2 v, 3 final
    const int dcol0 = col0 % DMODEL;
    const float* bs = (sel == 1) ? b1p : (sel == 2) ? b2p : b0p;
    const float qsc = (sel == 0) ? 0.125f : 1.0f;

    #pragma unroll
    for (int im = 0; im < MI; im++)
        #pragma unroll
        for (int in = 0; in < NI; in++)
            #pragma unroll
            for (int half_ = 0; half_ < 2; half_++) {
                int m = row0 + wm0 + im * 16 + (l >> 2) + half_ * 8;
                int nd = dcol0 + wn0 + in * 8 + (l & 3) * 2;
                float v0 = c[im][in][2 * half_] * WSCI + bs[nd];
                float v1 = c[im][in][2 * half_ + 1] * WSCI + bs[nd + 1];
                if (sel == 3) {
                    float2 w; w.x = v0; w.y = v1;
                    *(float2*)((float*)o0 + (size_t)m * DMODEL + nd) = w;
                    continue;
                }
                v0 *= qsc; v1 *= qsc;
                int b = m >> 10, s = m & 1023, h = nd >> 6, dd = nd & 63;
                __half2 t; t.x = __float2half_rn(v0); t.y = __float2half_rn(v1);
                __half* ob = (sel == 0) ? (__half*)o0 : (sel == 1) ? (__half*)o1 : (__half*)o2;
                *(__half2*)(ob + ((size_t)(b * NHEAD + h) * SSEQ + s) * DHEAD + dd) = t;
            }
}

// ============================ fused attention ===============================
// CTA: (bh_base + blockIdx.y, 64 q-rows). 8 warps: rg rows, ch kv half.
#define SQ_OFF  0                         // 8KB q
#define SK_OFF  8192                      // 2 x 16KB K buffers
#define SV_OFF  40960                     // 16KB V
#define SRED_O  8192                      // reuse K region post-loop (16KB)
#define SRED_L  (8192 + 16384)
#define FSM_BYTES 57344

__global__ __launch_bounds__(256, 2) void fused_attn(
    const __half* __restrict__ Qp, const __half* __restrict__ Kp,
    const __half* __restrict__ Vp,
    __half* __restrict__ pt, float* __restrict__ lbuf,
    __half* __restrict__ ch_out, int bh_base)
{
    extern __shared__ char smem[];
    const uint32_t sbase = smem_u32(smem);
    const int tid = threadIdx.x, l = tid & 31, wid = tid >> 5;
    const int rg = wid >> 1, ch = wid & 1;
    const int bh = bh_base + blockIdx.y, q0 = blockIdx.x * 64;
    const int wm0 = rg * 16;

    const __half* Qb = Qp + (size_t)bh * SSEQ * DHEAD;
    const __half* Kb = Kp + (size_t)bh * SSEQ * DHEAD;
    const __half* Vb = Vp + (size_t)bh * SSEQ * DHEAD;

    auto issueK = [&](int t, int st) {
        const uint32_t kb = sbase + SK_OFF + st * 16384;
        for (int i = tid; i < 1024; i += 256) {
            int r = i >> 3, v = i & 7;
            cp16(kb + SWZ(r * 128 + v * 16), Kb + (size_t)(t * 128 + r) * DHEAD + v * 8);
        }
    };
    auto issueV = [&](int t) {
        for (int i = tid; i < 1024; i += 256) {
            int r = i >> 3, v = i & 7;
            cp16(sbase + SV_OFF + SWZ(r * 128 + v * 16),
                 Vb + (size_t)(t * 128 + r) * DHEAD + v * 8);
        }
    };

    for (int i = tid; i < 512; i += 256) {
        int r = i >> 3, v = i & 7;
        cp16(sbase + SQ_OFF + SWZ(r * 128 + v * 16), Qb + (size_t)(q0 + r) * DHEAD + v * 8);
    }
    issueK(0, 0);
    CP_COMMIT();

    float c_o[8][4] = {};
    float lsum0 = 0.f, lsum1 = 0.f;

    for (int t = 0; t < 8; t++) {
        CP_WAIT(0);
        __syncthreads();
        issueV(t); CP_COMMIT();
        if (t < 7) { issueK(t + 1, (t + 1) & 1); CP_COMMIT(); }

        // ---- S: 16 q-rows x 64 kv (this warp's half), 1-term ----
        float cs[8][4] = {};
        const uint32_t kb = sbase + SK_OFF + (t & 1) * 16384;
        const uint32_t sQ = sbase + SQ_OFF;
        #pragma unroll
        for (int ks = 0; ks < 4; ks++) {
            uint32_t af[4];
            ldsm4(af[0], af[1], af[2], af[3],
                  sQ + SWZ((wm0 + (l & 15)) * 128 + ks * 32 + ((l >> 4) & 1) * 16));
            #pragma unroll
            for (int i2 = 0; i2 < 4; i2++) {
                int g = l >> 3;
                uint32_t r0, r1, r2, r3;
                ldsm4(r0, r1, r2, r3,
                      kb + SWZ((ch * 64 + i2 * 16 + ((g >> 1) & 1) * 8 + (l & 7)) * 128
                               + ks * 32 + (g & 1) * 16));
                uint32_t b0[2] = {r0, r1}, b1[2] = {r2, r3};
                mma16816(cs[2 * i2],     af, b0);
                mma16816(cs[2 * i2 + 1], af, b1);
            }
        }

        // ---- exp + row-sum; pack P-hi (feeds PV and p~ write) ----
        uint32_t ph[8][2];
        #pragma unroll
        for (int in = 0; in < 8; in++) {
            cs[in][0] = __expf(cs[in][0]);
            cs[in][1] = __expf(cs[in][1]);
            cs[in][2] = __expf(cs[in][2]);
            cs[in][3] = __expf(cs[in][3]);
            lsum0 += cs[in][0] + cs[in][1];
            lsum1 += cs[in][2] + cs[in][3];
            ph[in][0] = pk_hi(cs[in][0], cs[in][1]);
            ph[in][1] = pk_hi(cs[in][2], cs[in][3]);
        }
        {
            __half* p0 = pt + ((size_t)bh << 20) + (size_t)(q0 + wm0 + (l >> 2)) * SSEQ
                         + t * 128 + ch * 64 + 2 * (l & 3);
            __half* p1 = p0 + 8 * SSEQ;
            #pragma unroll
            for (int in = 0; in < 8; in++) {
                *(uint32_t*)(p0 + in * 8) = ph[in][0];
                *(uint32_t*)(p1 + in * 8) = ph[in][1];
            }
        }

        if (t < 7) CP_WAIT(1); else CP_WAIT(0);
        __syncthreads();

        // ---- partial O += P~hi @ V over warp's 64 kv (1-term) ----
        const uint32_t sVh = sbase + SV_OFF;
        #pragma unroll
        for (int kk = 0; kk < 4; kk++) {
            uint32_t ah[4];
            ah[0] = ph[2*kk][0];   ah[1] = ph[2*kk][1];
            ah[2] = ph[2*kk+1][0]; ah[3] = ph[2*kk+1][1];
            uint32_t vrow = (uint32_t)(ch * 64 + kk * 16 + ((l >> 3) & 1) * 8 + (l & 7)) * 128
                          + ((uint32_t)(l >> 4)) * 16;
            #pragma unroll
            for (int in = 0; in < 8; in += 2) {
                uint32_t h0, h1, h2, h3;
                ldsm4t(h0, h1, h2, h3, sVh + SWZ(vrow + in * 16));
                uint32_t bh2[2] = {h0, h1}, bh3[2] = {h2, h3};
                mma16816(c_o[in],     ah, bh2);
                mma16816(c_o[in + 1], ah, bh3);
            }
        }
        __syncthreads();
    }

    // ---- pair reduction (ch=1 -> smem -> ch=0), then finalize ----
    lsum0 += __shfl_xor_sync(0xffffffffu, lsum0, 1);
    lsum0 += __shfl_xor_sync(0xffffffffu, lsum0, 2);
    lsum1 += __shfl_xor_sync(0xffffffffu, lsum1, 1);
    lsum1 += __shfl_xor_sync(0xffffffffu, lsum1, 2);

    float* redO = (float*)(smem + SRED_O);             // 4 rg x 16 x 64 = 16KB
    float* redL = (float*)(smem + SRED_L);             // 4 rg x 16
    __syncthreads();
    if (ch == 1) {
        #pragma unroll
        for (int in = 0; in < 8; in++) {
            int cidx = in * 8 + 2 * (l & 3);
            int r = l >> 2;
            redO[rg * 1024 + r * 64 + cidx]           = c_o[in][0];
            redO[rg * 1024 + r * 64 + cidx + 1]       = c_o[in][1];
            redO[rg * 1024 + (r + 8) * 64 + cidx]     = c_o[in][2];
            redO[rg * 1024 + (r + 8) * 64 + cidx + 1] = c_o[in][3];
        }
        if ((l & 3) == 0) {
            redL[rg * 16 + (l >> 2)]     = lsum0;
            redL[rg * 16 + (l >> 2) + 8] = lsum1;
        }
    }
    __syncthreads();
    if (ch == 0) {
        lsum0 += redL[rg * 16 + (l >> 2)];
        lsum1 += redL[rg * 16 + (l >> 2) + 8];
        const float inv0 = 1.0f / lsum0, inv1 = 1.0f / lsum1;

        const int r0g = q0 + wm0 + (l >> 2);
        if ((l & 3) == 0) {
            lbuf[(size_t)bh * SSEQ + r0g]     = lsum0;
            lbuf[(size_t)bh * SSEQ + r0g + 8] = lsum1;
        }
        const int b = bh / NHEAD, h = bh % NHEAD;
        const size_t gm0 = (size_t)(b * SSEQ + r0g) * DMODEL;
        const size_t gm1 = gm0 + (size_t)8 * DMODEL;
        #pragma unroll
        for (int in = 0; in < 8; in++) {
            int cidx = in * 8 + 2 * (l & 3);
            int r = l >> 2;
            float o0 = (c_o[in][0] + redO[rg * 1024 + r * 64 + cidx])           * inv0;
            float o1 = (c_o[in][1] + redO[rg * 1024 + r * 64 + cidx + 1])       * inv0;
            float o2 = (c_o[in][2] + redO[rg * 1024 + (r + 8) * 64 + cidx])     * inv1;
            float o3 = (c_o[in][3] + redO[rg * 1024 + (r + 8) * 64 + cidx + 1]) * inv1;
            int d = h * DHEAD + cidx;
            __half2 t0; t0.x = __float2half_rn(o0); t0.y = __float2half_rn(o1);
            __half2 t1; t1.x = __float2half_rn(o2); t1.y = __float2half_rn(o3);
            *(__half2*)(ch_out + gm0 + d) = t0;
            *(__half2*)(ch_out + gm1 + d) = t1;
        }
    }
}

// rescale: 2 rows/block, 16B p~ loads, 32B fp32 stores; row_base selects half
__global__ __launch_bounds__(256) void rescale_attn(const __half* __restrict__ pt,
                                                    float* __restrict__ attn,
                                                    const float* __restrict__ lbuf,
                                                    size_t row_base)
{
    const int t = threadIdx.x;
    const size_t row = row_base + (size_t)blockIdx.x * 2 + (t >> 7);
    const int lane = t & 127;
    const float inv = 1.0f / lbuf[row];
    const uint4* s = (const uint4*)(pt + row * SSEQ);
    float4* d = (float4*)(attn + row * SSEQ);
    uint4 pv = s[lane];
    __half2 h0 = *(__half2*)&pv.x, h1 = *(__half2*)&pv.y;
    __half2 h2 = *(__half2*)&pv.z, h3 = *(__half2*)&pv.w;
    float4 v0, v1;
    v0.x = __half2float(h0.x) * inv; v0.y = __half2float(h0.y) * inv;
    v0.z = __half2float(h1.x) * inv; v0.w = __half2float(h1.y) * inv;
    v1.x = __half2float(h2.x) * inv; v1.y = __half2float(h2.y) * inv;
    v1.z = __half2float(h3.x) * inv; v1.w = __half2float(h3.y) * inv;
    d[2 * lane]     = v0;
    d[2 * lane + 1] = v1;
}

// ============================ prep kernels ==================================
__global__ __launch_bounds__(256) void pack_x(const float* __restrict__ in, __half* __restrict__ o)
{
    size_t i = (size_t)blockIdx.x * 256 + threadIdx.x;   // float4 index
    if (i >= (size_t)MROWS * DMODEL / 4) return;
    float4 v = ((const float4*)in)[i];
    __half2 a, b;
    a.x = __float2half_rn(v.x); a.y = __float2half_rn(v.y);
    b.x = __float2half_rn(v.z); b.y = __float2half_rn(v.w);
    ((__half2*)o)[2 * i]     = a;
    ((__half2*)o)[2 * i + 1] = b;
}

__global__ void pack_w_all(const float* __restrict__ Wq, const float* __restrict__ Wk,
                           const float* __restrict__ Wv, const float* __restrict__ Wo,
                           __half* __restrict__ wqkvh, __half* __restrict__ woh)
{
    __shared__ float t[32][33];
    const int z = blockIdx.z;
    const float* W = (z == 0) ? Wq : (z == 1) ? Wk : (z == 2) ? Wv : Wo;
    int n0 = blockIdx.x * 32, k0 = blockIdx.y * 32;
    int x = threadIdx.x, y = threadIdx.y;
    #pragma unroll
    for (int j = 0; j < 32; j += 8)
        t[y + j][x] = W[(size_t)(k0 + y + j) * DMODEL + n0 + x] * WSC;
    __syncthreads();
    __half* o = (z == 3) ? woh : wqkvh + (size_t)z * DMODEL * DMODEL;
    #pragma unroll
    for (int j = 0; j < 32; j += 8)
        o[(size_t)(n0 + y + j) * DMODEL + k0 + x] = __float2half_rn(t[x][y + j]);
}

// ============================ host launcher =================================
extern "C" void kernel_launch(void* const* d_in, const int* in_sizes, int n_in,
                              void* d_out, int out_size)
{
    (void)in_sizes; (void)n_in;
    const float* x  = (const float*)d_in[0];
    const float* Wq = (const float*)d_in[1];
    const float* bq = (const float*)d_in[2];
    const float* Wk = (const float*)d_in[3];
    const float* bk = (const float*)d_in[4];
    const float* Wv = (const float*)d_in[5];
    const float* bv = (const float*)d_in[6];
    const float* Wo = (const float*)d_in[7];
    const float* bo = (const float*)d_in[8];
    float* out = (float*)d_out;

    float *gattn, *gl;
    __half *pt, *xh, *wqkvh, *woh, *qP, *kP, *vP, *chx;
    cudaGetSymbolAddress((void**)&gattn, g_attn);
    cudaGetSymbolAddress((void**)&gl,    g_l);
    cudaGetSymbolAddress((void**)&pt,    g_pt);
    cudaGetSymbolAddress((void**)&xh,    g_xh);
    cudaGetSymbolAddress((void**)&wqkvh, g_wqkvh);
    cudaGetSymbolAddress((void**)&woh,   g_woh);
    cudaGetSymbolAddress((void**)&qP,    g_q);
    cudaGetSymbolAddress((void**)&kP,    g_k);
    cudaGetSymbolAddress((void**)&vP,    g_v);
    cudaGetSymbolAddress((void**)&chx,   g_ch);

    const size_t final_elems = (size_t)MROWS * DMODEL;
    const int wattn = ((size_t)out_size > final_elems) ? 1 : 0;
    float* attn = wattn ? (out + final_elems) : gattn;

    static cudaStream_t s2 = nullptr;
    static cudaEvent_t evF = nullptr, evP = nullptr, evA = nullptr, evB = nullptr, evC = nullptr;
    if (s2 == nullptr) {
        cudaStreamCreateWithFlags(&s2, cudaStreamNonBlocking);
        cudaEventCreateWithFlags(&evF, cudaEventDisableTiming);
        cudaEventCreateWithFlags(&evP, cudaEventDisableTiming);
        cudaEventCreateWithFlags(&evA, cudaEventDisableTiming);
        cudaEventCreateWithFlags(&evB, cudaEventDisableTiming);
        cudaEventCreateWithFlags(&evC, cudaEventDisableTiming);
    }

    constexpr int SM_GEMM = 3 * (128 * 64 * 2 + 128 * 64 * 2);   // 96KB, 3-stage
    cudaFuncSetAttribute(hgemm,      cudaFuncAttributeMaxDynamicSharedMemorySize, SM_GEMM);
    cudaFuncSetAttribute(fused_attn, cudaFuncAttributeMaxDynamicSharedMemorySize, FSM_BYTES);

    // pack: fork s2 FROM the capture origin stream first (capture-legal),
    // then x on stream 0 ∥ weights on s2.
    {
        cudaEventRecord(evF, 0);               // origin-stream event: brings s2 into capture
        cudaStreamWaitEvent(s2, evF, 0);
        size_t n4 = (size_t)MROWS * DMODEL / 4;
        pack_x<<<(unsigned)((n4 + 255) / 256), 256>>>(x, xh);
        dim3 tb(32, 8), tg(DMODEL / 32, DMODEL / 32, 4);
        pack_w_all<<<tg, tb, 0, s2>>>(Wq, Wk, Wv, Wo, wqkvh, woh);
        cudaEventRecord(evP, s2);
        cudaStreamWaitEvent(0, evP, 0);        // join before QKV GEMM
    }

    // merged QKV projection (N = 2304, K = 768, 1-term)
    dim3 gqkv(3 * DMODEL / 128, MROWS / 128);     // (18, 64)
    hgemm<<<gqkv, 256, SM_GEMM>>>(xh, wqkvh, bq, bk, bv, qP, kP, vP,
                                  DMODEL, DMODEL, DMODEL, 0);

    // fused attention: two bh-halves, pipelined with rescale halves on s2
    dim3 gf(SSEQ / 64, NBH / 2);                  // (16, 48)
    fused_attn<<<gf, 256, FSM_BYTES>>>(qP, kP, vP, pt, gl, chx, 0);
    cudaEventRecord(evA, 0);
    fused_attn<<<gf, 256, FSM_BYTES>>>(qP, kP, vP, pt, gl, chx, NBH / 2);
    cudaEventRecord(evB, 0);

    if (wattn) {
        cudaStreamWaitEvent(s2, evA, 0);
        rescale_attn<<<NBH * SSEQ / 4, 256, 0, s2>>>(pt, attn, gl, 0);
        cudaStreamWaitEvent(s2, evB, 0);
        rescale_attn<<<NBH * SSEQ / 4, 256, 0, s2>>>(pt, attn, gl, (size_t)(NBH / 2) * SSEQ);
        cudaEventRecord(evC, s2);
    }

    // out = ctx @ Wo + bo (K = 768, 1-term) — overlaps rescale2 on s2
    dim3 gfin(DMODEL / 128, MROWS / 128);         // (6, 64)
    hgemm<<<gfin, 256, SM_GEMM>>>(chx, woh, bo, nullptr, nullptr, out, nullptr, nullptr,
                                  DMODEL, DMODEL, DMODEL, 1);

    if (wattn) cudaStreamWaitEvent(0, evC, 0);
}